// round 1
// baseline (speedup 1.0000x reference)
#include <cuda_runtime.h>
#include <math.h>

// Problem constants
#define Hd   4096
#define Id   14336
#define Rr   159
#define R2   318
#define R4   636
#define Ee   8
#define Tt   4096
#define PLD  640     // row stride of P scratch (>= R4)
#define QLD  320     // row stride of Q scratch (>= R2)

#define BM 128
#define BN 128
#define BK 8

// ---------------- scratch (device globals; no allocation allowed) ----------------
__device__ int   g_cnt[Ee];
__device__ int   g_off[Ee];
__device__ int   g_tok[Ee][Tt];
__device__ float g_wt[Ee][Tt];
__device__ float g_P[(unsigned long long)8192 * PLD];      // [8192, 640]
__device__ float g_hbuf[(unsigned long long)8192 * Id];    // [8192, 14336]  (~470MB)
__device__ float g_Q[(unsigned long long)8192 * QLD];      // [8192, 320]

// ---------------- small helpers ----------------
__device__ __forceinline__ float warpsum(float v) {
#pragma unroll
    for (int o = 16; o; o >>= 1) v += __shfl_down_sync(0xffffffffu, v, o);
    return v;
}

// ---------------- router logits: logits[t][e] = x[t] . gate_w[e] ----------------
__global__ __launch_bounds__(256) void router_kernel(
    const float* __restrict__ x, const float* __restrict__ gw, float* __restrict__ logits)
{
    int t = blockIdx.x;
    const float4* xr = (const float4*)(x + (size_t)t * Hd);
    float acc[Ee];
#pragma unroll
    for (int e = 0; e < Ee; e++) acc[e] = 0.f;
    for (int i = threadIdx.x; i < Hd / 4; i += 256) {
        float4 xv = xr[i];
#pragma unroll
        for (int e = 0; e < Ee; e++) {
            float4 wv = ((const float4*)(gw + (size_t)e * Hd))[i];
            acc[e] = fmaf(xv.x, wv.x, fmaf(xv.y, wv.y, fmaf(xv.z, wv.z, fmaf(xv.w, wv.w, acc[e]))));
        }
    }
    __shared__ float red[8][Ee];
    int lane = threadIdx.x & 31, w = threadIdx.x >> 5;
#pragma unroll
    for (int e = 0; e < Ee; e++) {
        float s = warpsum(acc[e]);
        if (lane == 0) red[w][e] = s;
    }
    __syncthreads();
    if (threadIdx.x < Ee) {
        float s = 0.f;
#pragma unroll
        for (int w2 = 0; w2 < 8; w2++) s += red[w2][threadIdx.x];
        logits[(size_t)t * Ee + threadIdx.x] = s;
    }
}

// ---------------- routing: top-2, normalized weights, per-expert gather lists ----------------
__global__ void prep_kernel() {
    if (threadIdx.x < Ee) g_cnt[threadIdx.x] = 0;
}

__global__ void route_kernel(const float* __restrict__ logits)
{
    int t = blockIdx.x * blockDim.x + threadIdx.x;
    if (t >= Tt) return;
    float l[Ee];
#pragma unroll
    for (int e = 0; e < Ee; e++) l[e] = logits[(size_t)t * Ee + e];
    int i1 = 0; float m1 = l[0];
#pragma unroll
    for (int e = 1; e < Ee; e++) if (l[e] > m1) { m1 = l[e]; i1 = e; }
    int i2 = -1; float m2 = -1e30f;
#pragma unroll
    for (int e = 0; e < Ee; e++) if (e != i1 && l[e] > m2) { m2 = l[e]; i2 = e; }
    // softmax denominator cancels in top-2 renorm: w1 = 1/(1+exp(m2-m1))
    float w1 = 1.f / (1.f + expf(m2 - m1));
    float w2 = 1.f - w1;
    int p = atomicAdd(&g_cnt[i1], 1); g_tok[i1][p] = t; g_wt[i1][p] = w1;
    p     = atomicAdd(&g_cnt[i2], 1); g_tok[i2][p] = t; g_wt[i2][p] = w2;
}

__global__ void offsets_kernel()
{
    if (threadIdx.x == 0) {
        int s = 0;
        for (int e = 0; e < Ee; e++) { g_off[e] = s; s += g_cnt[e]; }
    }
}

// ---------------- GEMM tile machinery (128x128x8, 8x8 microtile, 256 threads) ----------------
#define GEMM_PROLOG()                                   \
    int e     = blockIdx.z;                             \
    int n_e   = g_cnt[e];                               \
    int mbase = blockIdx.x * BM;                        \
    if (mbase >= n_e) return;                           \
    int nbase = blockIdx.y * BN;                        \
    int off   = g_off[e];                               \
    (void)off; (void)nbase;                             \
    __shared__ float As[BK][BM];                        \
    __shared__ float Bs[BK][BN];                        \
    int tid = threadIdx.x;                              \
    int lr  = tid >> 1;                                 \
    int lc  = (tid & 1) * 4;                            \
    int tx  = tid & 15, ty = tid >> 4;                  \
    float acc[8][8] = {};

#define GEMM_COMPUTE()                                                     \
    __syncthreads();                                                       \
    _Pragma("unroll")                                                      \
    for (int k = 0; k < BK; k++) {                                         \
        float a[8], b[8];                                                  \
        *(float4*)(a)     = *(const float4*)(&As[k][ty * 4]);              \
        *(float4*)(a + 4) = *(const float4*)(&As[k][ty * 4 + 64]);         \
        *(float4*)(b)     = *(const float4*)(&Bs[k][tx * 4]);              \
        *(float4*)(b + 4) = *(const float4*)(&Bs[k][tx * 4 + 64]);         \
        _Pragma("unroll")                                                  \
        for (int i = 0; i < 8; i++)                                        \
            _Pragma("unroll")                                              \
            for (int j = 0; j < 8; j++)                                    \
                acc[i][j] = fmaf(a[i], b[j], acc[i][j]);                   \
    }                                                                      \
    __syncthreads();

#define MROW(i) (((i) < 4) ? (ty * 4 + (i)) : (64 + ty * 4 + (i) - 4))
#define NCOL(j) (((j) < 4) ? (tx * 4 + (j)) : (64 + tx * 4 + (j) - 4))

// ---------------- P = gather(x) @ [w1v; v1; w3v; v3]^T    [n_e, 636], K = 4096 ----------------
__global__ __launch_bounds__(256) void gemm_P(
    const float* __restrict__ x,
    const float* __restrict__ w1v, const float* __restrict__ v1,
    const float* __restrict__ w3v, const float* __restrict__ v3)
{
    GEMM_PROLOG();
    const float* arow = nullptr;
    if (mbase + lr < n_e) arow = x + (size_t)g_tok[e][mbase + lr] * Hd;
    const float* brow = nullptr;
    {
        int j = nbase + lr;
        if (j < R4) {
            const float* base; int jr;
            if      (j < Rr)     { base = w1v; jr = j; }
            else if (j < 2 * Rr) { base = v1;  jr = j - Rr; }
            else if (j < 3 * Rr) { base = w3v; jr = j - 2 * Rr; }
            else                 { base = v3;  jr = j - 3 * Rr; }
            brow = base + ((size_t)e * Rr + jr) * Hd;
        }
    }
    for (int k0 = 0; k0 < Hd; k0 += BK) {
        float4 av = arow ? *(const float4*)(arow + k0 + lc) : make_float4(0.f, 0.f, 0.f, 0.f);
        float4 bv = brow ? *(const float4*)(brow + k0 + lc) : make_float4(0.f, 0.f, 0.f, 0.f);
        As[lc + 0][lr] = av.x; As[lc + 1][lr] = av.y; As[lc + 2][lr] = av.z; As[lc + 3][lr] = av.w;
        Bs[lc + 0][lr] = bv.x; Bs[lc + 1][lr] = bv.y; Bs[lc + 2][lr] = bv.z; Bs[lc + 3][lr] = bv.w;
        GEMM_COMPUTE();
    }
#pragma unroll
    for (int i = 0; i < 8; i++) {
        int m = mbase + MROW(i);
        if (m >= n_e) continue;
        float* dst = g_P + (size_t)(off + m) * PLD;
#pragma unroll
        for (int j = 0; j < 8; j++) {
            int c = nbase + NCOL(j);
            if (c < R4) dst[c] = acc[i][j];
        }
    }
}

// ---------------- gate/up: [n_e, I] = P[:, COLOFF:COLOFF+318] @ concat(W,U)^T, K = 318 ----------------
// UP=false: h = silu(gate);  UP=true: h *= up
template <int COLOFF, bool UP>
__global__ __launch_bounds__(256) void gemm_gu(
    const float* __restrict__ W, const float* __restrict__ U)
{
    GEMM_PROLOG();
    const float* arow = nullptr;
    if (mbase + lr < n_e) arow = g_P + (size_t)(off + mbase + lr) * PLD + COLOFF;
    int bi = nbase + lr;  // I-dim row (Id % 128 == 0, always valid)
    const float* wr = W + ((size_t)e * Id + bi) * Rr;
    const float* ur = U + ((size_t)e * Id + bi) * Rr;

    for (int k0 = 0; k0 < R2; k0 += BK) {
#pragma unroll
        for (int q = 0; q < 4; q++) {
            int k = k0 + lc + q;
            float aval = 0.f, bval = 0.f;
            if (k < R2) {
                if (arow) aval = arow[k];
                bval = (k < Rr) ? wr[k] : ur[k - Rr];
            }
            As[lc + q][lr] = aval;
            Bs[lc + q][lr] = bval;
        }
        GEMM_COMPUTE();
    }
#pragma unroll
    for (int i = 0; i < 8; i++) {
        int m = mbase + MROW(i);
        if (m >= n_e) continue;
        float* dst = g_hbuf + (size_t)(off + m) * Id + nbase;
#pragma unroll
        for (int j = 0; j < 8; j++) {
            int c = NCOL(j);
            if (!UP) {
                float g = acc[i][j];
                dst[c] = g / (1.f + __expf(-g));   // silu
            } else {
                dst[c] = dst[c] * acc[i][j];
            }
        }
    }
}

// ---------------- Q = h @ [w2v; v2]^T    [n_e, 318], K = 14336 ----------------
__global__ __launch_bounds__(256) void gemm_Q(
    const float* __restrict__ w2v_, const float* __restrict__ v2_)
{
    GEMM_PROLOG();
    const float* arow = nullptr;
    if (mbase + lr < n_e) arow = g_hbuf + (size_t)(off + mbase + lr) * Id;
    const float* brow = nullptr;
    {
        int q = nbase + lr;
        if (q < R2) {
            brow = (q < Rr) ? (w2v_ + ((size_t)e * Rr + q) * Id)
                            : (v2_  + ((size_t)e * Rr + (q - Rr)) * Id);
        }
    }
    for (int k0 = 0; k0 < Id; k0 += BK) {
        float4 av = arow ? *(const float4*)(arow + k0 + lc) : make_float4(0.f, 0.f, 0.f, 0.f);
        float4 bv = brow ? *(const float4*)(brow + k0 + lc) : make_float4(0.f, 0.f, 0.f, 0.f);
        As[lc + 0][lr] = av.x; As[lc + 1][lr] = av.y; As[lc + 2][lr] = av.z; As[lc + 3][lr] = av.w;
        Bs[lc + 0][lr] = bv.x; Bs[lc + 1][lr] = bv.y; Bs[lc + 2][lr] = bv.z; Bs[lc + 3][lr] = bv.w;
        GEMM_COMPUTE();
    }
#pragma unroll
    for (int i = 0; i < 8; i++) {
        int m = mbase + MROW(i);
        if (m >= n_e) continue;
        float* dst = g_Q + (size_t)(off + m) * QLD;
#pragma unroll
        for (int j = 0; j < 8; j++) {
            int c = nbase + NCOL(j);
            if (c < R2) dst[c] = acc[i][j];
        }
    }
}

// ---------------- out scatter: final[tok] += wt * (Q @ [w2u; u2]^T)    K = 318 ----------------
__global__ __launch_bounds__(256) void gemm_out(
    const float* __restrict__ w2u_, const float* __restrict__ u2_, float* __restrict__ outp)
{
    GEMM_PROLOG();
    const float* arow = nullptr;
    if (mbase + lr < n_e) arow = g_Q + (size_t)(off + mbase + lr) * QLD;
    int hj = nbase + lr;  // H-dim col (Hd % 128 == 0, always valid)
    const float* wr = w2u_ + ((size_t)e * Hd + hj) * Rr;
    const float* ur = u2_  + ((size_t)e * Hd + hj) * Rr;

    for (int k0 = 0; k0 < R2; k0 += BK) {
#pragma unroll
        for (int q = 0; q < 4; q++) {
            int k = k0 + lc + q;
            float aval = 0.f, bval = 0.f;
            if (k < R2) {
                if (arow) aval = arow[k];
                bval = (k < Rr) ? wr[k] : ur[k - Rr];
            }
            As[lc + q][lr] = aval;
            Bs[lc + q][lr] = bval;
        }
        GEMM_COMPUTE();
    }
#pragma unroll
    for (int i = 0; i < 8; i++) {
        int m = mbase + MROW(i);
        if (m >= n_e) continue;
        float wt  = g_wt[e][m];
        int   tok = g_tok[e][m];
        float* dst = outp + (size_t)tok * Hd + nbase;
#pragma unroll
        for (int j = 0; j < 8; j++) {
            int c = NCOL(j);
            atomicAdd(&dst[c], wt * acc[i][j]);   // exactly 2 adds/element -> deterministic
        }
    }
}

// ---------------- launch ----------------
extern "C" void kernel_launch(void* const* d_in, const int* in_sizes, int n_in,
                              void* d_out, int out_size)
{
    const float* x    = (const float*)d_in[0];
    const float* gw   = (const float*)d_in[1];
    const float* w1u  = (const float*)d_in[2];
    const float* w1v  = (const float*)d_in[3];
    const float* w2u  = (const float*)d_in[4];
    const float* w2v  = (const float*)d_in[5];
    const float* w3u  = (const float*)d_in[6];
    const float* w3v  = (const float*)d_in[7];
    const float* u1   = (const float*)d_in[8];
    const float* v1   = (const float*)d_in[9];
    const float* u2   = (const float*)d_in[10];
    const float* v2   = (const float*)d_in[11];
    const float* u3   = (const float*)d_in[12];
    const float* v3   = (const float*)d_in[13];

    float* outp   = (float*)d_out;
    float* logits = outp + (size_t)Tt * Hd;

    cudaMemsetAsync(outp, 0, (size_t)Tt * Hd * sizeof(float));
    prep_kernel<<<1, 32>>>();
    router_kernel<<<Tt, 256>>>(x, gw, logits);
    route_kernel<<<Tt / 256, 256>>>(logits);
    offsets_kernel<<<1, 32>>>();

    dim3 gP(Tt / BM, (R4 + BN - 1) / BN, Ee);   // (32, 5, 8)
    gemm_P<<<gP, 256>>>(x, w1v, v1, w3v, v3);

    dim3 gG(Tt / BM, Id / BN, Ee);              // (32, 112, 8)
    gemm_gu<0,  false><<<gG, 256>>>(w1u, u1);   // gate -> silu -> h
    gemm_gu<R2, true ><<<gG, 256>>>(w3u, u3);   // up   -> h *= up

    dim3 gQ(Tt / BM, (R2 + BN - 1) / BN, Ee);   // (32, 3, 8)
    gemm_Q<<<gQ, 256>>>(w2v, v2);

    dim3 gO(Tt / BM, Hd / BN, Ee);              // (32, 32, 8)
    gemm_out<<<gO, 256>>>(w2u, u2, outp);
}

// round 2
// speedup vs baseline: 1.0063x; 1.0063x over previous
#include <cuda_runtime.h>
#include <math.h>

// Problem constants
#define Hd   4096
#define Id   14336
#define Rr   159
#define R2   318
#define R4   636
#define Ee   8
#define Tt   4096
#define PLD  640     // row stride of P scratch (>= R4)
#define QLD  320     // row stride of Q scratch (>= R2)

#define BM 128
#define BN 128
#define BK 8

// ---------------- scratch (device globals; no allocation allowed) ----------------
__device__ int   g_cnt[Ee];
__device__ int   g_off[Ee];
__device__ int   g_tok[Ee][Tt];
__device__ float g_wt[Ee][Tt];
__device__ float g_P[(unsigned long long)8192 * PLD];      // [8192, 640]
__device__ float g_hbuf[(unsigned long long)8192 * Id];    // [8192, 14336]  (~470MB)
__device__ float g_Q[(unsigned long long)8192 * QLD];      // [8192, 320]

// ---------------- small helpers ----------------
__device__ __forceinline__ float warpsum(float v) {
#pragma unroll
    for (int o = 16; o; o >>= 1) v += __shfl_down_sync(0xffffffffu, v, o);
    return v;
}

// ---------------- router logits: logits[t][e] = x[t] . gate_w[e] ----------------
__global__ __launch_bounds__(256) void router_kernel(
    const float* __restrict__ x, const float* __restrict__ gw, float* __restrict__ logits)
{
    int t = blockIdx.x;
    const float4* xr = (const float4*)(x + (size_t)t * Hd);
    float acc[Ee];
#pragma unroll
    for (int e = 0; e < Ee; e++) acc[e] = 0.f;
    for (int i = threadIdx.x; i < Hd / 4; i += 256) {
        float4 xv = xr[i];
#pragma unroll
        for (int e = 0; e < Ee; e++) {
            float4 wv = ((const float4*)(gw + (size_t)e * Hd))[i];
            acc[e] = fmaf(xv.x, wv.x, fmaf(xv.y, wv.y, fmaf(xv.z, wv.z, fmaf(xv.w, wv.w, acc[e]))));
        }
    }
    __shared__ float red[8][Ee];
    int lane = threadIdx.x & 31, w = threadIdx.x >> 5;
#pragma unroll
    for (int e = 0; e < Ee; e++) {
        float s = warpsum(acc[e]);
        if (lane == 0) red[w][e] = s;
    }
    __syncthreads();
    if (threadIdx.x < Ee) {
        float s = 0.f;
#pragma unroll
        for (int w2 = 0; w2 < 8; w2++) s += red[w2][threadIdx.x];
        logits[(size_t)t * Ee + threadIdx.x] = s;
    }
}

// ---------------- routing: top-2, normalized weights, per-expert gather lists ----------------
__global__ void prep_kernel() {
    if (threadIdx.x < Ee) g_cnt[threadIdx.x] = 0;
}

__global__ void route_kernel(const float* __restrict__ logits)
{
    int t = blockIdx.x * blockDim.x + threadIdx.x;
    if (t >= Tt) return;
    float l[Ee];
#pragma unroll
    for (int e = 0; e < Ee; e++) l[e] = logits[(size_t)t * Ee + e];
    int i1 = 0; float m1 = l[0];
#pragma unroll
    for (int e = 1; e < Ee; e++) if (l[e] > m1) { m1 = l[e]; i1 = e; }
    int i2 = -1; float m2 = -1e30f;
#pragma unroll
    for (int e = 0; e < Ee; e++) if (e != i1 && l[e] > m2) { m2 = l[e]; i2 = e; }
    // softmax denominator cancels in top-2 renorm: w1 = 1/(1+exp(m2-m1))
    float w1 = 1.f / (1.f + expf(m2 - m1));
    float w2 = 1.f - w1;
    int p = atomicAdd(&g_cnt[i1], 1); g_tok[i1][p] = t; g_wt[i1][p] = w1;
    p     = atomicAdd(&g_cnt[i2], 1); g_tok[i2][p] = t; g_wt[i2][p] = w2;
}

__global__ void offsets_kernel()
{
    if (threadIdx.x == 0) {
        int s = 0;
        for (int e = 0; e < Ee; e++) { g_off[e] = s; s += g_cnt[e]; }
    }
}

// ---------------- GEMM tile machinery (128x128x8, 8x8 microtile, 256 threads) ----------------
#define GEMM_PROLOG()                                   \
    int e     = blockIdx.z;                             \
    int n_e   = g_cnt[e];                               \
    int mbase = blockIdx.x * BM;                        \
    if (mbase >= n_e) return;                           \
    int nbase = blockIdx.y * BN;                        \
    int off   = g_off[e];                               \
    (void)off; (void)nbase;                             \
    __shared__ float As[BK][BM];                        \
    __shared__ float Bs[BK][BN];                        \
    int tid = threadIdx.x;                              \
    int lr  = tid >> 1;                                 \
    int lc  = (tid & 1) * 4;                            \
    int tx  = tid & 15, ty = tid >> 4;                  \
    float acc[8][8] = {};

#define GEMM_COMPUTE()                                                     \
    __syncthreads();                                                       \
    _Pragma("unroll")                                                      \
    for (int k = 0; k < BK; k++) {                                         \
        float a[8], b[8];                                                  \
        *(float4*)(a)     = *(const float4*)(&As[k][ty * 4]);              \
        *(float4*)(a + 4) = *(const float4*)(&As[k][ty * 4 + 64]);         \
        *(float4*)(b)     = *(const float4*)(&Bs[k][tx * 4]);              \
        *(float4*)(b + 4) = *(const float4*)(&Bs[k][tx * 4 + 64]);         \
        _Pragma("unroll")                                                  \
        for (int i = 0; i < 8; i++)                                        \
            _Pragma("unroll")                                              \
            for (int j = 0; j < 8; j++)                                    \
                acc[i][j] = fmaf(a[i], b[j], acc[i][j]);                   \
    }                                                                      \
    __syncthreads();

#define MROW(i) (((i) < 4) ? (ty * 4 + (i)) : (64 + ty * 4 + (i) - 4))
#define NCOL(j) (((j) < 4) ? (tx * 4 + (j)) : (64 + tx * 4 + (j) - 4))

// ---------------- P = gather(x) @ [w1v; v1; w3v; v3]^T    [n_e, 636], K = 4096 ----------------
__global__ __launch_bounds__(256) void gemm_P(
    const float* __restrict__ x,
    const float* __restrict__ w1v, const float* __restrict__ v1,
    const float* __restrict__ w3v, const float* __restrict__ v3)
{
    GEMM_PROLOG();
    const float* arow = nullptr;
    if (mbase + lr < n_e) arow = x + (size_t)g_tok[e][mbase + lr] * Hd;
    const float* brow = nullptr;
    {
        int j = nbase + lr;
        if (j < R4) {
            const float* base; int jr;
            if      (j < Rr)     { base = w1v; jr = j; }
            else if (j < 2 * Rr) { base = v1;  jr = j - Rr; }
            else if (j < 3 * Rr) { base = w3v; jr = j - 2 * Rr; }
            else                 { base = v3;  jr = j - 3 * Rr; }
            brow = base + ((size_t)e * Rr + jr) * Hd;
        }
    }
    for (int k0 = 0; k0 < Hd; k0 += BK) {
        float4 av = arow ? *(const float4*)(arow + k0 + lc) : make_float4(0.f, 0.f, 0.f, 0.f);
        float4 bv = brow ? *(const float4*)(brow + k0 + lc) : make_float4(0.f, 0.f, 0.f, 0.f);
        As[lc + 0][lr] = av.x; As[lc + 1][lr] = av.y; As[lc + 2][lr] = av.z; As[lc + 3][lr] = av.w;
        Bs[lc + 0][lr] = bv.x; Bs[lc + 1][lr] = bv.y; Bs[lc + 2][lr] = bv.z; Bs[lc + 3][lr] = bv.w;
        GEMM_COMPUTE();
    }
#pragma unroll
    for (int i = 0; i < 8; i++) {
        int m = mbase + MROW(i);
        if (m >= n_e) continue;
        float* dst = g_P + (size_t)(off + m) * PLD;
#pragma unroll
        for (int j = 0; j < 8; j++) {
            int c = nbase + NCOL(j);
            if (c < R4) dst[c] = acc[i][j];
        }
    }
}

// ---------------- gate/up: [n_e, I] = P[:, COLOFF:COLOFF+318] @ concat(W,U)^T, K = 318 ----------------
// UP=false: h = silu(gate);  UP=true: h *= up
template <int COLOFF, bool UP>
__global__ __launch_bounds__(256) void gemm_gu(
    const float* __restrict__ W, const float* __restrict__ U)
{
    GEMM_PROLOG();
    const float* arow = nullptr;
    if (mbase + lr < n_e) arow = g_P + (size_t)(off + mbase + lr) * PLD + COLOFF;
    int bi = nbase + lr;  // I-dim row (Id % 128 == 0, always valid)
    const float* wr = W + ((size_t)e * Id + bi) * Rr;
    const float* ur = U + ((size_t)e * Id + bi) * Rr;

    for (int k0 = 0; k0 < R2; k0 += BK) {
#pragma unroll
        for (int q = 0; q < 4; q++) {
            int k = k0 + lc + q;
            float aval = 0.f, bval = 0.f;
            if (k < R2) {
                if (arow) aval = arow[k];
                bval = (k < Rr) ? wr[k] : ur[k - Rr];
            }
            As[lc + q][lr] = aval;
            Bs[lc + q][lr] = bval;
        }
        GEMM_COMPUTE();
    }
#pragma unroll
    for (int i = 0; i < 8; i++) {
        int m = mbase + MROW(i);
        if (m >= n_e) continue;
        float* dst = g_hbuf + (size_t)(off + m) * Id + nbase;
#pragma unroll
        for (int j = 0; j < 8; j++) {
            int c = NCOL(j);
            if (!UP) {
                float g = acc[i][j];
                dst[c] = g / (1.f + __expf(-g));   // silu
            } else {
                dst[c] = dst[c] * acc[i][j];
            }
        }
    }
}

// ---------------- Q = h @ [w2v; v2]^T    [n_e, 318], K = 14336 ----------------
__global__ __launch_bounds__(256) void gemm_Q(
    const float* __restrict__ w2v_, const float* __restrict__ v2_)
{
    GEMM_PROLOG();
    const float* arow = nullptr;
    if (mbase + lr < n_e) arow = g_hbuf + (size_t)(off + mbase + lr) * Id;
    const float* brow = nullptr;
    {
        int q = nbase + lr;
        if (q < R2) {
            brow = (q < Rr) ? (w2v_ + ((size_t)e * Rr + q) * Id)
                            : (v2_  + ((size_t)e * Rr + (q - Rr)) * Id);
        }
    }
    for (int k0 = 0; k0 < Id; k0 += BK) {
        float4 av = arow ? *(const float4*)(arow + k0 + lc) : make_float4(0.f, 0.f, 0.f, 0.f);
        float4 bv = brow ? *(const float4*)(brow + k0 + lc) : make_float4(0.f, 0.f, 0.f, 0.f);
        As[lc + 0][lr] = av.x; As[lc + 1][lr] = av.y; As[lc + 2][lr] = av.z; As[lc + 3][lr] = av.w;
        Bs[lc + 0][lr] = bv.x; Bs[lc + 1][lr] = bv.y; Bs[lc + 2][lr] = bv.z; Bs[lc + 3][lr] = bv.w;
        GEMM_COMPUTE();
    }
#pragma unroll
    for (int i = 0; i < 8; i++) {
        int m = mbase + MROW(i);
        if (m >= n_e) continue;
        float* dst = g_Q + (size_t)(off + m) * QLD;
#pragma unroll
        for (int j = 0; j < 8; j++) {
            int c = nbase + NCOL(j);
            if (c < R2) dst[c] = acc[i][j];
        }
    }
}

// ---------------- out scatter: final[tok] += wt * (Q @ [w2u; u2]^T)    K = 318 ----------------
__global__ __launch_bounds__(256) void gemm_out(
    const float* __restrict__ w2u_, const float* __restrict__ u2_, float* __restrict__ outp)
{
    GEMM_PROLOG();
    const float* arow = nullptr;
    if (mbase + lr < n_e) arow = g_Q + (size_t)(off + mbase + lr) * QLD;
    int hj = nbase + lr;  // H-dim col (Hd % 128 == 0, always valid)
    const float* wr = w2u_ + ((size_t)e * Hd + hj) * Rr;
    const float* ur = u2_  + ((size_t)e * Hd + hj) * Rr;

    for (int k0 = 0; k0 < R2; k0 += BK) {
#pragma unroll
        for (int q = 0; q < 4; q++) {
            int k = k0 + lc + q;
            float aval = 0.f, bval = 0.f;
            if (k < R2) {
                if (arow) aval = arow[k];
                bval = (k < Rr) ? wr[k] : ur[k - Rr];
            }
            As[lc + q][lr] = aval;
            Bs[lc + q][lr] = bval;
        }
        GEMM_COMPUTE();
    }
#pragma unroll
    for (int i = 0; i < 8; i++) {
        int m = mbase + MROW(i);
        if (m >= n_e) continue;
        float wt  = g_wt[e][m];
        int   tok = g_tok[e][m];
        float* dst = outp + (size_t)tok * Hd + nbase;
#pragma unroll
        for (int j = 0; j < 8; j++) {
            int c = NCOL(j);
            atomicAdd(&dst[c], wt * acc[i][j]);   // exactly 2 adds/element -> deterministic
        }
    }
}

// ---------------- launch ----------------
extern "C" void kernel_launch(void* const* d_in, const int* in_sizes, int n_in,
                              void* d_out, int out_size)
{
    const float* x    = (const float*)d_in[0];
    const float* gw   = (const float*)d_in[1];
    const float* w1u  = (const float*)d_in[2];
    const float* w1v  = (const float*)d_in[3];
    const float* w2u  = (const float*)d_in[4];
    const float* w2v  = (const float*)d_in[5];
    const float* w3u  = (const float*)d_in[6];
    const float* w3v  = (const float*)d_in[7];
    const float* u1   = (const float*)d_in[8];
    const float* v1   = (const float*)d_in[9];
    const float* u2   = (const float*)d_in[10];
    const float* v2   = (const float*)d_in[11];
    const float* u3   = (const float*)d_in[12];
    const float* v3   = (const float*)d_in[13];

    float* outp   = (float*)d_out;
    float* logits = outp + (size_t)Tt * Hd;

    cudaMemsetAsync(outp, 0, (size_t)Tt * Hd * sizeof(float));
    prep_kernel<<<1, 32>>>();
    router_kernel<<<Tt, 256>>>(x, gw, logits);
    route_kernel<<<Tt / 256, 256>>>(logits);
    offsets_kernel<<<1, 32>>>();

    dim3 gP(Tt / BM, (R4 + BN - 1) / BN, Ee);   // (32, 5, 8)
    gemm_P<<<gP, 256>>>(x, w1v, v1, w3v, v3);

    dim3 gG(Tt / BM, Id / BN, Ee);              // (32, 112, 8)
    gemm_gu<0,  false><<<gG, 256>>>(w1u, u1);   // gate -> silu -> h
    gemm_gu<R2, true ><<<gG, 256>>>(w3u, u3);   // up   -> h *= up

    dim3 gQ(Tt / BM, (R2 + BN - 1) / BN, Ee);   // (32, 3, 8)
    gemm_Q<<<gQ, 256>>>(w2v, v2);

    dim3 gO(Tt / BM, Hd / BN, Ee);              // (32, 32, 8)
    gemm_out<<<gO, 256>>>(w2u, u2, outp);
}

// round 4
// speedup vs baseline: 1.9655x; 1.9533x over previous
#include <cuda_runtime.h>
#include <cuda_bf16.h>
#include <cstdint>
#include <math.h>

// ---------------- problem constants ----------------
#define Hd   4096
#define Id   14336
#define Rr   159
#define R2   318
#define R4   636
#define Ee   8
#define Tt   4096
#define PLD  640     // g_P row stride (gate 0..317, up 320..637, pads zero-init)
#define QLD  320     // g_Q row stride
#define KC   64      // K chunk (64 bf16 = 128B row)

// ---------------- scratch ----------------
__device__ int   g_cnt[Ee];
__device__ int   g_off[Ee];
__device__ int   g_tok[Ee][Tt];
__device__ float g_wt[Ee][Tt];
__device__ float g_P[(size_t)8192 * PLD];
__device__ float g_hbuf[(size_t)8192 * Id];
__device__ float g_Q[(size_t)8192 * QLD];

// ---------------- helpers ----------------
__device__ __forceinline__ uint32_t smem_to_u32(const void* p) {
    uint32_t a;
    asm("{ .reg .u64 t; cvta.to.shared.u64 t, %1; cvt.u32.u64 %0, t; }" : "=r"(a) : "l"(p));
    return a;
}

#define LDSM4(r, a)                                                               \
    asm volatile("ldmatrix.sync.aligned.m8n8.x4.shared.b16 {%0,%1,%2,%3}, [%4];"  \
        : "=r"((r)[0]), "=r"((r)[1]), "=r"((r)[2]), "=r"((r)[3]) : "r"(a))

#define MMA16816(d, a, b)                                                         \
    asm volatile("mma.sync.aligned.m16n8k16.row.col.f32.bf16.bf16.f32 "           \
        "{%0,%1,%2,%3},{%4,%5,%6,%7},{%8,%9},{%0,%1,%2,%3};"                      \
        : "+f"((d)[0]), "+f"((d)[1]), "+f"((d)[2]), "+f"((d)[3])                  \
        : "r"((a)[0]), "r"((a)[1]), "r"((a)[2]), "r"((a)[3]),                     \
          "r"((b)[0]), "r"((b)[1]))

// tile: 128 rows x 64 bf16 cols, 128B/row, chunk = 16B, swizzle chunk^=(row&7)
__device__ __forceinline__ uint32_t tile_off(int row, int chunk) {
    return (uint32_t)(row * 128 + ((chunk ^ (row & 7)) << 4));
}

// convert 8 floats -> hi bf16x4 word-pairs + lo residual
__device__ __forceinline__ void cvt8(const float* f, uint4& h4, uint4& l4) {
    uint32_t hw[4], lw[4];
#pragma unroll
    for (int i = 0; i < 4; i++) {
        __nv_bfloat162 h2 = __floats2bfloat162_rn(f[2 * i], f[2 * i + 1]);
        float2 hf = __bfloat1622float2(h2);
        __nv_bfloat162 l2 = __floats2bfloat162_rn(f[2 * i] - hf.x, f[2 * i + 1] - hf.y);
        hw[i] = *reinterpret_cast<uint32_t*>(&h2);
        lw[i] = *reinterpret_cast<uint32_t*>(&l2);
    }
    h4 = make_uint4(hw[0], hw[1], hw[2], hw[3]);
    l4 = make_uint4(lw[0], lw[1], lw[2], lw[3]);
}

// ---------------- router / routing ----------------
__device__ __forceinline__ float warpsum(float v) {
#pragma unroll
    for (int o = 16; o; o >>= 1) v += __shfl_down_sync(0xffffffffu, v, o);
    return v;
}

__global__ __launch_bounds__(256) void router_kernel(
    const float* __restrict__ x, const float* __restrict__ gw, float* __restrict__ logits)
{
    int t = blockIdx.x;
    const float4* xr = (const float4*)(x + (size_t)t * Hd);
    float acc[Ee];
#pragma unroll
    for (int e = 0; e < Ee; e++) acc[e] = 0.f;
    for (int i = threadIdx.x; i < Hd / 4; i += 256) {
        float4 xv = xr[i];
#pragma unroll
        for (int e = 0; e < Ee; e++) {
            float4 wv = ((const float4*)(gw + (size_t)e * Hd))[i];
            acc[e] = fmaf(xv.x, wv.x, fmaf(xv.y, wv.y, fmaf(xv.z, wv.z, fmaf(xv.w, wv.w, acc[e]))));
        }
    }
    __shared__ float red[8][Ee];
    int lane = threadIdx.x & 31, w = threadIdx.x >> 5;
#pragma unroll
    for (int e = 0; e < Ee; e++) {
        float s = warpsum(acc[e]);
        if (lane == 0) red[w][e] = s;
    }
    __syncthreads();
    if (threadIdx.x < Ee) {
        float s = 0.f;
#pragma unroll
        for (int w2 = 0; w2 < 8; w2++) s += red[w2][threadIdx.x];
        logits[(size_t)t * Ee + threadIdx.x] = s;
    }
}

__global__ void prep_kernel() { if (threadIdx.x < Ee) g_cnt[threadIdx.x] = 0; }

__global__ void route_kernel(const float* __restrict__ logits)
{
    int t = blockIdx.x * blockDim.x + threadIdx.x;
    if (t >= Tt) return;
    float l[Ee];
#pragma unroll
    for (int e = 0; e < Ee; e++) l[e] = logits[(size_t)t * Ee + e];
    int i1 = 0; float m1 = l[0];
#pragma unroll
    for (int e = 1; e < Ee; e++) if (l[e] > m1) { m1 = l[e]; i1 = e; }
    int i2 = -1; float m2 = -1e30f;
#pragma unroll
    for (int e = 0; e < Ee; e++) if (e != i1 && l[e] > m2) { m2 = l[e]; i2 = e; }
    float w1 = 1.f / (1.f + expf(m2 - m1));
    float w2 = 1.f - w1;
    int p = atomicAdd(&g_cnt[i1], 1); g_tok[i1][p] = t; g_wt[i1][p] = w1;
    p     = atomicAdd(&g_cnt[i2], 1); g_tok[i2][p] = t; g_wt[i2][p] = w2;
}

__global__ void offsets_kernel()
{
    if (threadIdx.x == 0) {
        int s = 0;
        for (int e = 0; e < Ee; e++) { g_off[e] = s; s += g_cnt[e]; }
    }
}

// ---------------- HMMA MoE GEMM ----------------
// KIND 0: P   = gather(x)          @ [w1v;v1;w3v;v3]^T   K=4096, NC=64
// KIND 1: h   = silu(P_g @ W1U^T) * (P_u @ W3U^T)        K=320x2 passes, NC=5
// KIND 2: Q   = h @ [w2v;v2]^T                           K=14336, NC=224
// KIND 3: out += wt * (Q @ [w2u;u2]^T)                   K=320, NC=5
//
// CTA: 256 thr = 8 warps (2M x 4N), tile 128x128, warp 64x32, frag m16n8k16.
// SMEM: 2 buf x {Ah,Al,Bh,Bl} x 16KB = 128KB (+64KB silu stash for KIND1).

#define BUF_B   65536
#define TILE_B  16384

template <int KIND>
__global__ __launch_bounds__(256, 1) void moe_mma(
    const float* __restrict__ A0,
    const float* __restrict__ B0, const float* __restrict__ B1,
    const float* __restrict__ B2, const float* __restrict__ B3,
    float* __restrict__ outp)
{
    constexpr int NC    = (KIND == 0) ? 64 : (KIND == 2) ? 224 : 5;
    constexpr int NPASS = (KIND == 1) ? 2 : 1;

    int e     = blockIdx.z;
    int n_e   = g_cnt[e];
    int mbase = blockIdx.x * 128;
    if (mbase >= n_e) return;
    int nbase = blockIdx.y * 128;
    int off   = g_off[e];

    extern __shared__ char smem[];
    uint32_t smem_u32 = smem_to_u32(smem);
    float* sg = (float*)(smem + 2 * BUF_B);   // KIND1 silu stash (64KB)

    int tid = threadIdx.x, lane = tid & 31, wid = tid >> 5;
    int wm = wid & 1, wn = wid >> 1;
    int lrow = tid >> 1, lhalf = tid & 1;
    int ml = mbase + lrow;

    float acc[4][4][4];
#pragma unroll
    for (int i = 0; i < 4; i++)
#pragma unroll
        for (int j = 0; j < 4; j++)
#pragma unroll
            for (int q = 0; q < 4; q++) acc[i][j][q] = 0.f;

    // A row base (c-independent)
    const float* Abase = nullptr;
    if (ml < n_e) {
        if (KIND == 0)      Abase = A0 + (size_t)g_tok[e][ml] * Hd;
        else if (KIND == 1) Abase = g_P + (size_t)(off + ml) * PLD;
        else if (KIND == 2) Abase = g_hbuf + (size_t)(off + ml) * Id;
        else                Abase = g_Q + (size_t)(off + ml) * QLD;
    }
    // B row base (vector kinds)
    const float* Bbase = nullptr;
    if (KIND == 0) {
        int j = nbase + lrow;
        if (j < R4) {
            const float* w; int jr;
            if      (j < Rr)     { w = B0; jr = j; }
            else if (j < 2 * Rr) { w = B1; jr = j - Rr; }
            else if (j < 3 * Rr) { w = B2; jr = j - 2 * Rr; }
            else                 { w = B3; jr = j - 3 * Rr; }
            Bbase = w + ((size_t)e * Rr + jr) * Hd;
        }
    } else if (KIND == 2) {
        int j = nbase + lrow;
        if (j < R2)
            Bbase = (j < Rr) ? B0 + ((size_t)e * Rr + j) * Id
                             : B1 + ((size_t)e * Rr + (j - Rr)) * Id;
    }

    float la[32], lb[32];

    auto ldchunk = [&](int p, int c) {
        int aoff = c * KC + ((KIND == 1) ? p * 320 : 0);
        if (Abase) {
#pragma unroll
            for (int i = 0; i < 8; i++)
                *(float4*)(la + 4 * i) = ((const float4*)(Abase + aoff))[lhalf * 8 + i];
        } else {
#pragma unroll
            for (int i = 0; i < 8; i++)
                *(float4*)(la + 4 * i) = make_float4(0.f, 0.f, 0.f, 0.f);
        }
        if (KIND == 0 || KIND == 2) {
            if (Bbase) {
#pragma unroll
                for (int i = 0; i < 8; i++)
                    *(float4*)(lb + 4 * i) = ((const float4*)(Bbase + c * KC))[lhalf * 8 + i];
            } else {
#pragma unroll
                for (int i = 0; i < 8; i++)
                    *(float4*)(lb + 4 * i) = make_float4(0.f, 0.f, 0.f, 0.f);
            }
        } else {
            const float *W, *U;
            if (KIND == 1) {
                size_t eo = (size_t)e * Id * Rr;
                W = (p ? B2 : B0) + eo; U = (p ? B3 : B1) + eo;
            } else {
                size_t eo = (size_t)e * Hd * Rr;
                W = B0 + eo; U = B1 + eo;
            }
            size_t nr = (size_t)(nbase + lrow) * Rr;
#pragma unroll
            for (int i = 0; i < 32; i++) {
                int kg = c * KC + lhalf * 32 + i;
                lb[i] = (kg < Rr) ? W[nr + kg] : ((kg < R2) ? U[nr + kg - Rr] : 0.f);
            }
        }
    };

    auto stchunk = [&](int buf) {
        char* b  = smem + buf * BUF_B;
        char* Ah = b;  char* Al = b + TILE_B;
        char* Bh = b + 2 * TILE_B;  char* Bl = b + 3 * TILE_B;
#pragma unroll
        for (int i = 0; i < 4; i++) {
            uint4 h, l;
            uint32_t o = tile_off(lrow, lhalf * 4 + i);
            cvt8(la + 8 * i, h, l);
            *(uint4*)(Ah + o) = h;  *(uint4*)(Al + o) = l;
            cvt8(lb + 8 * i, h, l);
            *(uint4*)(Bh + o) = h;  *(uint4*)(Bl + o) = l;
        }
    };

    auto compute = [&](int buf) {
        uint32_t base = smem_u32 + buf * BUF_B;
#pragma unroll
        for (int ks = 0; ks < 4; ks++) {
            uint32_t Ahf[4][4], Alf[4][4], Bhf[4][2], Blf[4][2];
#pragma unroll
            for (int mf = 0; mf < 4; mf++) {
                int ar = wm * 64 + mf * 16 + (lane & 15);
                uint32_t o = tile_off(ar, ks * 2 + (lane >> 4));
                LDSM4(Ahf[mf], base + o);
                LDSM4(Alf[mf], base + TILE_B + o);
            }
#pragma unroll
            for (int g = 0; g < 2; g++) {
                int br = wn * 32 + g * 16 + ((lane >> 4) << 3) + (lane & 7);
                uint32_t o = tile_off(br, ks * 2 + ((lane >> 3) & 1));
                uint32_t r[4];
                LDSM4(r, base + 2 * TILE_B + o);
                Bhf[2 * g][0] = r[0]; Bhf[2 * g][1] = r[1];
                Bhf[2 * g + 1][0] = r[2]; Bhf[2 * g + 1][1] = r[3];
                LDSM4(r, base + 3 * TILE_B + o);
                Blf[2 * g][0] = r[0]; Blf[2 * g][1] = r[1];
                Blf[2 * g + 1][0] = r[2]; Blf[2 * g + 1][1] = r[3];
            }
#pragma unroll
            for (int mf = 0; mf < 4; mf++)
#pragma unroll
                for (int nf = 0; nf < 4; nf++) MMA16816(acc[mf][nf], Ahf[mf], Bhf[nf]);
#pragma unroll
            for (int mf = 0; mf < 4; mf++)
#pragma unroll
                for (int nf = 0; nf < 4; nf++) MMA16816(acc[mf][nf], Ahf[mf], Blf[nf]);
#pragma unroll
            for (int mf = 0; mf < 4; mf++)
#pragma unroll
                for (int nf = 0; nf < 4; nf++) MMA16816(acc[mf][nf], Alf[mf], Bhf[nf]);
        }
    };

    for (int p = 0; p < NPASS; p++) {
        ldchunk(p, 0);
        stchunk(0);
        __syncthreads();
        int buf = 0;
        for (int c = 0; c < NC; c++) {
            bool more = (c + 1 < NC);
            if (more) ldchunk(p, c + 1);
            compute(buf);
            if (more) stchunk(buf ^ 1);
            __syncthreads();
            if (more) buf ^= 1;
        }
        if (KIND == 1 && p == 0) {
#pragma unroll
            for (int mf = 0; mf < 4; mf++)
#pragma unroll
                for (int nf = 0; nf < 4; nf++)
#pragma unroll
                    for (int q = 0; q < 4; q++) {
                        float g = acc[mf][nf][q];
                        sg[((mf * 4 + nf) * 4 + q) * 256 + tid] = g / (1.f + __expf(-g));
                        acc[mf][nf][q] = 0.f;
                    }
        }
    }

    // ---------------- epilogue ----------------
#pragma unroll
    for (int mf = 0; mf < 4; mf++)
#pragma unroll
        for (int nf = 0; nf < 4; nf++)
#pragma unroll
            for (int q = 0; q < 4; q++) {
                int rloc = wm * 64 + mf * 16 + (lane >> 2) + ((q >= 2) ? 8 : 0);
                int m = mbase + rloc;
                if (m >= n_e) continue;
                int col = nbase + wn * 32 + nf * 8 + (lane & 3) * 2 + (q & 1);
                float v = acc[mf][nf][q];
                if (KIND == 0) {
                    if (col < R4) {
                        int pc = (col < R2) ? col : col + 2;
                        g_P[(size_t)(off + m) * PLD + pc] = v;
                    }
                } else if (KIND == 1) {
                    float sgv = sg[((mf * 4 + nf) * 4 + q) * 256 + tid];
                    g_hbuf[(size_t)(off + m) * Id + col] = sgv * v;
                } else if (KIND == 2) {
                    if (col < R2) g_Q[(size_t)(off + m) * QLD + col] = v;
                } else {
                    float wt  = g_wt[e][m];
                    int   tok = g_tok[e][m];
                    atomicAdd(outp + (size_t)tok * Hd + col, wt * v);
                }
            }
}

// ---------------- launch ----------------
extern "C" void kernel_launch(void* const* d_in, const int* in_sizes, int n_in,
                              void* d_out, int out_size)
{
    const float* x    = (const float*)d_in[0];
    const float* gw   = (const float*)d_in[1];
    const float* w1u  = (const float*)d_in[2];
    const float* w1v  = (const float*)d_in[3];
    const float* w2u  = (const float*)d_in[4];
    const float* w2v  = (const float*)d_in[5];
    const float* w3u  = (const float*)d_in[6];
    const float* w3v  = (const float*)d_in[7];
    const float* u1   = (const float*)d_in[8];
    const float* v1   = (const float*)d_in[9];
    const float* u2   = (const float*)d_in[10];
    const float* v2   = (const float*)d_in[11];
    const float* u3   = (const float*)d_in[12];
    const float* v3   = (const float*)d_in[13];

    float* outp   = (float*)d_out;
    float* logits = outp + (size_t)Tt * Hd;

    static bool attr_done = false;
    if (!attr_done) {
        cudaFuncSetAttribute(moe_mma<0>, cudaFuncAttributeMaxDynamicSharedMemorySize, 2 * BUF_B);
        cudaFuncSetAttribute(moe_mma<1>, cudaFuncAttributeMaxDynamicSharedMemorySize, 2 * BUF_B + 65536);
        cudaFuncSetAttribute(moe_mma<2>, cudaFuncAttributeMaxDynamicSharedMemorySize, 2 * BUF_B);
        cudaFuncSetAttribute(moe_mma<3>, cudaFuncAttributeMaxDynamicSharedMemorySize, 2 * BUF_B);
        attr_done = true;
    }

    cudaMemsetAsync(outp, 0, (size_t)Tt * Hd * sizeof(float));
    prep_kernel<<<1, 32>>>();
    router_kernel<<<Tt, 256>>>(x, gw, logits);
    route_kernel<<<Tt / 256, 256>>>(logits);
    offsets_kernel<<<1, 32>>>();

    // P = gather(x) @ [w1v; v1; w3v; v3]^T
    moe_mma<0><<<dim3(32, 5, 8), 256, 2 * BUF_B>>>(x, w1v, v1, w3v, v3, nullptr);
    // h = silu(P_g @ [w1u;u1]^T) * (P_u @ [w3u;u3]^T)
    moe_mma<1><<<dim3(32, 112, 8), 256, 2 * BUF_B + 65536>>>(nullptr, w1u, u1, w3u, u3, nullptr);
    // Q = h @ [w2v; v2]^T
    moe_mma<2><<<dim3(32, 3, 8), 256, 2 * BUF_B>>>(nullptr, w2v, v2, nullptr, nullptr, nullptr);
    // out += wt * (Q @ [w2u; u2]^T)
    moe_mma<3><<<dim3(32, 32, 8), 256, 2 * BUF_B>>>(nullptr, w2u, u2, nullptr, nullptr, outp);
}

// round 5
// speedup vs baseline: 3.7028x; 1.8839x over previous
#include <cuda_runtime.h>
#include <cuda_fp16.h>
#include <cstdint>
#include <math.h>

// ---------------- problem constants ----------------
#define Hd   4096
#define Id   14336
#define Rr   159
#define R2   318
#define Ee   8
#define Tt   4096
#define RT   8192          // total routed rows (Tt * topk)

#define STAGES  3
#define TILE_B  16384      // one 128x64 fp16 tile
#define STAGE_B 49152      // Ah + Al + B
#define QSPLIT  4
#define QNC     56         // 224/4

// ---------------- scratch (device globals) ----------------
__device__ int   g_cnt[Ee];
__device__ int   g_off[Ee];
__device__ int   g_tok[Ee][Tt];
__device__ float g_wt[Ee][Tt];

__device__ __align__(16) __half g_xh[(size_t)Tt * Hd];
__device__ __align__(16) __half g_xl[(size_t)Tt * Hd];
__device__ __align__(16) __half g_Bp[(size_t)Ee * 640 * Hd];      // rows: 0-317 gate(w1v,v1), 320-637 up(w3v,v3)
__device__ __align__(16) __half g_Bg[(size_t)Ee * Id * 320];      // [I,320] = w1u|u1|pad
__device__ __align__(16) __half g_Bu[(size_t)Ee * Id * 320];      // w3u|u3|pad
__device__ __align__(16) __half g_Bq[(size_t)Ee * 384 * Id];      // rows: w2v|v2|pad
__device__ __align__(16) __half g_Bo[(size_t)Ee * Hd * 320];      // w2u|u2|pad
__device__ __align__(16) __half g_Ph[(size_t)RT * 640];
__device__ __align__(16) __half g_Pl[(size_t)RT * 640];
__device__ __align__(16) __half g_hh[(size_t)RT * Id];
__device__ __align__(16) __half g_hl[(size_t)RT * Id];
__device__ float g_Qf[(size_t)QSPLIT * RT * 320];
__device__ __align__(16) __half g_Qh[(size_t)RT * 320];
__device__ __align__(16) __half g_Ql[(size_t)RT * 320];

// ---------------- PTX helpers ----------------
__device__ __forceinline__ uint32_t smem_to_u32(const void* p) {
    uint32_t a;
    asm("{ .reg .u64 t; cvta.to.shared.u64 t, %1; cvt.u32.u64 %0, t; }" : "=r"(a) : "l"(p));
    return a;
}
#define LDSM4(r, a)                                                               \
    asm volatile("ldmatrix.sync.aligned.m8n8.x4.shared.b16 {%0,%1,%2,%3}, [%4];"  \
        : "=r"((r)[0]), "=r"((r)[1]), "=r"((r)[2]), "=r"((r)[3]) : "r"(a))
#define MMA16816(d, a, b)                                                         \
    asm volatile("mma.sync.aligned.m16n8k16.row.col.f32.f16.f16.f32 "             \
        "{%0,%1,%2,%3},{%4,%5,%6,%7},{%8,%9},{%0,%1,%2,%3};"                      \
        : "+f"((d)[0]), "+f"((d)[1]), "+f"((d)[2]), "+f"((d)[3])                  \
        : "r"((a)[0]), "r"((a)[1]), "r"((a)[2]), "r"((a)[3]),                     \
          "r"((b)[0]), "r"((b)[1]))
#define CP16(dst, src, sz)                                                        \
    asm volatile("cp.async.cg.shared.global [%0], [%1], 16, %2;"                  \
        :: "r"(dst), "l"(src), "r"(sz))
#define CP_COMMIT() asm volatile("cp.async.commit_group;" ::: "memory")
#define CP_WAIT(n)  asm volatile("cp.async.wait_group %0;" :: "n"(n) : "memory")

__device__ __forceinline__ uint32_t tile_off(int row, int chunk) {
    return (uint32_t)(row * 128 + ((chunk ^ (row & 7)) << 4));
}
__device__ __forceinline__ void split2_store(float a, float b, __half* H, __half* L) {
    __half2 h = __floats2half2_rn(a, b);
    float2 f = __half22float2(h);
    __half2 l = __floats2half2_rn(a - f.x, b - f.y);
    *(__half2*)H = h;
    *(__half2*)L = l;
}

// ---------------- conversion / packing kernels ----------------
__global__ __launch_bounds__(256) void k_split_x(const float* __restrict__ x) {
    int t = blockIdx.x;
    const float4* src = (const float4*)(x + (size_t)t * Hd);
    __half2* dh = (__half2*)(g_xh + (size_t)t * Hd);
    __half2* dl = (__half2*)(g_xl + (size_t)t * Hd);
    for (int i = threadIdx.x; i < Hd / 4; i += 256) {
        float4 v = src[i];
        __half2 h0 = __floats2half2_rn(v.x, v.y), h1 = __floats2half2_rn(v.z, v.w);
        float2 f0 = __half22float2(h0), f1 = __half22float2(h1);
        dh[2 * i] = h0; dh[2 * i + 1] = h1;
        dl[2 * i]     = __floats2half2_rn(v.x - f0.x, v.y - f0.y);
        dl[2 * i + 1] = __floats2half2_rn(v.z - f1.x, v.w - f1.y);
    }
}

__global__ __launch_bounds__(256) void k_conv_Bp(
    const float* __restrict__ w1v, const float* __restrict__ v1,
    const float* __restrict__ w3v, const float* __restrict__ v3)
{
    int j = blockIdx.x, e = blockIdx.y;
    const float* src = nullptr;
    if      (j < Rr)            src = w1v + ((size_t)e * Rr + j) * Hd;
    else if (j < R2)            src = v1  + ((size_t)e * Rr + j - Rr) * Hd;
    else if (j >= 320 && j < 320 + Rr) src = w3v + ((size_t)e * Rr + j - 320) * Hd;
    else if (j >= 320 + Rr && j < 320 + R2) src = v3 + ((size_t)e * Rr + j - 320 - Rr) * Hd;
    __half2* dst = (__half2*)(g_Bp + ((size_t)e * 640 + j) * Hd);
    for (int i = threadIdx.x; i < Hd / 2; i += 256) {
        float2 v = src ? ((const float2*)src)[i] : make_float2(0.f, 0.f);
        dst[i] = __floats2half2_rn(v.x, v.y);
    }
}

template <int SEL>  // 0: Bg(w1u,u1,I)  1: Bu(w3u,u3,I)  2: Bo(w2u,u2,H)
__global__ __launch_bounds__(256) void k_pack320(
    const float* __restrict__ W, const float* __restrict__ U)
{
    constexpr int ROWS = (SEL == 2) ? Hd : Id;
    __half* D = (SEL == 0) ? g_Bg : (SEL == 1) ? g_Bu : g_Bo;
    int e = blockIdx.y;
    int r = blockIdx.x * 8 + (threadIdx.x >> 5);
    int lane = threadIdx.x & 31;
    const float* w = W + ((size_t)e * ROWS + r) * Rr;
    const float* u = U + ((size_t)e * ROWS + r) * Rr;
    __half* d = D + ((size_t)e * ROWS + r) * 320;
    for (int k = lane; k < 320; k += 32) {
        float v = (k < Rr) ? w[k] : ((k < R2) ? u[k - Rr] : 0.f);
        d[k] = __float2half_rn(v);
    }
}

__global__ __launch_bounds__(256) void k_conv_Bq(
    const float* __restrict__ w2v, const float* __restrict__ v2)
{
    int j = blockIdx.x, e = blockIdx.y;
    const float* src = nullptr;
    if      (j < Rr) src = w2v + ((size_t)e * Rr + j) * Id;
    else if (j < R2) src = v2  + ((size_t)e * Rr + j - Rr) * Id;
    __half2* dst = (__half2*)(g_Bq + ((size_t)e * 384 + j) * Id);
    for (int i = threadIdx.x; i < Id / 2; i += 256) {
        float2 v = src ? ((const float2*)src)[i] : make_float2(0.f, 0.f);
        dst[i] = __floats2half2_rn(v.x, v.y);
    }
}

__global__ __launch_bounds__(256) void k_qsum() {
    size_t i = (size_t)blockIdx.x * 256 + threadIdx.x;   // grid covers RT*320
    constexpr size_t S = (size_t)RT * 320;
    float s = g_Qf[i] + g_Qf[i + S] + g_Qf[i + 2 * S] + g_Qf[i + 3 * S];
    __half h = __float2half_rn(s);
    g_Qh[i] = h;
    g_Ql[i] = __float2half_rn(s - __half2float(h));
}

// ---------------- router / routing ----------------
__device__ __forceinline__ float warpsum(float v) {
#pragma unroll
    for (int o = 16; o; o >>= 1) v += __shfl_down_sync(0xffffffffu, v, o);
    return v;
}

__global__ __launch_bounds__(256) void router_kernel(
    const float* __restrict__ x, const float* __restrict__ gw, float* __restrict__ logits)
{
    int t = blockIdx.x;
    const float4* xr = (const float4*)(x + (size_t)t * Hd);
    float acc[Ee];
#pragma unroll
    for (int e = 0; e < Ee; e++) acc[e] = 0.f;
    for (int i = threadIdx.x; i < Hd / 4; i += 256) {
        float4 xv = xr[i];
#pragma unroll
        for (int e = 0; e < Ee; e++) {
            float4 wv = ((const float4*)(gw + (size_t)e * Hd))[i];
            acc[e] = fmaf(xv.x, wv.x, fmaf(xv.y, wv.y, fmaf(xv.z, wv.z, fmaf(xv.w, wv.w, acc[e]))));
        }
    }
    __shared__ float red[8][Ee];
    int lane = threadIdx.x & 31, w = threadIdx.x >> 5;
#pragma unroll
    for (int e = 0; e < Ee; e++) {
        float s = warpsum(acc[e]);
        if (lane == 0) red[w][e] = s;
    }
    __syncthreads();
    if (threadIdx.x < Ee) {
        float s = 0.f;
#pragma unroll
        for (int w2 = 0; w2 < 8; w2++) s += red[w2][threadIdx.x];
        logits[(size_t)t * Ee + threadIdx.x] = s;
    }
}

__global__ void prep_kernel() { if (threadIdx.x < Ee) g_cnt[threadIdx.x] = 0; }

__global__ void route_kernel(const float* __restrict__ logits)
{
    int t = blockIdx.x * blockDim.x + threadIdx.x;
    if (t >= Tt) return;
    float l[Ee];
#pragma unroll
    for (int e = 0; e < Ee; e++) l[e] = logits[(size_t)t * Ee + e];
    int i1 = 0; float m1 = l[0];
#pragma unroll
    for (int e = 1; e < Ee; e++) if (l[e] > m1) { m1 = l[e]; i1 = e; }
    int i2 = -1; float m2 = -1e30f;
#pragma unroll
    for (int e = 0; e < Ee; e++) if (e != i1 && l[e] > m2) { m2 = l[e]; i2 = e; }
    float w1 = 1.f / (1.f + expf(m2 - m1));
    float w2 = 1.f - w1;
    int p = atomicAdd(&g_cnt[i1], 1); g_tok[i1][p] = t; g_wt[i1][p] = w1;
    p     = atomicAdd(&g_cnt[i2], 1); g_tok[i2][p] = t; g_wt[i2][p] = w2;
}

__global__ void offsets_kernel()
{
    if (threadIdx.x == 0) {
        int s = 0;
        for (int e = 0; e < Ee; e++) { g_off[e] = s; s += g_cnt[e]; }
    }
}

// ---------------- fp16 split-2 HMMA GEMM ----------------
// KIND 0: P = gather(x) @ Bp^T       K=4096 NC=64  N=640(5)
// KIND 1: h = silu(P_g@Bg^T)*(P_u@Bu^T)  K=320 NC=5x2  N=14336(112)
// KIND 2: Qf[slice] = h @ Bq^T       K=14336 4 slices x NC=56  N=384(3)
// KIND 3: out += wt * (Q @ Bo^T)     K=320 NC=5  N=4096(32)
template <int KIND>
__global__ __launch_bounds__(256, 1) void moe_mma(float* __restrict__ outp)
{
    constexpr int NCc   = (KIND == 0) ? 64 : (KIND == 2) ? QNC : 5;
    constexpr int NPASS = (KIND == 1) ? 2 : 1;
    constexpr int Ka    = (KIND == 0) ? Hd : (KIND == 1) ? 640 : (KIND == 2) ? Id : 320;
    constexpr int Kb    = (KIND == 0) ? Hd : (KIND == 2) ? Id : 320;
    constexpr int Brows = (KIND == 0) ? 640 : (KIND == 1) ? Id : (KIND == 2) ? 384 : Hd;

    int e     = blockIdx.z;
    int n_e   = g_cnt[e];
    int mbase = blockIdx.x * 128;
    if (mbase >= n_e) return;
    int ntile  = (KIND == 2) ? (blockIdx.y % 3) : blockIdx.y;
    int kslice = (KIND == 2) ? (blockIdx.y / 3) : 0;
    int cbase  = kslice * QNC;
    int nbase  = ntile * 128;
    int off    = g_off[e];

    extern __shared__ char smem[];
    uint32_t smem_u32 = smem_to_u32(smem);
    float* sg = (float*)(smem + STAGES * STAGE_B);   // KIND1 silu stash

    int tid = threadIdx.x, lane = tid & 31, wid = tid >> 5;
    int wm = wid & 1, wn = wid >> 1;
    int row = tid >> 1, half = tid & 1;
    int ml = mbase + row;
    unsigned szA = (ml < n_e) ? 16u : 0u;

    // A row bases
    const __half *Ah_row, *Al_row;
    if (KIND == 0) {
        int t = (ml < n_e) ? g_tok[e][ml] : 0;
        Ah_row = g_xh + (size_t)t * Hd;
        Al_row = g_xl + (size_t)t * Hd;
    } else {
        size_t r = (size_t)off + ((ml < n_e) ? ml : 0);
        if (KIND == 1)      { Ah_row = g_Ph + r * 640; Al_row = g_Pl + r * 640; }
        else if (KIND == 2) { Ah_row = g_hh + r * Id;  Al_row = g_hl + r * Id; }
        else                { Ah_row = g_Qh + r * 320; Al_row = g_Ql + r * 320; }
    }

    float acc[4][4][4];
#pragma unroll
    for (int i = 0; i < 4; i++)
#pragma unroll
        for (int j = 0; j < 4; j++)
#pragma unroll
            for (int q = 0; q < 4; q++) acc[i][j][q] = 0.f;

    for (int p = 0; p < NPASS; p++) {
        int acoff = (KIND == 1) ? p * 320 : 0;
        const __half* Bm = (KIND == 0) ? g_Bp : (KIND == 1) ? (p ? g_Bu : g_Bg)
                         : (KIND == 2) ? g_Bq : g_Bo;
        const __half* Brow = Bm + ((size_t)e * Brows + nbase + row) * Kb;

        auto issue_load = [&](int st, int c) {
            uint32_t sb = smem_u32 + st * STAGE_B;
            int col = (cbase + c) * 64 + half * 32;
#pragma unroll
            for (int i = 0; i < 4; i++) {
                uint32_t so = tile_off(row, half * 4 + i);
                CP16(sb + so,              Ah_row + acoff + col + i * 8, szA);
                CP16(sb + TILE_B + so,     Al_row + acoff + col + i * 8, szA);
                CP16(sb + 2 * TILE_B + so, Brow + col + i * 8, 16u);
            }
        };

        auto compute = [&](int st) {
            uint32_t base = smem_u32 + st * STAGE_B;
#pragma unroll
            for (int ks = 0; ks < 4; ks++) {
                uint32_t Ahf[4][4], Alf[4][4], Bf[4][2];
#pragma unroll
                for (int mf = 0; mf < 4; mf++) {
                    int ar = wm * 64 + mf * 16 + (lane & 15);
                    uint32_t o = tile_off(ar, ks * 2 + (lane >> 4));
                    LDSM4(Ahf[mf], base + o);
                    LDSM4(Alf[mf], base + TILE_B + o);
                }
#pragma unroll
                for (int g = 0; g < 2; g++) {
                    int br = wn * 32 + g * 16 + ((lane >> 4) << 3) + (lane & 7);
                    uint32_t o = tile_off(br, ks * 2 + ((lane >> 3) & 1));
                    uint32_t r[4];
                    LDSM4(r, base + 2 * TILE_B + o);
                    Bf[2 * g][0] = r[0]; Bf[2 * g][1] = r[1];
                    Bf[2 * g + 1][0] = r[2]; Bf[2 * g + 1][1] = r[3];
                }
#pragma unroll
                for (int mf = 0; mf < 4; mf++)
#pragma unroll
                    for (int nf = 0; nf < 4; nf++) MMA16816(acc[mf][nf], Ahf[mf], Bf[nf]);
#pragma unroll
                for (int mf = 0; mf < 4; mf++)
#pragma unroll
                    for (int nf = 0; nf < 4; nf++) MMA16816(acc[mf][nf], Alf[mf], Bf[nf]);
            }
        };

        // prologue: stages 0..1
        issue_load(0, 0); CP_COMMIT();
        if (NCc > 1) issue_load(1, 1);
        CP_COMMIT();
        CP_WAIT(1);
        __syncthreads();

        for (int c = 0; c < NCc; c++) {
            if (c + 2 < NCc) issue_load((c + 2) % STAGES, c + 2);
            CP_COMMIT();
            compute(c % STAGES);
            CP_WAIT(1);
            __syncthreads();
        }

        if (KIND == 1 && p == 0) {
#pragma unroll
            for (int mf = 0; mf < 4; mf++)
#pragma unroll
                for (int nf = 0; nf < 4; nf++)
#pragma unroll
                    for (int q = 0; q < 4; q++) {
                        float g = acc[mf][nf][q];
                        sg[((mf * 4 + nf) * 4 + q) * 256 + tid] = g / (1.f + __expf(-g));
                        acc[mf][nf][q] = 0.f;
                    }
            __syncthreads();
        }
    }

    // ---------------- epilogue ----------------
    float* qf = (KIND == 2) ? (g_Qf + (size_t)kslice * RT * 320) : nullptr;
#pragma unroll
    for (int mf = 0; mf < 4; mf++)
#pragma unroll
        for (int nf = 0; nf < 4; nf++)
#pragma unroll
            for (int qp = 0; qp < 2; qp++) {
                int r = wm * 64 + mf * 16 + (lane >> 2) + qp * 8;
                int m = mbase + r;
                if (m >= n_e) continue;
                int col = nbase + wn * 32 + nf * 8 + (lane & 3) * 2;
                float v0 = acc[mf][nf][qp * 2 + 0];
                float v1 = acc[mf][nf][qp * 2 + 1];
                if (KIND == 0) {
                    size_t b = (size_t)(off + m) * 640 + col;
                    split2_store(v0, v1, g_Ph + b, g_Pl + b);
                } else if (KIND == 1) {
                    v0 *= sg[((mf * 4 + nf) * 4 + qp * 2 + 0) * 256 + tid];
                    v1 *= sg[((mf * 4 + nf) * 4 + qp * 2 + 1) * 256 + tid];
                    size_t b = (size_t)(off + m) * Id + col;
                    split2_store(v0, v1, g_hh + b, g_hl + b);
                } else if (KIND == 2) {
                    if (col < 320) {
                        size_t b = (size_t)(off + m) * 320 + col;
                        qf[b] = v0; qf[b + 1] = v1;
                    }
                } else {
                    float wt  = g_wt[e][m];
                    int   tok = g_tok[e][m];
                    float* dst = outp + (size_t)tok * Hd + col;
                    atomicAdd(dst, wt * v0);
                    atomicAdd(dst + 1, wt * v1);
                }
            }
}

// ---------------- launch ----------------
extern "C" void kernel_launch(void* const* d_in, const int* in_sizes, int n_in,
                              void* d_out, int out_size)
{
    const float* x    = (const float*)d_in[0];
    const float* gw   = (const float*)d_in[1];
    const float* w1u  = (const float*)d_in[2];
    const float* w1v  = (const float*)d_in[3];
    const float* w2u  = (const float*)d_in[4];
    const float* w2v  = (const float*)d_in[5];
    const float* w3u  = (const float*)d_in[6];
    const float* w3v  = (const float*)d_in[7];
    const float* u1   = (const float*)d_in[8];
    const float* v1   = (const float*)d_in[9];
    const float* u2   = (const float*)d_in[10];
    const float* v2   = (const float*)d_in[11];
    const float* u3   = (const float*)d_in[12];
    const float* v3   = (const float*)d_in[13];

    float* outp   = (float*)d_out;
    float* logits = outp + (size_t)Tt * Hd;

    int smem_g = STAGES * STAGE_B;            // 144KB
    int smem_gu = smem_g + 65536;             // +64KB stash
    cudaFuncSetAttribute(moe_mma<0>, cudaFuncAttributeMaxDynamicSharedMemorySize, smem_g);
    cudaFuncSetAttribute(moe_mma<1>, cudaFuncAttributeMaxDynamicSharedMemorySize, smem_gu);
    cudaFuncSetAttribute(moe_mma<2>, cudaFuncAttributeMaxDynamicSharedMemorySize, smem_g);
    cudaFuncSetAttribute(moe_mma<3>, cudaFuncAttributeMaxDynamicSharedMemorySize, smem_g);

    cudaMemsetAsync(outp, 0, (size_t)Tt * Hd * sizeof(float));

    // pack weights / split activations (independent of routing)
    k_split_x<<<Tt, 256>>>(x);
    k_conv_Bp<<<dim3(640, Ee), 256>>>(w1v, v1, w3v, v3);
    k_pack320<0><<<dim3(Id / 8, Ee), 256>>>(w1u, u1);
    k_pack320<1><<<dim3(Id / 8, Ee), 256>>>(w3u, u3);
    k_pack320<2><<<dim3(Hd / 8, Ee), 256>>>(w2u, u2);
    k_conv_Bq<<<dim3(384, Ee), 256>>>(w2v, v2);

    prep_kernel<<<1, 32>>>();
    router_kernel<<<Tt, 256>>>(x, gw, logits);
    route_kernel<<<Tt / 256, 256>>>(logits);
    offsets_kernel<<<1, 32>>>();

    moe_mma<0><<<dim3(32, 5, Ee),   256, smem_g>>>(nullptr);   // P
    moe_mma<1><<<dim3(32, 112, Ee), 256, smem_gu>>>(nullptr);  // gate/up -> h
    moe_mma<2><<<dim3(32, 12, Ee),  256, smem_g>>>(nullptr);   // Q (4 K-slices)
    k_qsum<<<(RT * 320) / 256, 256>>>();
    moe_mma<3><<<dim3(32, 32, Ee),  256, smem_g>>>(outp);      // scatter
}

// round 6
// speedup vs baseline: 4.9789x; 1.3446x over previous
#include <cuda_runtime.h>
#include <cuda_fp16.h>
#include <cstdint>
#include <math.h>

// ---------------- problem constants ----------------
#define Hd   4096
#define Id   14336
#define Rr   159
#define R2   318
#define Ee   8
#define Tt   4096
#define RT   8192          // total routed rows (Tt * topk)

#define STAGES  3
#define TILE_B  16384      // one 128x64 fp16 tile
#define QSPLIT  4
#define QNC     56         // 224/4

// ---------------- scratch (device globals) ----------------
__device__ int   g_cnt[Ee];
__device__ int   g_off[Ee];
__device__ int   g_tok[Ee][Tt];
__device__ float g_wt[Ee][Tt];

__device__ __align__(16) __half g_xh[(size_t)Tt * Hd];
__device__ __align__(16) __half g_xl[(size_t)Tt * Hd];
__device__ __align__(16) __half g_Bp[(size_t)Ee * 640 * Hd];      // rows: 0-317 gate(w1v,v1), 320-637 up(w3v,v3)
__device__ __align__(16) __half g_Bg[(size_t)Ee * Id * 320];      // [I,320] = w1u|u1|pad
__device__ __align__(16) __half g_Bu[(size_t)Ee * Id * 320];      // w3u|u3|pad
__device__ __align__(16) __half g_Bq[(size_t)Ee * 384 * Id];      // rows: w2v|v2|pad
__device__ __align__(16) __half g_Bo[(size_t)Ee * Hd * 320];      // w2u|u2|pad
__device__ __align__(16) __half g_Ph[(size_t)RT * 640];           // hi only (A of gate/up)
__device__ __align__(16) __half g_hh[(size_t)RT * Id];            // hi only (A of Q)
__device__ float g_Qf[(size_t)QSPLIT * RT * 320];
__device__ __align__(16) __half g_Qh[(size_t)RT * 320];
__device__ __align__(16) __half g_Ql[(size_t)RT * 320];

// ---------------- PTX helpers ----------------
__device__ __forceinline__ uint32_t smem_to_u32(const void* p) {
    uint32_t a;
    asm("{ .reg .u64 t; cvta.to.shared.u64 t, %1; cvt.u32.u64 %0, t; }" : "=r"(a) : "l"(p));
    return a;
}
#define LDSM4(r, a)                                                               \
    asm volatile("ldmatrix.sync.aligned.m8n8.x4.shared.b16 {%0,%1,%2,%3}, [%4];"  \
        : "=r"((r)[0]), "=r"((r)[1]), "=r"((r)[2]), "=r"((r)[3]) : "r"(a))
#define MMA16816(d, a, b)                                                         \
    asm volatile("mma.sync.aligned.m16n8k16.row.col.f32.f16.f16.f32 "             \
        "{%0,%1,%2,%3},{%4,%5,%6,%7},{%8,%9},{%0,%1,%2,%3};"                      \
        : "+f"((d)[0]), "+f"((d)[1]), "+f"((d)[2]), "+f"((d)[3])                  \
        : "r"((a)[0]), "r"((a)[1]), "r"((a)[2]), "r"((a)[3]),                     \
          "r"((b)[0]), "r"((b)[1]))
#define CP16(dst, src, sz)                                                        \
    asm volatile("cp.async.cg.shared.global [%0], [%1], 16, %2;"                  \
        :: "r"(dst), "l"(src), "r"(sz))
#define CP_COMMIT() asm volatile("cp.async.commit_group;" ::: "memory")
#define CP_WAIT(n)  asm volatile("cp.async.wait_group %0;" :: "n"(n) : "memory")

__device__ __forceinline__ uint32_t tile_off(int row, int chunk) {
    return (uint32_t)(row * 128 + ((chunk ^ (row & 7)) << 4));
}

// ---------------- conversion / packing kernels ----------------
__global__ __launch_bounds__(256) void k_split_x(const float* __restrict__ x) {
    int t = blockIdx.x;
    const float4* src = (const float4*)(x + (size_t)t * Hd);
    __half2* dh = (__half2*)(g_xh + (size_t)t * Hd);
    __half2* dl = (__half2*)(g_xl + (size_t)t * Hd);
    for (int i = threadIdx.x; i < Hd / 4; i += 256) {
        float4 v = src[i];
        __half2 h0 = __floats2half2_rn(v.x, v.y), h1 = __floats2half2_rn(v.z, v.w);
        float2 f0 = __half22float2(h0), f1 = __half22float2(h1);
        dh[2 * i] = h0; dh[2 * i + 1] = h1;
        dl[2 * i]     = __floats2half2_rn(v.x - f0.x, v.y - f0.y);
        dl[2 * i + 1] = __floats2half2_rn(v.z - f1.x, v.w - f1.y);
    }
}

__global__ __launch_bounds__(256) void k_conv_Bp(
    const float* __restrict__ w1v, const float* __restrict__ v1,
    const float* __restrict__ w3v, const float* __restrict__ v3)
{
    int j = blockIdx.x, e = blockIdx.y;
    const float* src = nullptr;
    if      (j < Rr)            src = w1v + ((size_t)e * Rr + j) * Hd;
    else if (j < R2)            src = v1  + ((size_t)e * Rr + j - Rr) * Hd;
    else if (j >= 320 && j < 320 + Rr) src = w3v + ((size_t)e * Rr + j - 320) * Hd;
    else if (j >= 320 + Rr && j < 320 + R2) src = v3 + ((size_t)e * Rr + j - 320 - Rr) * Hd;
    __half2* dst = (__half2*)(g_Bp + ((size_t)e * 640 + j) * Hd);
    for (int i = threadIdx.x; i < Hd / 2; i += 256) {
        float2 v = src ? ((const float2*)src)[i] : make_float2(0.f, 0.f);
        dst[i] = __floats2half2_rn(v.x, v.y);
    }
}

template <int SEL>  // 0: Bg(w1u,u1,I)  1: Bu(w3u,u3,I)  2: Bo(w2u,u2,H)
__global__ __launch_bounds__(256) void k_pack320(
    const float* __restrict__ W, const float* __restrict__ U)
{
    constexpr int ROWS = (SEL == 2) ? Hd : Id;
    __half* D = (SEL == 0) ? g_Bg : (SEL == 1) ? g_Bu : g_Bo;
    int e = blockIdx.y;
    int r = blockIdx.x * 8 + (threadIdx.x >> 5);
    int lane = threadIdx.x & 31;
    const float* w = W + ((size_t)e * ROWS + r) * Rr;
    const float* u = U + ((size_t)e * ROWS + r) * Rr;
    __half* d = D + ((size_t)e * ROWS + r) * 320;
    for (int k = lane; k < 320; k += 32) {
        float v = (k < Rr) ? w[k] : ((k < R2) ? u[k - Rr] : 0.f);
        d[k] = __float2half_rn(v);
    }
}

__global__ __launch_bounds__(256) void k_conv_Bq(
    const float* __restrict__ w2v, const float* __restrict__ v2)
{
    int j = blockIdx.x, e = blockIdx.y;
    const float* src = nullptr;
    if      (j < Rr) src = w2v + ((size_t)e * Rr + j) * Id;
    else if (j < R2) src = v2  + ((size_t)e * Rr + j - Rr) * Id;
    __half2* dst = (__half2*)(g_Bq + ((size_t)e * 384 + j) * Id);
    for (int i = threadIdx.x; i < Id / 2; i += 256) {
        float2 v = src ? ((const float2*)src)[i] : make_float2(0.f, 0.f);
        dst[i] = __floats2half2_rn(v.x, v.y);
    }
}

__global__ __launch_bounds__(256) void k_qsum() {
    size_t i = (size_t)blockIdx.x * 256 + threadIdx.x;   // grid covers RT*320
    constexpr size_t S = (size_t)RT * 320;
    float s = g_Qf[i] + g_Qf[i + S] + g_Qf[i + 2 * S] + g_Qf[i + 3 * S];
    __half h = __float2half_rn(s);
    g_Qh[i] = h;
    g_Ql[i] = __float2half_rn(s - __half2float(h));
}

// ---------------- router / routing ----------------
__device__ __forceinline__ float warpsum(float v) {
#pragma unroll
    for (int o = 16; o; o >>= 1) v += __shfl_down_sync(0xffffffffu, v, o);
    return v;
}

__global__ __launch_bounds__(256) void router_kernel(
    const float* __restrict__ x, const float* __restrict__ gw, float* __restrict__ logits)
{
    int t = blockIdx.x;
    const float4* xr = (const float4*)(x + (size_t)t * Hd);
    float acc[Ee];
#pragma unroll
    for (int e = 0; e < Ee; e++) acc[e] = 0.f;
    for (int i = threadIdx.x; i < Hd / 4; i += 256) {
        float4 xv = xr[i];
#pragma unroll
        for (int e = 0; e < Ee; e++) {
            float4 wv = ((const float4*)(gw + (size_t)e * Hd))[i];
            acc[e] = fmaf(xv.x, wv.x, fmaf(xv.y, wv.y, fmaf(xv.z, wv.z, fmaf(xv.w, wv.w, acc[e]))));
        }
    }
    __shared__ float red[8][Ee];
    int lane = threadIdx.x & 31, w = threadIdx.x >> 5;
#pragma unroll
    for (int e = 0; e < Ee; e++) {
        float s = warpsum(acc[e]);
        if (lane == 0) red[w][e] = s;
    }
    __syncthreads();
    if (threadIdx.x < Ee) {
        float s = 0.f;
#pragma unroll
        for (int w2 = 0; w2 < 8; w2++) s += red[w2][threadIdx.x];
        logits[(size_t)t * Ee + threadIdx.x] = s;
    }
}

__global__ void prep_kernel() { if (threadIdx.x < Ee) g_cnt[threadIdx.x] = 0; }

__global__ void route_kernel(const float* __restrict__ logits)
{
    int t = blockIdx.x * blockDim.x + threadIdx.x;
    if (t >= Tt) return;
    float l[Ee];
#pragma unroll
    for (int e = 0; e < Ee; e++) l[e] = logits[(size_t)t * Ee + e];
    int i1 = 0; float m1 = l[0];
#pragma unroll
    for (int e = 1; e < Ee; e++) if (l[e] > m1) { m1 = l[e]; i1 = e; }
    int i2 = -1; float m2 = -1e30f;
#pragma unroll
    for (int e = 0; e < Ee; e++) if (e != i1 && l[e] > m2) { m2 = l[e]; i2 = e; }
    float w1 = 1.f / (1.f + expf(m2 - m1));
    float w2 = 1.f - w1;
    int p = atomicAdd(&g_cnt[i1], 1); g_tok[i1][p] = t; g_wt[i1][p] = w1;
    p     = atomicAdd(&g_cnt[i2], 1); g_tok[i2][p] = t; g_wt[i2][p] = w2;
}

__global__ void offsets_kernel()
{
    if (threadIdx.x == 0) {
        int s = 0;
        for (int e = 0; e < Ee; e++) { g_off[e] = s; s += g_cnt[e]; }
    }
}

// ---------------- fp16 HMMA GEMM ----------------
// KIND 0 (A split-2): P = gather(x) @ Bp^T        K=4096 NC=64  N=640(5)
// KIND 1 (A single) : h = silu(P@Bg^T)*(P@Bu^T)   K=320 NC=5x2  N=14336(112)
// KIND 2 (A single) : Qf[slice] = h @ Bq^T        K=14336, 4 slices x NC=56
// KIND 3 (A split-2): out += wt * (Q @ Bo^T)      K=320 NC=5    N=4096(32)
template <int KIND>
__global__ __launch_bounds__(256, 1) void moe_mma(float* __restrict__ outp)
{
    constexpr bool ALO  = (KIND == 0 || KIND == 3);
    constexpr int ATILES = ALO ? 2 : 1;
    constexpr int STAGE_B = (ATILES + 1) * TILE_B;
    constexpr int NCc   = (KIND == 0) ? 64 : (KIND == 2) ? QNC : 5;
    constexpr int NPASS = (KIND == 1) ? 2 : 1;
    constexpr int Kb    = (KIND == 0) ? Hd : (KIND == 2) ? Id : 320;
    constexpr int Brows = (KIND == 0) ? 640 : (KIND == 1) ? Id : (KIND == 2) ? 384 : Hd;

    int e     = blockIdx.z;
    int n_e   = g_cnt[e];
    int mbase = blockIdx.x * 128;
    if (mbase >= n_e) return;
    int ntile  = (KIND == 2) ? (blockIdx.y % 3) : blockIdx.y;
    int kslice = (KIND == 2) ? (blockIdx.y / 3) : 0;
    int cbase  = kslice * QNC;
    int nbase  = ntile * 128;
    int off    = g_off[e];

    extern __shared__ char smem[];
    uint32_t smem_u32 = smem_to_u32(smem);
    float* sg = (float*)(smem + STAGES * STAGE_B);   // KIND1 silu stash

    int tid = threadIdx.x, lane = tid & 31, wid = tid >> 5;
    int wm = wid & 1, wn = wid >> 1;
    int row = tid >> 1, half = tid & 1;
    int ml = mbase + row;
    unsigned szA = (ml < n_e) ? 16u : 0u;

    // A row bases
    const __half *Ah_row = nullptr, *Al_row = nullptr;
    if (KIND == 0) {
        int t = (ml < n_e) ? g_tok[e][ml] : 0;
        Ah_row = g_xh + (size_t)t * Hd;
        Al_row = g_xl + (size_t)t * Hd;
    } else {
        size_t r = (size_t)off + ((ml < n_e) ? ml : 0);
        if (KIND == 1)      { Ah_row = g_Ph + r * 640; }
        else if (KIND == 2) { Ah_row = g_hh + r * Id; }
        else                { Ah_row = g_Qh + r * 320; Al_row = g_Ql + r * 320; }
    }

    float acc[4][4][4];
#pragma unroll
    for (int i = 0; i < 4; i++)
#pragma unroll
        for (int j = 0; j < 4; j++)
#pragma unroll
            for (int q = 0; q < 4; q++) acc[i][j][q] = 0.f;

    for (int p = 0; p < NPASS; p++) {
        int acoff = (KIND == 1) ? p * 320 : 0;
        const __half* Bm = (KIND == 0) ? g_Bp : (KIND == 1) ? (p ? g_Bu : g_Bg)
                         : (KIND == 2) ? g_Bq : g_Bo;
        const __half* Brow = Bm + ((size_t)e * Brows + nbase + row) * Kb;

        auto issue_load = [&](int st, int c) {
            uint32_t sb = smem_u32 + st * STAGE_B;
            int col = (cbase + c) * 64 + half * 32;
#pragma unroll
            for (int i = 0; i < 4; i++) {
                uint32_t so = tile_off(row, half * 4 + i);
                CP16(sb + so, Ah_row + acoff + col + i * 8, szA);
                if (ALO) CP16(sb + TILE_B + so, Al_row + acoff + col + i * 8, szA);
                CP16(sb + ATILES * TILE_B + so, Brow + col + i * 8, 16u);
            }
        };

        auto compute = [&](int st) {
            uint32_t base = smem_u32 + st * STAGE_B;
#pragma unroll
            for (int ks = 0; ks < 4; ks++) {
                uint32_t Ahf[4][4], Alf[4][4], Bf[4][2];
#pragma unroll
                for (int mf = 0; mf < 4; mf++) {
                    int ar = wm * 64 + mf * 16 + (lane & 15);
                    uint32_t o = tile_off(ar, ks * 2 + (lane >> 4));
                    LDSM4(Ahf[mf], base + o);
                    if (ALO) LDSM4(Alf[mf], base + TILE_B + o);
                }
#pragma unroll
                for (int g = 0; g < 2; g++) {
                    int br = wn * 32 + g * 16 + ((lane >> 4) << 3) + (lane & 7);
                    uint32_t o = tile_off(br, ks * 2 + ((lane >> 3) & 1));
                    uint32_t r[4];
                    LDSM4(r, base + ATILES * TILE_B + o);
                    Bf[2 * g][0] = r[0]; Bf[2 * g][1] = r[1];
                    Bf[2 * g + 1][0] = r[2]; Bf[2 * g + 1][1] = r[3];
                }
#pragma unroll
                for (int mf = 0; mf < 4; mf++)
#pragma unroll
                    for (int nf = 0; nf < 4; nf++) MMA16816(acc[mf][nf], Ahf[mf], Bf[nf]);
                if (ALO) {
#pragma unroll
                    for (int mf = 0; mf < 4; mf++)
#pragma unroll
                        for (int nf = 0; nf < 4; nf++) MMA16816(acc[mf][nf], Alf[mf], Bf[nf]);
                }
            }
        };

        // prologue: stages 0..1
        issue_load(0, 0); CP_COMMIT();
        if (NCc > 1) issue_load(1, 1);
        CP_COMMIT();
        CP_WAIT(1);
        __syncthreads();

        for (int c = 0; c < NCc; c++) {
            if (c + 2 < NCc) issue_load((c + 2) % STAGES, c + 2);
            CP_COMMIT();
            compute(c % STAGES);
            CP_WAIT(1);
            __syncthreads();
        }

        if (KIND == 1 && p == 0) {
#pragma unroll
            for (int mf = 0; mf < 4; mf++)
#pragma unroll
                for (int nf = 0; nf < 4; nf++)
#pragma unroll
                    for (int q = 0; q < 4; q++) {
                        float g = acc[mf][nf][q];
                        sg[((mf * 4 + nf) * 4 + q) * 256 + tid] = g / (1.f + __expf(-g));
                        acc[mf][nf][q] = 0.f;
                    }
            __syncthreads();
        }
    }

    // ---------------- epilogue ----------------
    float* qf = (KIND == 2) ? (g_Qf + (size_t)kslice * RT * 320) : nullptr;
#pragma unroll
    for (int mf = 0; mf < 4; mf++)
#pragma unroll
        for (int nf = 0; nf < 4; nf++)
#pragma unroll
            for (int qp = 0; qp < 2; qp++) {
                int r = wm * 64 + mf * 16 + (lane >> 2) + qp * 8;
                int m = mbase + r;
                if (m >= n_e) continue;
                int col = nbase + wn * 32 + nf * 8 + (lane & 3) * 2;
                float v0 = acc[mf][nf][qp * 2 + 0];
                float v1 = acc[mf][nf][qp * 2 + 1];
                if (KIND == 0) {
                    size_t b = (size_t)(off + m) * 640 + col;
                    *(__half2*)(g_Ph + b) = __floats2half2_rn(v0, v1);
                } else if (KIND == 1) {
                    v0 *= sg[((mf * 4 + nf) * 4 + qp * 2 + 0) * 256 + tid];
                    v1 *= sg[((mf * 4 + nf) * 4 + qp * 2 + 1) * 256 + tid];
                    size_t b = (size_t)(off + m) * Id + col;
                    *(__half2*)(g_hh + b) = __floats2half2_rn(v0, v1);
                } else if (KIND == 2) {
                    if (col < 320) {
                        size_t b = (size_t)(off + m) * 320 + col;
                        qf[b] = v0; qf[b + 1] = v1;
                    }
                } else {
                    float wt  = g_wt[e][m];
                    int   tok = g_tok[e][m];
                    float* dst = outp + (size_t)tok * Hd + col;
                    atomicAdd(dst, wt * v0);
                    atomicAdd(dst + 1, wt * v1);
                }
            }
}

// ---------------- launch ----------------
extern "C" void kernel_launch(void* const* d_in, const int* in_sizes, int n_in,
                              void* d_out, int out_size)
{
    const float* x    = (const float*)d_in[0];
    const float* gw   = (const float*)d_in[1];
    const float* w1u  = (const float*)d_in[2];
    const float* w1v  = (const float*)d_in[3];
    const float* w2u  = (const float*)d_in[4];
    const float* w2v  = (const float*)d_in[5];
    const float* w3u  = (const float*)d_in[6];
    const float* w3v  = (const float*)d_in[7];
    const float* u1   = (const float*)d_in[8];
    const float* v1   = (const float*)d_in[9];
    const float* u2   = (const float*)d_in[10];
    const float* v2   = (const float*)d_in[11];
    const float* u3   = (const float*)d_in[12];
    const float* v3   = (const float*)d_in[13];

    float* outp   = (float*)d_out;
    float* logits = outp + (size_t)Tt * Hd;

    int smem_s3 = STAGES * 3 * TILE_B;            // 144KB (split-2 A kinds)
    int smem_s2 = STAGES * 2 * TILE_B;            // 96KB  (single A kinds)
    int smem_gu = smem_s2 + 65536;                // +64KB stash
    cudaFuncSetAttribute(moe_mma<0>, cudaFuncAttributeMaxDynamicSharedMemorySize, smem_s3);
    cudaFuncSetAttribute(moe_mma<1>, cudaFuncAttributeMaxDynamicSharedMemorySize, smem_gu);
    cudaFuncSetAttribute(moe_mma<2>, cudaFuncAttributeMaxDynamicSharedMemorySize, smem_s2);
    cudaFuncSetAttribute(moe_mma<3>, cudaFuncAttributeMaxDynamicSharedMemorySize, smem_s3);

    cudaMemsetAsync(outp, 0, (size_t)Tt * Hd * sizeof(float));

    // pack weights / split activations (independent of routing)
    k_split_x<<<Tt, 256>>>(x);
    k_conv_Bp<<<dim3(640, Ee), 256>>>(w1v, v1, w3v, v3);
    k_pack320<0><<<dim3(Id / 8, Ee), 256>>>(w1u, u1);
    k_pack320<1><<<dim3(Id / 8, Ee), 256>>>(w3u, u3);
    k_pack320<2><<<dim3(Hd / 8, Ee), 256>>>(w2u, u2);
    k_conv_Bq<<<dim3(384, Ee), 256>>>(w2v, v2);

    prep_kernel<<<1, 32>>>();
    router_kernel<<<Tt, 256>>>(x, gw, logits);
    route_kernel<<<Tt / 256, 256>>>(logits);
    offsets_kernel<<<1, 32>>>();

    moe_mma<0><<<dim3(32, 5, Ee),   256, smem_s3>>>(nullptr);   // P
    moe_mma<1><<<dim3(32, 112, Ee), 256, smem_gu>>>(nullptr);   // gate/up -> h
    moe_mma<2><<<dim3(32, 12, Ee),  256, smem_s2>>>(nullptr);   // Q (4 K-slices)
    k_qsum<<<(RT * 320) / 256, 256>>>();
    moe_mma<3><<<dim3(32, 32, Ee),  256, smem_s3>>>(outp);      // scatter
}

// round 8
// speedup vs baseline: 5.8624x; 1.1774x over previous
#include <cuda_runtime.h>
#include <cuda_fp16.h>
#include <cstdint>
#include <math.h>

// ---------------- problem constants ----------------
#define Hd   4096
#define Id   14336
#define Rr   159
#define R2   318
#define Ee   8
#define Tt   4096
#define RT   8192          // total routed rows (Tt * topk)

#define STAGES  3
#define TILE_B  16384      // one 128x64 fp16 tile
#define QSPLIT  4
#define QNC     56         // 14336 / 64 / 4

// ---------------- scratch (device globals) ----------------
__device__ int   g_cnt[Ee];
__device__ int   g_off[Ee];
__device__ int   g_tok[Ee][Tt];
__device__ float g_wt[Ee][Tt];

__device__ __align__(16) __half g_xh[(size_t)Tt * Hd];
__device__ __align__(16) __half g_Bp[(size_t)Ee * 640 * Hd];      // rows: 0-317 gate(w1v,v1), 320-637 up(w3v,v3)
__device__ __align__(16) __half g_Bg[(size_t)Ee * Id * 320];      // [I,320] = w1u|u1|pad
__device__ __align__(16) __half g_Bu[(size_t)Ee * Id * 320];      // w3u|u3|pad
__device__ __align__(16) __half g_Bq[(size_t)Ee * 384 * Id];      // rows: w2v|v2|pad
__device__ __align__(16) __half g_Bo[(size_t)Ee * Hd * 320];      // w2u|u2|pad
__device__ __align__(16) __half g_Ph[(size_t)RT * 640];           // hi only (A of gate/up)
__device__ __align__(16) __half g_hh[(size_t)RT * Id];            // hi only (A of Q)
__device__ float g_Qf[(size_t)QSPLIT * RT * 320];
__device__ __align__(16) __half g_Qh[(size_t)RT * 320];
__device__ __align__(16) __half g_Ql[(size_t)RT * 320];

// ---------------- PTX helpers ----------------
__device__ __forceinline__ uint32_t smem_to_u32(const void* p) {
    uint32_t a;
    asm("{ .reg .u64 t; cvta.to.shared.u64 t, %1; cvt.u32.u64 %0, t; }" : "=r"(a) : "l"(p));
    return a;
}
#define LDSM4(r, a)                                                               \
    asm volatile("ldmatrix.sync.aligned.m8n8.x4.shared.b16 {%0,%1,%2,%3}, [%4];"  \
        : "=r"((r)[0]), "=r"((r)[1]), "=r"((r)[2]), "=r"((r)[3]) : "r"(a))
#define MMA16816(d, a, b)                                                         \
    asm volatile("mma.sync.aligned.m16n8k16.row.col.f32.f16.f16.f32 "             \
        "{%0,%1,%2,%3},{%4,%5,%6,%7},{%8,%9},{%0,%1,%2,%3};"                      \
        : "+f"((d)[0]), "+f"((d)[1]), "+f"((d)[2]), "+f"((d)[3])                  \
        : "r"((a)[0]), "r"((a)[1]), "r"((a)[2]), "r"((a)[3]),                     \
          "r"((b)[0]), "r"((b)[1]))
#define CP16(dst, src, sz)                                                        \
    asm volatile("cp.async.cg.shared.global [%0], [%1], 16, %2;"                  \
        :: "r"(dst), "l"(src), "r"(sz))
#define CP_COMMIT() asm volatile("cp.async.commit_group;" ::: "memory")
#define CP_WAIT(n)  asm volatile("cp.async.wait_group %0;" :: "n"(n) : "memory")

__device__ __forceinline__ uint32_t tile_off(int row, int chunk) {
    return (uint32_t)(row * 128 + ((chunk ^ (row & 7)) << 4));
}

// ---------------- conversion / packing kernels ----------------
__global__ __launch_bounds__(256) void k_split_x(const float* __restrict__ x) {
    int t = blockIdx.x;
    const float4* src = (const float4*)(x + (size_t)t * Hd);
    __half2* dh = (__half2*)(g_xh + (size_t)t * Hd);
    for (int i = threadIdx.x; i < Hd / 4; i += 256) {
        float4 v = src[i];
        dh[2 * i]     = __floats2half2_rn(v.x, v.y);
        dh[2 * i + 1] = __floats2half2_rn(v.z, v.w);
    }
}

__global__ __launch_bounds__(256) void k_conv_Bp(
    const float* __restrict__ w1v, const float* __restrict__ v1,
    const float* __restrict__ w3v, const float* __restrict__ v3)
{
    int j = blockIdx.x, e = blockIdx.y;
    const float* src = nullptr;
    if      (j < Rr)            src = w1v + ((size_t)e * Rr + j) * Hd;
    else if (j < R2)            src = v1  + ((size_t)e * Rr + j - Rr) * Hd;
    else if (j >= 320 && j < 320 + Rr) src = w3v + ((size_t)e * Rr + j - 320) * Hd;
    else if (j >= 320 + Rr && j < 320 + R2) src = v3 + ((size_t)e * Rr + j - 320 - Rr) * Hd;
    __half2* dst = (__half2*)(g_Bp + ((size_t)e * 640 + j) * Hd);
    for (int i = threadIdx.x; i < Hd / 2; i += 256) {
        float2 v = src ? ((const float2*)src)[i] : make_float2(0.f, 0.f);
        dst[i] = __floats2half2_rn(v.x, v.y);
    }
}

template <int SEL>  // 0: Bg(w1u,u1,I)  1: Bu(w3u,u3,I)  2: Bo(w2u,u2,H)
__global__ __launch_bounds__(320) void k_pack320(
    const float* __restrict__ W, const float* __restrict__ U)
{
    constexpr int ROWS = (SEL == 2) ? Hd : Id;
    __half* D = (SEL == 0) ? g_Bg : (SEL == 1) ? g_Bu : g_Bo;
    int e = blockIdx.y;
    int r = blockIdx.x * 4 + (threadIdx.x / 80);
    int c4 = (threadIdx.x % 80) * 4;
    const float* w = W + ((size_t)e * ROWS + r) * Rr;
    const float* u = U + ((size_t)e * ROWS + r) * Rr;
    float v[4];
#pragma unroll
    for (int j = 0; j < 4; j++) {
        int k = c4 + j;
        v[j] = (k < Rr) ? w[k] : ((k < R2) ? u[k - Rr] : 0.f);
    }
    __half2 h0 = __floats2half2_rn(v[0], v[1]);
    __half2 h1 = __floats2half2_rn(v[2], v[3]);
    uint2 pk = make_uint2(*(uint32_t*)&h0, *(uint32_t*)&h1);
    *(uint2*)(D + ((size_t)e * ROWS + r) * 320 + c4) = pk;
}

__global__ __launch_bounds__(256) void k_conv_Bq(
    const float* __restrict__ w2v, const float* __restrict__ v2)
{
    int j = blockIdx.x, e = blockIdx.y;
    const float* src = nullptr;
    if      (j < Rr) src = w2v + ((size_t)e * Rr + j) * Id;
    else if (j < R2) src = v2  + ((size_t)e * Rr + j - Rr) * Id;
    __half2* dst = (__half2*)(g_Bq + ((size_t)e * 384 + j) * Id);
    for (int i = threadIdx.x; i < Id / 2; i += 256) {
        float2 v = src ? ((const float2*)src)[i] : make_float2(0.f, 0.f);
        dst[i] = __floats2half2_rn(v.x, v.y);
    }
}

__global__ __launch_bounds__(256) void k_qsum() {
    size_t i = (size_t)blockIdx.x * 256 + threadIdx.x;   // grid covers RT*320
    constexpr size_t S = (size_t)RT * 320;
    float s = g_Qf[i] + g_Qf[i + S] + g_Qf[i + 2 * S] + g_Qf[i + 3 * S];
    __half h = __float2half_rn(s);
    g_Qh[i] = h;
    g_Ql[i] = __float2half_rn(s - __half2float(h));
}

// ---------------- router / routing ----------------
__device__ __forceinline__ float warpsum(float v) {
#pragma unroll
    for (int o = 16; o; o >>= 1) v += __shfl_down_sync(0xffffffffu, v, o);
    return v;
}

__global__ __launch_bounds__(256) void router_kernel(
    const float* __restrict__ x, const float* __restrict__ gw, float* __restrict__ logits)
{
    int t = blockIdx.x;
    const float4* xr = (const float4*)(x + (size_t)t * Hd);
    float acc[Ee];
#pragma unroll
    for (int e = 0; e < Ee; e++) acc[e] = 0.f;
    for (int i = threadIdx.x; i < Hd / 4; i += 256) {
        float4 xv = xr[i];
#pragma unroll
        for (int e = 0; e < Ee; e++) {
            float4 wv = ((const float4*)(gw + (size_t)e * Hd))[i];
            acc[e] = fmaf(xv.x, wv.x, fmaf(xv.y, wv.y, fmaf(xv.z, wv.z, fmaf(xv.w, wv.w, acc[e]))));
        }
    }
    __shared__ float red[8][Ee];
    int lane = threadIdx.x & 31, w = threadIdx.x >> 5;
#pragma unroll
    for (int e = 0; e < Ee; e++) {
        float s = warpsum(acc[e]);
        if (lane == 0) red[w][e] = s;
    }
    __syncthreads();
    if (threadIdx.x < Ee) {
        float s = 0.f;
#pragma unroll
        for (int w2 = 0; w2 < 8; w2++) s += red[w2][threadIdx.x];
        logits[(size_t)t * Ee + threadIdx.x] = s;
    }
}

__global__ void prep_kernel() { if (threadIdx.x < Ee) g_cnt[threadIdx.x] = 0; }

__global__ void route_kernel(const float* __restrict__ logits)
{
    int t = blockIdx.x * blockDim.x + threadIdx.x;
    if (t >= Tt) return;
    float l[Ee];
#pragma unroll
    for (int e = 0; e < Ee; e++) l[e] = logits[(size_t)t * Ee + e];
    int i1 = 0; float m1 = l[0];
#pragma unroll
    for (int e = 1; e < Ee; e++) if (l[e] > m1) { m1 = l[e]; i1 = e; }
    int i2 = -1; float m2 = -1e30f;
#pragma unroll
    for (int e = 0; e < Ee; e++) if (e != i1 && l[e] > m2) { m2 = l[e]; i2 = e; }
    float w1 = 1.f / (1.f + expf(m2 - m1));
    float w2 = 1.f - w1;
    int p = atomicAdd(&g_cnt[i1], 1); g_tok[i1][p] = t; g_wt[i1][p] = w1;
    p     = atomicAdd(&g_cnt[i2], 1); g_tok[i2][p] = t; g_wt[i2][p] = w2;
}

__global__ void offsets_kernel()
{
    if (threadIdx.x == 0) {
        int s = 0;
        for (int e = 0; e < Ee; e++) { g_off[e] = s; s += g_cnt[e]; }
    }
}

// ---------------- fp16 HMMA GEMM (128-M tile family) ----------------
// KIND 0 (A single) : P = gather(xh) @ Bp^T       K=4096 NC=64  N=640(5)
// KIND 1 (A single) : h = silu(P@Bg^T)*(P@Bu^T)   K=320 NC=5x2  N=14336(112)
// KIND 3 (A split-2): out += wt * (Q @ Bo^T)      K=320 NC=5    N=4096(32)
template <int KIND>
__global__ __launch_bounds__(256, 1) void moe_mma(float* __restrict__ outp)
{
    constexpr bool ALO  = (KIND == 3);
    constexpr int ATILES = ALO ? 2 : 1;
    constexpr int STAGE_B = (ATILES + 1) * TILE_B;
    constexpr int NCc   = (KIND == 0) ? 64 : 5;
    constexpr int NPASS = (KIND == 1) ? 2 : 1;
    constexpr int Kb    = (KIND == 0) ? Hd : 320;
    constexpr int Brows = (KIND == 0) ? 640 : (KIND == 1) ? Id : Hd;

    int e     = blockIdx.z;
    int n_e   = g_cnt[e];
    int mbase = blockIdx.x * 128;
    if (mbase >= n_e) return;
    int nbase = blockIdx.y * 128;
    int off   = g_off[e];

    extern __shared__ char smem[];
    uint32_t smem_u32 = smem_to_u32(smem);
    float* sg = (float*)(smem + STAGES * STAGE_B);   // KIND1 silu stash

    int tid = threadIdx.x, lane = tid & 31, wid = tid >> 5;
    int wm = wid & 1, wn = wid >> 1;
    int row = tid >> 1, half = tid & 1;
    int ml = mbase + row;
    unsigned szA = (ml < n_e) ? 16u : 0u;

    // A row bases
    const __half *Ah_row = nullptr, *Al_row = nullptr;
    if (KIND == 0) {
        int t = (ml < n_e) ? g_tok[e][ml] : 0;
        Ah_row = g_xh + (size_t)t * Hd;
    } else {
        size_t r = (size_t)off + ((ml < n_e) ? ml : 0);
        if (KIND == 1) { Ah_row = g_Ph + r * 640; }
        else           { Ah_row = g_Qh + r * 320; Al_row = g_Ql + r * 320; }
    }

    float acc[4][4][4];
#pragma unroll
    for (int i = 0; i < 4; i++)
#pragma unroll
        for (int j = 0; j < 4; j++)
#pragma unroll
            for (int q = 0; q < 4; q++) acc[i][j][q] = 0.f;

    for (int p = 0; p < NPASS; p++) {
        int acoff = (KIND == 1) ? p * 320 : 0;
        const __half* Bm = (KIND == 0) ? g_Bp : (KIND == 1) ? (p ? g_Bu : g_Bg) : g_Bo;
        const __half* Brow = Bm + ((size_t)e * Brows + nbase + row) * Kb;

        auto issue_load = [&](int st, int c) {
            uint32_t sb = smem_u32 + st * STAGE_B;
            int col = c * 64 + half * 32;
#pragma unroll
            for (int i = 0; i < 4; i++) {
                uint32_t so = tile_off(row, half * 4 + i);
                CP16(sb + so, Ah_row + acoff + col + i * 8, szA);
                if (ALO) CP16(sb + TILE_B + so, Al_row + acoff + col + i * 8, szA);
                CP16(sb + ATILES * TILE_B + so, Brow + col + i * 8, 16u);
            }
        };

        auto compute = [&](int st) {
            uint32_t base = smem_u32 + st * STAGE_B;
#pragma unroll
            for (int ks = 0; ks < 4; ks++) {
                uint32_t Ahf[4][4], Alf[4][4], Bf[4][2];
#pragma unroll
                for (int mf = 0; mf < 4; mf++) {
                    int ar = wm * 64 + mf * 16 + (lane & 15);
                    uint32_t o = tile_off(ar, ks * 2 + (lane >> 4));
                    LDSM4(Ahf[mf], base + o);
                    if (ALO) LDSM4(Alf[mf], base + TILE_B + o);
                }
#pragma unroll
                for (int g = 0; g < 2; g++) {
                    int br = wn * 32 + g * 16 + ((lane >> 4) << 3) + (lane & 7);
                    uint32_t o = tile_off(br, ks * 2 + ((lane >> 3) & 1));
                    uint32_t r[4];
                    LDSM4(r, base + ATILES * TILE_B + o);
                    Bf[2 * g][0] = r[0]; Bf[2 * g][1] = r[1];
                    Bf[2 * g + 1][0] = r[2]; Bf[2 * g + 1][1] = r[3];
                }
#pragma unroll
                for (int mf = 0; mf < 4; mf++)
#pragma unroll
                    for (int nf = 0; nf < 4; nf++) MMA16816(acc[mf][nf], Ahf[mf], Bf[nf]);
                if (ALO) {
#pragma unroll
                    for (int mf = 0; mf < 4; mf++)
#pragma unroll
                        for (int nf = 0; nf < 4; nf++) MMA16816(acc[mf][nf], Alf[mf], Bf[nf]);
                }
            }
        };

        issue_load(0, 0); CP_COMMIT();
        if (NCc > 1) issue_load(1, 1);
        CP_COMMIT();
        CP_WAIT(1);
        __syncthreads();

        for (int c = 0; c < NCc; c++) {
            if (c + 2 < NCc) issue_load((c + 2) % STAGES, c + 2);
            CP_COMMIT();
            compute(c % STAGES);
            CP_WAIT(1);
            __syncthreads();
        }

        if (KIND == 1 && p == 0) {
#pragma unroll
            for (int mf = 0; mf < 4; mf++)
#pragma unroll
                for (int nf = 0; nf < 4; nf++)
#pragma unroll
                    for (int q = 0; q < 4; q++) {
                        float g = acc[mf][nf][q];
                        sg[((mf * 4 + nf) * 4 + q) * 256 + tid] = g / (1.f + __expf(-g));
                        acc[mf][nf][q] = 0.f;
                    }
            __syncthreads();
        }
    }

    // ---------------- epilogue ----------------
#pragma unroll
    for (int mf = 0; mf < 4; mf++)
#pragma unroll
        for (int nf = 0; nf < 4; nf++)
#pragma unroll
            for (int qp = 0; qp < 2; qp++) {
                int r = wm * 64 + mf * 16 + (lane >> 2) + qp * 8;
                int m = mbase + r;
                if (m >= n_e) continue;
                int col = nbase + wn * 32 + nf * 8 + (lane & 3) * 2;
                float v0 = acc[mf][nf][qp * 2 + 0];
                float v1 = acc[mf][nf][qp * 2 + 1];
                if (KIND == 0) {
                    size_t b = (size_t)(off + m) * 640 + col;
                    *(__half2*)(g_Ph + b) = __floats2half2_rn(v0, v1);
                } else if (KIND == 1) {
                    v0 *= sg[((mf * 4 + nf) * 4 + qp * 2 + 0) * 256 + tid];
                    v1 *= sg[((mf * 4 + nf) * 4 + qp * 2 + 1) * 256 + tid];
                    size_t b = (size_t)(off + m) * Id + col;
                    *(__half2*)(g_hh + b) = __floats2half2_rn(v0, v1);
                } else {
                    float wt  = g_wt[e][m];
                    int   tok = g_tok[e][m];
                    float* dst = outp + (size_t)tok * Hd + col;
                    atomicAdd(dst, wt * v0);
                    atomicAdd(dst + 1, wt * v1);
                }
            }
}

// ---------------- Q GEMM: M=64, N=384 single pass, 4 K-slices ----------------
// Qf[slice] = h @ Bq^T.  A (h) read exactly once — no N-tile reread.
#define QA_B 8192
#define QB_B 49152
#define QST_B (QA_B + QB_B)
#define QCHUNKS 3584   // (64 + 384) rows * 8 chunks
__global__ __launch_bounds__(256, 1) void moe_mma_q()
{
    int e     = blockIdx.z;
    int n_e   = g_cnt[e];
    int mbase = blockIdx.x * 64;
    if (mbase >= n_e) return;
    int kslice = blockIdx.y;
    int cbase  = kslice * QNC;
    int off    = g_off[e];

    extern __shared__ char smem[];
    uint32_t smem_u32 = smem_to_u32(smem);

    int tid = threadIdx.x, lane = tid & 31, wn = tid >> 5;

    float acc[4][6][4];
#pragma unroll
    for (int i = 0; i < 4; i++)
#pragma unroll
        for (int j = 0; j < 6; j++)
#pragma unroll
            for (int q = 0; q < 4; q++) acc[i][j][q] = 0.f;

    const __half* Bq_e = g_Bq + (size_t)e * 384 * Id;

    auto issue_load = [&](int st, int c) {
        uint32_t sb = smem_u32 + st * QST_B;
        int col = (cbase + c) * 64;
#pragma unroll
        for (int i = 0; i < 14; i++) {
            int ci = tid + i * 256;
            if (ci >= QCHUNKS) break;
            if (ci < 512) {
                int row = ci >> 3, ch = ci & 7;
                int m = mbase + row;
                unsigned sz = (m < n_e) ? 16u : 0u;
                const __half* src = g_hh + ((size_t)off + ((m < n_e) ? m : 0)) * Id + col + ch * 8;
                CP16(sb + tile_off(row, ch), src, sz);
            } else {
                int bi = ci - 512;
                int row = bi >> 3, ch = bi & 7;
                const __half* src = Bq_e + (size_t)row * Id + col + ch * 8;
                CP16(sb + QA_B + tile_off(row, ch), src, 16u);
            }
        }
    };

    auto compute = [&](int st) {
        uint32_t base = smem_u32 + st * QST_B;
#pragma unroll
        for (int ks = 0; ks < 4; ks++) {
            uint32_t Af[4][4], Bf[6][2];
#pragma unroll
            for (int mf = 0; mf < 4; mf++) {
                int ar = mf * 16 + (lane & 15);
                LDSM4(Af[mf], base + tile_off(ar, ks * 2 + (lane >> 4)));
            }
#pragma unroll
            for (int g = 0; g < 3; g++) {
                int br = wn * 48 + g * 16 + ((lane >> 4) << 3) + (lane & 7);
                uint32_t o = tile_off(br, ks * 2 + ((lane >> 3) & 1));
                uint32_t r[4];
                LDSM4(r, base + QA_B + o);
                Bf[2 * g][0] = r[0]; Bf[2 * g][1] = r[1];
                Bf[2 * g + 1][0] = r[2]; Bf[2 * g + 1][1] = r[3];
            }
#pragma unroll
            for (int mf = 0; mf < 4; mf++)
#pragma unroll
                for (int nf = 0; nf < 6; nf++) MMA16816(acc[mf][nf], Af[mf], Bf[nf]);
        }
    };

    issue_load(0, 0); CP_COMMIT();
    issue_load(1, 1); CP_COMMIT();
    CP_WAIT(1);
    __syncthreads();

    for (int c = 0; c < QNC; c++) {
        if (c + 2 < QNC) issue_load((c + 2) % STAGES, c + 2);
        CP_COMMIT();
        compute(c % STAGES);
        CP_WAIT(1);
        __syncthreads();
    }

    float* qf = g_Qf + (size_t)kslice * RT * 320;
#pragma unroll
    for (int mf = 0; mf < 4; mf++)
#pragma unroll
        for (int nf = 0; nf < 6; nf++)
#pragma unroll
            for (int qp = 0; qp < 2; qp++) {
                int m = mbase + mf * 16 + (lane >> 2) + qp * 8;
                if (m >= n_e) continue;
                int col = wn * 48 + nf * 8 + (lane & 3) * 2;
                if (col >= 320) continue;
                size_t b = (size_t)(off + m) * 320 + col;
                qf[b]     = acc[mf][nf][qp * 2 + 0];
                qf[b + 1] = acc[mf][nf][qp * 2 + 1];
            }
}

// ---------------- launch ----------------
extern "C" void kernel_launch(void* const* d_in, const int* in_sizes, int n_in,
                              void* d_out, int out_size)
{
    const float* x    = (const float*)d_in[0];
    const float* gw   = (const float*)d_in[1];
    const float* w1u  = (const float*)d_in[2];
    const float* w1v  = (const float*)d_in[3];
    const float* w2u  = (const float*)d_in[4];
    const float* w2v  = (const float*)d_in[5];
    const float* w3u  = (const float*)d_in[6];
    const float* w3v  = (const float*)d_in[7];
    const float* u1   = (const float*)d_in[8];
    const float* v1   = (const float*)d_in[9];
    const float* u2   = (const float*)d_in[10];
    const float* v2   = (const float*)d_in[11];
    const float* u3   = (const float*)d_in[12];
    const float* v3   = (const float*)d_in[13];

    float* outp   = (float*)d_out;
    float* logits = outp + (size_t)Tt * Hd;

    int smem_s3 = STAGES * 3 * TILE_B;            // 144KB (KIND3 split-2)
    int smem_s2 = STAGES * 2 * TILE_B;            // 96KB  (KIND0)
    int smem_gu = smem_s2 + 65536;                // +64KB stash (KIND1)
    int smem_q  = STAGES * QST_B;                 // 168KB
    cudaFuncSetAttribute(moe_mma<0>, cudaFuncAttributeMaxDynamicSharedMemorySize, smem_s2);
    cudaFuncSetAttribute(moe_mma<1>, cudaFuncAttributeMaxDynamicSharedMemorySize, smem_gu);
    cudaFuncSetAttribute(moe_mma<3>, cudaFuncAttributeMaxDynamicSharedMemorySize, smem_s3);
    cudaFuncSetAttribute(moe_mma_q,  cudaFuncAttributeMaxDynamicSharedMemorySize, smem_q);

    cudaMemsetAsync(outp, 0, (size_t)Tt * Hd * sizeof(float));

    // pack weights / convert activations (independent of routing)
    k_split_x<<<Tt, 256>>>(x);
    k_conv_Bp<<<dim3(640, Ee), 256>>>(w1v, v1, w3v, v3);
    k_pack320<0><<<dim3(Id / 4, Ee), 320>>>(w1u, u1);
    k_pack320<1><<<dim3(Id / 4, Ee), 320>>>(w3u, u3);
    k_pack320<2><<<dim3(Hd / 4, Ee), 320>>>(w2u, u2);
    k_conv_Bq<<<dim3(384, Ee), 256>>>(w2v, v2);

    prep_kernel<<<1, 32>>>();
    router_kernel<<<Tt, 256>>>(x, gw, logits);
    route_kernel<<<Tt / 256, 256>>>(logits);
    offsets_kernel<<<1, 32>>>();

    moe_mma<0><<<dim3(32, 5, Ee),   256, smem_s2>>>(nullptr);   // P
    moe_mma<1><<<dim3(32, 112, Ee), 256, smem_gu>>>(nullptr);   // gate/up -> h
    moe_mma_q<<<dim3(64, QSPLIT, Ee), 256, smem_q>>>();         // Q (h read once)
    k_qsum<<<(RT * 320) / 256, 256>>>();
    moe_mma<3><<<dim3(32, 32, Ee),  256, smem_s3>>>(outp);      // scatter
}

// round 9
// speedup vs baseline: 6.0977x; 1.0401x over previous
#include <cuda_runtime.h>
#include <cuda_fp16.h>
#include <cstdint>
#include <math.h>

// ---------------- problem constants ----------------
#define Hd   4096
#define Id   14336
#define Rr   159
#define R2   318
#define Ee   8
#define Tt   4096
#define RT   8192          // total routed rows (Tt * topk)

#define STAGES  3
#define TILE_B  16384      // one 128x64 fp16 tile
#define QSPLIT  4
#define QNC     56         // 14336 / 64 / 4

// ---------------- scratch (device globals) ----------------
__device__ int   g_cnt[Ee];
__device__ int   g_off[Ee];
__device__ int   g_tok[Ee][Tt];
__device__ float g_wt[Ee][Tt];

__device__ __align__(16) __half g_xh[(size_t)Tt * Hd];
__device__ __align__(16) __half g_Bp[(size_t)Ee * 640 * Hd];      // rows: 0-317 gate(w1v,v1), 320-637 up(w3v,v3)
__device__ __align__(16) __half g_Bg[(size_t)Ee * Id * 320];      // [I,320] = w1u|u1|pad
__device__ __align__(16) __half g_Bu[(size_t)Ee * Id * 320];      // w3u|u3|pad
__device__ __align__(16) __half g_Bq[(size_t)Ee * 384 * Id];      // rows: w2v|v2|pad
__device__ __align__(16) __half g_Bo[(size_t)Ee * Hd * 320];      // w2u|u2|pad
__device__ __align__(16) __half g_Ph[(size_t)RT * 640];           // hi only (A of gate/up)
__device__ __align__(16) __half g_hh[(size_t)RT * Id];            // hi only (A of Q)
__device__ float g_Qf[(size_t)QSPLIT * RT * 320];
__device__ __align__(16) __half g_Qh[(size_t)RT * 320];

// ---------------- PTX helpers ----------------
__device__ __forceinline__ uint32_t smem_to_u32(const void* p) {
    uint32_t a;
    asm("{ .reg .u64 t; cvta.to.shared.u64 t, %1; cvt.u32.u64 %0, t; }" : "=r"(a) : "l"(p));
    return a;
}
#define LDSM4(r, a)                                                               \
    asm volatile("ldmatrix.sync.aligned.m8n8.x4.shared.b16 {%0,%1,%2,%3}, [%4];"  \
        : "=r"((r)[0]), "=r"((r)[1]), "=r"((r)[2]), "=r"((r)[3]) : "r"(a))
#define MMA16816(d, a, b)                                                         \
    asm volatile("mma.sync.aligned.m16n8k16.row.col.f32.f16.f16.f32 "             \
        "{%0,%1,%2,%3},{%4,%5,%6,%7},{%8,%9},{%0,%1,%2,%3};"                      \
        : "+f"((d)[0]), "+f"((d)[1]), "+f"((d)[2]), "+f"((d)[3])                  \
        : "r"((a)[0]), "r"((a)[1]), "r"((a)[2]), "r"((a)[3]),                     \
          "r"((b)[0]), "r"((b)[1]))
#define CP16(dst, src, sz)                                                        \
    asm volatile("cp.async.cg.shared.global [%0], [%1], 16, %2;"                  \
        :: "r"(dst), "l"(src), "r"(sz))
#define CP_COMMIT() asm volatile("cp.async.commit_group;" ::: "memory")
#define CP_WAIT(n)  asm volatile("cp.async.wait_group %0;" :: "n"(n) : "memory")

__device__ __forceinline__ uint32_t tile_off(int row, int chunk) {
    return (uint32_t)(row * 128 + ((chunk ^ (row & 7)) << 4));
}

// ---------------- conversion / packing kernels ----------------
__global__ __launch_bounds__(256) void k_split_x(const float* __restrict__ x) {
    int t = blockIdx.x;
    const float4* src = (const float4*)(x + (size_t)t * Hd);
    __half2* dh = (__half2*)(g_xh + (size_t)t * Hd);
    for (int i = threadIdx.x; i < Hd / 4; i += 256) {
        float4 v = src[i];
        dh[2 * i]     = __floats2half2_rn(v.x, v.y);
        dh[2 * i + 1] = __floats2half2_rn(v.z, v.w);
    }
}

__global__ __launch_bounds__(256) void k_conv_Bp(
    const float* __restrict__ w1v, const float* __restrict__ v1,
    const float* __restrict__ w3v, const float* __restrict__ v3)
{
    int j = blockIdx.x, e = blockIdx.y;
    const float* src = nullptr;
    if      (j < Rr)            src = w1v + ((size_t)e * Rr + j) * Hd;
    else if (j < R2)            src = v1  + ((size_t)e * Rr + j - Rr) * Hd;
    else if (j >= 320 && j < 320 + Rr) src = w3v + ((size_t)e * Rr + j - 320) * Hd;
    else if (j >= 320 + Rr && j < 320 + R2) src = v3 + ((size_t)e * Rr + j - 320 - Rr) * Hd;
    __half2* dst = (__half2*)(g_Bp + ((size_t)e * 640 + j) * Hd);
    for (int i = threadIdx.x; i < Hd / 2; i += 256) {
        float2 v = src ? ((const float2*)src)[i] : make_float2(0.f, 0.f);
        dst[i] = __floats2half2_rn(v.x, v.y);
    }
}

template <int SEL>  // 0: Bg(w1u,u1,I)  1: Bu(w3u,u3,I)  2: Bo(w2u,u2,H)
__global__ __launch_bounds__(320) void k_pack320(
    const float* __restrict__ W, const float* __restrict__ U)
{
    constexpr int ROWS = (SEL == 2) ? Hd : Id;
    __half* D = (SEL == 0) ? g_Bg : (SEL == 1) ? g_Bu : g_Bo;
    int e = blockIdx.y;
    int r = blockIdx.x * 4 + (threadIdx.x / 80);
    int c4 = (threadIdx.x % 80) * 4;
    const float* w = W + ((size_t)e * ROWS + r) * Rr;
    const float* u = U + ((size_t)e * ROWS + r) * Rr;
    float v[4];
#pragma unroll
    for (int j = 0; j < 4; j++) {
        int k = c4 + j;
        v[j] = (k < Rr) ? w[k] : ((k < R2) ? u[k - Rr] : 0.f);
    }
    __half2 h0 = __floats2half2_rn(v[0], v[1]);
    __half2 h1 = __floats2half2_rn(v[2], v[3]);
    uint2 pk = make_uint2(*(uint32_t*)&h0, *(uint32_t*)&h1);
    *(uint2*)(D + ((size_t)e * ROWS + r) * 320 + c4) = pk;
}

__global__ __launch_bounds__(256) void k_conv_Bq(
    const float* __restrict__ w2v, const float* __restrict__ v2)
{
    int j = blockIdx.x, e = blockIdx.y;
    const float* src = nullptr;
    if      (j < Rr) src = w2v + ((size_t)e * Rr + j) * Id;
    else if (j < R2) src = v2  + ((size_t)e * Rr + j - Rr) * Id;
    __half2* dst = (__half2*)(g_Bq + ((size_t)e * 384 + j) * Id);
    for (int i = threadIdx.x; i < Id / 2; i += 256) {
        float2 v = src ? ((const float2*)src)[i] : make_float2(0.f, 0.f);
        dst[i] = __floats2half2_rn(v.x, v.y);
    }
}

__global__ __launch_bounds__(256) void k_qsum() {
    size_t i = (size_t)blockIdx.x * 256 + threadIdx.x;   // grid covers RT*320
    constexpr size_t S = (size_t)RT * 320;
    float s = g_Qf[i] + g_Qf[i + S] + g_Qf[i + 2 * S] + g_Qf[i + 3 * S];
    g_Qh[i] = __float2half_rn(s);
}

// ---------------- router / routing ----------------
__device__ __forceinline__ float warpsum(float v) {
#pragma unroll
    for (int o = 16; o; o >>= 1) v += __shfl_down_sync(0xffffffffu, v, o);
    return v;
}

__global__ __launch_bounds__(256) void router_kernel(
    const float* __restrict__ x, const float* __restrict__ gw, float* __restrict__ logits)
{
    int t = blockIdx.x;
    const float4* xr = (const float4*)(x + (size_t)t * Hd);
    float acc[Ee];
#pragma unroll
    for (int e = 0; e < Ee; e++) acc[e] = 0.f;
    for (int i = threadIdx.x; i < Hd / 4; i += 256) {
        float4 xv = xr[i];
#pragma unroll
        for (int e = 0; e < Ee; e++) {
            float4 wv = ((const float4*)(gw + (size_t)e * Hd))[i];
            acc[e] = fmaf(xv.x, wv.x, fmaf(xv.y, wv.y, fmaf(xv.z, wv.z, fmaf(xv.w, wv.w, acc[e]))));
        }
    }
    __shared__ float red[8][Ee];
    int lane = threadIdx.x & 31, w = threadIdx.x >> 5;
#pragma unroll
    for (int e = 0; e < Ee; e++) {
        float s = warpsum(acc[e]);
        if (lane == 0) red[w][e] = s;
    }
    __syncthreads();
    if (threadIdx.x < Ee) {
        float s = 0.f;
#pragma unroll
        for (int w2 = 0; w2 < 8; w2++) s += red[w2][threadIdx.x];
        logits[(size_t)t * Ee + threadIdx.x] = s;
    }
}

__global__ void prep_kernel() { if (threadIdx.x < Ee) g_cnt[threadIdx.x] = 0; }

__global__ void route_kernel(const float* __restrict__ logits)
{
    int t = blockIdx.x * blockDim.x + threadIdx.x;
    if (t >= Tt) return;
    float l[Ee];
#pragma unroll
    for (int e = 0; e < Ee; e++) l[e] = logits[(size_t)t * Ee + e];
    int i1 = 0; float m1 = l[0];
#pragma unroll
    for (int e = 1; e < Ee; e++) if (l[e] > m1) { m1 = l[e]; i1 = e; }
    int i2 = -1; float m2 = -1e30f;
#pragma unroll
    for (int e = 0; e < Ee; e++) if (e != i1 && l[e] > m2) { m2 = l[e]; i2 = e; }
    float w1 = 1.f / (1.f + expf(m2 - m1));
    float w2 = 1.f - w1;
    int p = atomicAdd(&g_cnt[i1], 1); g_tok[i1][p] = t; g_wt[i1][p] = w1;
    p     = atomicAdd(&g_cnt[i2], 1); g_tok[i2][p] = t; g_wt[i2][p] = w2;
}

__global__ void offsets_kernel()
{
    if (threadIdx.x == 0) {
        int s = 0;
        for (int e = 0; e < Ee; e++) { g_off[e] = s; s += g_cnt[e]; }
    }
}

// ---------------- fp16 HMMA GEMM (128-M tile family, single-A) ----------------
// KIND 0: P = gather(xh) @ Bp^T       K=4096 NC=64  N=640(5)
// KIND 1: h = silu(P@Bg^T)*(P@Bu^T)   K=320 NC=5x2  N=14336(112)
// KIND 3: out += wt * (Q @ Bo^T)      K=320 NC=5    N=4096(32)
template <int KIND>
__global__ __launch_bounds__(256, 1) void moe_mma(float* __restrict__ outp)
{
    constexpr int STAGE_B = 2 * TILE_B;
    constexpr int NCc   = (KIND == 0) ? 64 : 5;
    constexpr int NPASS = (KIND == 1) ? 2 : 1;
    constexpr int Kb    = (KIND == 0) ? Hd : 320;
    constexpr int Brows = (KIND == 0) ? 640 : (KIND == 1) ? Id : Hd;

    int e     = blockIdx.z;
    int n_e   = g_cnt[e];
    int mbase = blockIdx.x * 128;
    if (mbase >= n_e) return;
    int nbase = blockIdx.y * 128;
    int off   = g_off[e];

    extern __shared__ char smem[];
    uint32_t smem_u32 = smem_to_u32(smem);
    float* sg = (float*)(smem + STAGES * STAGE_B);   // KIND1 silu stash

    int tid = threadIdx.x, lane = tid & 31, wid = tid >> 5;
    int wm = wid & 1, wn = wid >> 1;
    int row = tid >> 1, half = tid & 1;
    int ml = mbase + row;
    unsigned szA = (ml < n_e) ? 16u : 0u;

    // A row base
    const __half* Ah_row;
    if (KIND == 0) {
        int t = (ml < n_e) ? g_tok[e][ml] : 0;
        Ah_row = g_xh + (size_t)t * Hd;
    } else {
        size_t r = (size_t)off + ((ml < n_e) ? ml : 0);
        Ah_row = (KIND == 1) ? (g_Ph + r * 640) : (g_Qh + r * 320);
    }

    float acc[4][4][4];
#pragma unroll
    for (int i = 0; i < 4; i++)
#pragma unroll
        for (int j = 0; j < 4; j++)
#pragma unroll
            for (int q = 0; q < 4; q++) acc[i][j][q] = 0.f;

    for (int p = 0; p < NPASS; p++) {
        int acoff = (KIND == 1) ? p * 320 : 0;
        const __half* Bm = (KIND == 0) ? g_Bp : (KIND == 1) ? (p ? g_Bu : g_Bg) : g_Bo;
        const __half* Brow = Bm + ((size_t)e * Brows + nbase + row) * Kb;

        auto issue_load = [&](int st, int c) {
            uint32_t sb = smem_u32 + st * STAGE_B;
            int col = c * 64 + half * 32;
#pragma unroll
            for (int i = 0; i < 4; i++) {
                uint32_t so = tile_off(row, half * 4 + i);
                CP16(sb + so, Ah_row + acoff + col + i * 8, szA);
                CP16(sb + TILE_B + so, Brow + col + i * 8, 16u);
            }
        };

        auto compute = [&](int st) {
            uint32_t base = smem_u32 + st * STAGE_B;
#pragma unroll
            for (int ks = 0; ks < 4; ks++) {
                uint32_t Ahf[4][4], Bf[4][2];
#pragma unroll
                for (int mf = 0; mf < 4; mf++) {
                    int ar = wm * 64 + mf * 16 + (lane & 15);
                    LDSM4(Ahf[mf], base + tile_off(ar, ks * 2 + (lane >> 4)));
                }
#pragma unroll
                for (int g = 0; g < 2; g++) {
                    int br = wn * 32 + g * 16 + ((lane >> 4) << 3) + (lane & 7);
                    uint32_t o = tile_off(br, ks * 2 + ((lane >> 3) & 1));
                    uint32_t r[4];
                    LDSM4(r, base + TILE_B + o);
                    Bf[2 * g][0] = r[0]; Bf[2 * g][1] = r[1];
                    Bf[2 * g + 1][0] = r[2]; Bf[2 * g + 1][1] = r[3];
                }
#pragma unroll
                for (int mf = 0; mf < 4; mf++)
#pragma unroll
                    for (int nf = 0; nf < 4; nf++) MMA16816(acc[mf][nf], Ahf[mf], Bf[nf]);
            }
        };

        issue_load(0, 0); CP_COMMIT();
        if (NCc > 1) issue_load(1, 1);
        CP_COMMIT();
        CP_WAIT(1);
        __syncthreads();

        for (int c = 0; c < NCc; c++) {
            if (c + 2 < NCc) issue_load((c + 2) % STAGES, c + 2);
            CP_COMMIT();
            compute(c % STAGES);
            CP_WAIT(1);
            __syncthreads();
        }

        if (KIND == 1 && p == 0) {
#pragma unroll
            for (int mf = 0; mf < 4; mf++)
#pragma unroll
                for (int nf = 0; nf < 4; nf++)
#pragma unroll
                    for (int q = 0; q < 4; q++) {
                        float g = acc[mf][nf][q];
                        sg[((mf * 4 + nf) * 4 + q) * 256 + tid] = g / (1.f + __expf(-g));
                        acc[mf][nf][q] = 0.f;
                    }
            __syncthreads();
        }
    }

    // ---------------- epilogue ----------------
#pragma unroll
    for (int mf = 0; mf < 4; mf++)
#pragma unroll
        for (int nf = 0; nf < 4; nf++)
#pragma unroll
            for (int qp = 0; qp < 2; qp++) {
                int r = wm * 64 + mf * 16 + (lane >> 2) + qp * 8;
                int m = mbase + r;
                if (m >= n_e) continue;
                int col = nbase + wn * 32 + nf * 8 + (lane & 3) * 2;
                float v0 = acc[mf][nf][qp * 2 + 0];
                float v1 = acc[mf][nf][qp * 2 + 1];
                if (KIND == 0) {
                    size_t b = (size_t)(off + m) * 640 + col;
                    *(__half2*)(g_Ph + b) = __floats2half2_rn(v0, v1);
                } else if (KIND == 1) {
                    v0 *= sg[((mf * 4 + nf) * 4 + qp * 2 + 0) * 256 + tid];
                    v1 *= sg[((mf * 4 + nf) * 4 + qp * 2 + 1) * 256 + tid];
                    size_t b = (size_t)(off + m) * Id + col;
                    *(__half2*)(g_hh + b) = __floats2half2_rn(v0, v1);
                } else {
                    float wt  = g_wt[e][m];
                    int   tok = g_tok[e][m];
                    float* dst = outp + (size_t)tok * Hd + col;
                    atomicAdd(dst, wt * v0);
                    atomicAdd(dst + 1, wt * v1);
                }
            }
}

// ---------------- Q GEMM: M=64, N=384 single pass, 4 K-slices ----------------
#define QA_B 8192
#define QB_B 49152
#define QST_B (QA_B + QB_B)
#define QCHUNKS 3584   // (64 + 384) rows * 8 chunks
__global__ __launch_bounds__(256, 1) void moe_mma_q()
{
    int e     = blockIdx.z;
    int n_e   = g_cnt[e];
    int mbase = blockIdx.x * 64;
    if (mbase >= n_e) return;
    int kslice = blockIdx.y;
    int cbase  = kslice * QNC;
    int off    = g_off[e];

    extern __shared__ char smem[];
    uint32_t smem_u32 = smem_to_u32(smem);

    int tid = threadIdx.x, lane = tid & 31, wn = tid >> 5;

    float acc[4][6][4];
#pragma unroll
    for (int i = 0; i < 4; i++)
#pragma unroll
        for (int j = 0; j < 6; j++)
#pragma unroll
            for (int q = 0; q < 4; q++) acc[i][j][q] = 0.f;

    const __half* Bq_e = g_Bq + (size_t)e * 384 * Id;

    auto issue_load = [&](int st, int c) {
        uint32_t sb = smem_u32 + st * QST_B;
        int col = (cbase + c) * 64;
#pragma unroll
        for (int i = 0; i < 14; i++) {
            int ci = tid + i * 256;
            if (ci >= QCHUNKS) break;
            if (ci < 512) {
                int row = ci >> 3, ch = ci & 7;
                int m = mbase + row;
                unsigned sz = (m < n_e) ? 16u : 0u;
                const __half* src = g_hh + ((size_t)off + ((m < n_e) ? m : 0)) * Id + col + ch * 8;
                CP16(sb + tile_off(row, ch), src, sz);
            } else {
                int bi = ci - 512;
                int row = bi >> 3, ch = bi & 7;
                const __half* src = Bq_e + (size_t)row * Id + col + ch * 8;
                CP16(sb + QA_B + tile_off(row, ch), src, 16u);
            }
        }
    };

    auto compute = [&](int st) {
        uint32_t base = smem_u32 + st * QST_B;
#pragma unroll
        for (int ks = 0; ks < 4; ks++) {
            uint32_t Af[4][4], Bf[6][2];
#pragma unroll
            for (int mf = 0; mf < 4; mf++) {
                int ar = mf * 16 + (lane & 15);
                LDSM4(Af[mf], base + tile_off(ar, ks * 2 + (lane >> 4)));
            }
#pragma unroll
            for (int g = 0; g < 3; g++) {
                int br = wn * 48 + g * 16 + ((lane >> 4) << 3) + (lane & 7);
                uint32_t o = tile_off(br, ks * 2 + ((lane >> 3) & 1));
                uint32_t r[4];
                LDSM4(r, base + QA_B + o);
                Bf[2 * g][0] = r[0]; Bf[2 * g][1] = r[1];
                Bf[2 * g + 1][0] = r[2]; Bf[2 * g + 1][1] = r[3];
            }
#pragma unroll
            for (int mf = 0; mf < 4; mf++)
#pragma unroll
                for (int nf = 0; nf < 6; nf++) MMA16816(acc[mf][nf], Af[mf], Bf[nf]);
        }
    };

    issue_load(0, 0); CP_COMMIT();
    issue_load(1, 1); CP_COMMIT();
    CP_WAIT(1);
    __syncthreads();

    for (int c = 0; c < QNC; c++) {
        if (c + 2 < QNC) issue_load((c + 2) % STAGES, c + 2);
        CP_COMMIT();
        compute(c % STAGES);
        CP_WAIT(1);
        __syncthreads();
    }

    float* qf = g_Qf + (size_t)kslice * RT * 320;
#pragma unroll
    for (int mf = 0; mf < 4; mf++)
#pragma unroll
        for (int nf = 0; nf < 6; nf++)
#pragma unroll
            for (int qp = 0; qp < 2; qp++) {
                int m = mbase + mf * 16 + (lane >> 2) + qp * 8;
                if (m >= n_e) continue;
                int col = wn * 48 + nf * 8 + (lane & 3) * 2;
                if (col >= 320) continue;
                size_t b = (size_t)(off + m) * 320 + col;
                qf[b]     = acc[mf][nf][qp * 2 + 0];
                qf[b + 1] = acc[mf][nf][qp * 2 + 1];
            }
}

// ---------------- launch ----------------
extern "C" void kernel_launch(void* const* d_in, const int* in_sizes, int n_in,
                              void* d_out, int out_size)
{
    const float* x    = (const float*)d_in[0];
    const float* gw   = (const float*)d_in[1];
    const float* w1u  = (const float*)d_in[2];
    const float* w1v  = (const float*)d_in[3];
    const float* w2u  = (const float*)d_in[4];
    const float* w2v  = (const float*)d_in[5];
    const float* w3u  = (const float*)d_in[6];
    const float* w3v  = (const float*)d_in[7];
    const float* u1   = (const float*)d_in[8];
    const float* v1   = (const float*)d_in[9];
    const float* u2   = (const float*)d_in[10];
    const float* v2   = (const float*)d_in[11];
    const float* u3   = (const float*)d_in[12];
    const float* v3   = (const float*)d_in[13];

    float* outp   = (float*)d_out;
    float* logits = outp + (size_t)Tt * Hd;

    // one-time host resources (streams/events are host objects; no device alloc)
    static cudaStream_t s_pack = nullptr;
    static cudaEvent_t evStart, evBp, evBgu, evBq, evBo;
    if (!s_pack) {
        cudaStreamCreateWithFlags(&s_pack, cudaStreamNonBlocking);
        cudaEventCreateWithFlags(&evStart, cudaEventDisableTiming);
        cudaEventCreateWithFlags(&evBp,    cudaEventDisableTiming);
        cudaEventCreateWithFlags(&evBgu,   cudaEventDisableTiming);
        cudaEventCreateWithFlags(&evBq,    cudaEventDisableTiming);
        cudaEventCreateWithFlags(&evBo,    cudaEventDisableTiming);

        int smem_s2 = STAGES * 2 * TILE_B;        // 96KB
        int smem_gu = smem_s2 + 65536;            // +64KB stash
        int smem_q  = STAGES * QST_B;             // 168KB
        cudaFuncSetAttribute(moe_mma<0>, cudaFuncAttributeMaxDynamicSharedMemorySize, smem_s2);
        cudaFuncSetAttribute(moe_mma<1>, cudaFuncAttributeMaxDynamicSharedMemorySize, smem_gu);
        cudaFuncSetAttribute(moe_mma<3>, cudaFuncAttributeMaxDynamicSharedMemorySize, smem_s2);
        cudaFuncSetAttribute(moe_mma_q,  cudaFuncAttributeMaxDynamicSharedMemorySize, smem_q);
    }
    int smem_s2 = STAGES * 2 * TILE_B;
    int smem_gu = smem_s2 + 65536;
    int smem_q  = STAGES * QST_B;

    // fork: weight packing on side stream, overlapped with router/P/GU chain
    cudaEventRecord(evStart, 0);
    cudaStreamWaitEvent(s_pack, evStart, 0);

    k_conv_Bp<<<dim3(640, Ee), 256, 0, s_pack>>>(w1v, v1, w3v, v3);
    cudaEventRecord(evBp, s_pack);
    k_pack320<0><<<dim3(Id / 4, Ee), 320, 0, s_pack>>>(w1u, u1);
    k_pack320<1><<<dim3(Id / 4, Ee), 320, 0, s_pack>>>(w3u, u3);
    cudaEventRecord(evBgu, s_pack);
    k_conv_Bq<<<dim3(384, Ee), 256, 0, s_pack>>>(w2v, v2);
    cudaEventRecord(evBq, s_pack);
    k_pack320<2><<<dim3(Hd / 4, Ee), 320, 0, s_pack>>>(w2u, u2);
    cudaEventRecord(evBo, s_pack);

    // main stream: routing chain
    cudaMemsetAsync(outp, 0, (size_t)Tt * Hd * sizeof(float));
    k_split_x<<<Tt, 256>>>(x);
    prep_kernel<<<1, 32>>>();
    router_kernel<<<Tt, 256>>>(x, gw, logits);
    route_kernel<<<Tt / 256, 256>>>(logits);
    offsets_kernel<<<1, 32>>>();

    cudaStreamWaitEvent(0, evBp, 0);
    moe_mma<0><<<dim3(32, 5, Ee),   256, smem_s2>>>(nullptr);   // P
    cudaStreamWaitEvent(0, evBgu, 0);
    moe_mma<1><<<dim3(32, 112, Ee), 256, smem_gu>>>(nullptr);   // gate/up -> h
    cudaStreamWaitEvent(0, evBq, 0);
    moe_mma_q<<<dim3(64, QSPLIT, Ee), 256, smem_q>>>();         // Q (h read once)
    k_qsum<<<(RT * 320) / 256, 256>>>();
    cudaStreamWaitEvent(0, evBo, 0);
    moe_mma<3><<<dim3(32, 32, Ee),  256, smem_s2>>>(outp);      // scatter
}

// round 10
// speedup vs baseline: 7.5507x; 1.2383x over previous
#include <cuda_runtime.h>
#include <cuda_fp16.h>
#include <cstdint>
#include <math.h>

// ---------------- problem constants ----------------
#define Hd   4096
#define Id   14336
#define Rr   159
#define R2   318
#define Ee   8
#define Tt   4096
#define RT   8192          // total routed rows (Tt * topk)

#define STAGES  3
#define TILE_B  16384      // one 128x64 fp16 tile
#define QSPLIT  4
#define QNC     56         // 14336 / 64 / 4

// ---------------- scratch (device globals) ----------------
__device__ int   g_cnt[Ee];
__device__ int   g_off[Ee];
__device__ int   g_tok[Ee][Tt];
__device__ float g_wt[Ee][Tt];

__device__ __align__(16) __half g_xh[(size_t)Tt * Hd];
__device__ __align__(16) __half g_Bp[(size_t)Ee * 640 * Hd];      // rows: 0-317 gate(w1v,v1), 320-637 up(w3v,v3)
__device__ __align__(16) __half g_Bg[(size_t)Ee * Id * 320];      // [I,320] = w1u|u1|pad
__device__ __align__(16) __half g_Bu[(size_t)Ee * Id * 320];      // w3u|u3|pad
__device__ __align__(16) __half g_Bq[(size_t)Ee * 384 * Id];      // rows: w2v|v2|pad
__device__ __align__(16) __half g_Bo[(size_t)Ee * Hd * 320];      // w2u|u2|pad
__device__ __align__(16) __half g_Ph[(size_t)RT * 640];           // hi only (A of gate/up)
__device__ __align__(16) __half g_hh[(size_t)RT * Id];            // hi only (A of Q)
__device__ float g_Qf[(size_t)QSPLIT * RT * 320];
__device__ __align__(16) __half g_Qh[(size_t)RT * 320];

// ---------------- PTX helpers ----------------
__device__ __forceinline__ uint32_t smem_to_u32(const void* p) {
    uint32_t a;
    asm("{ .reg .u64 t; cvta.to.shared.u64 t, %1; cvt.u32.u64 %0, t; }" : "=r"(a) : "l"(p));
    return a;
}
#define LDSM4(r, a)                                                               \
    asm volatile("ldmatrix.sync.aligned.m8n8.x4.shared.b16 {%0,%1,%2,%3}, [%4];"  \
        : "=r"((r)[0]), "=r"((r)[1]), "=r"((r)[2]), "=r"((r)[3]) : "r"(a))
#define MMA16816(d, a, b)                                                         \
    asm volatile("mma.sync.aligned.m16n8k16.row.col.f32.f16.f16.f32 "             \
        "{%0,%1,%2,%3},{%4,%5,%6,%7},{%8,%9},{%0,%1,%2,%3};"                      \
        : "+f"((d)[0]), "+f"((d)[1]), "+f"((d)[2]), "+f"((d)[3])                  \
        : "r"((a)[0]), "r"((a)[1]), "r"((a)[2]), "r"((a)[3]),                     \
          "r"((b)[0]), "r"((b)[1]))
#define CP16(dst, src, sz)                                                        \
    asm volatile("cp.async.cg.shared.global [%0], [%1], 16, %2;"                  \
        :: "r"(dst), "l"(src), "r"(sz))
#define CP_COMMIT() asm volatile("cp.async.commit_group;" ::: "memory")
#define CP_WAIT(n)  asm volatile("cp.async.wait_group %0;" :: "n"(n) : "memory")

__device__ __forceinline__ uint32_t tile_off(int row, int chunk) {
    return (uint32_t)(row * 128 + ((chunk ^ (row & 7)) << 4));
}

// ---------------- conversion / packing kernels ----------------
__global__ __launch_bounds__(256) void k_split_x(const float* __restrict__ x) {
    int t = blockIdx.x;
    const float4* src = (const float4*)(x + (size_t)t * Hd);
    __half2* dh = (__half2*)(g_xh + (size_t)t * Hd);
    for (int i = threadIdx.x; i < Hd / 4; i += 256) {
        float4 v = src[i];
        dh[2 * i]     = __floats2half2_rn(v.x, v.y);
        dh[2 * i + 1] = __floats2half2_rn(v.z, v.w);
    }
}

__global__ __launch_bounds__(256) void k_conv_Bp(
    const float* __restrict__ w1v, const float* __restrict__ v1,
    const float* __restrict__ w3v, const float* __restrict__ v3)
{
    int j = blockIdx.x, e = blockIdx.y;
    const float* src = nullptr;
    if      (j < Rr)            src = w1v + ((size_t)e * Rr + j) * Hd;
    else if (j < R2)            src = v1  + ((size_t)e * Rr + j - Rr) * Hd;
    else if (j >= 320 && j < 320 + Rr) src = w3v + ((size_t)e * Rr + j - 320) * Hd;
    else if (j >= 320 + Rr && j < 320 + R2) src = v3 + ((size_t)e * Rr + j - 320 - Rr) * Hd;
    __half2* dst = (__half2*)(g_Bp + ((size_t)e * 640 + j) * Hd);
    for (int i = threadIdx.x; i < Hd / 2; i += 256) {
        float2 v = src ? ((const float2*)src)[i] : make_float2(0.f, 0.f);
        dst[i] = __floats2half2_rn(v.x, v.y);
    }
}

template <int SEL>  // 0: Bg(w1u,u1,I)  1: Bu(w3u,u3,I)  2: Bo(w2u,u2,H)
__global__ __launch_bounds__(320) void k_pack320(
    const float* __restrict__ W, const float* __restrict__ U)
{
    constexpr int ROWS = (SEL == 2) ? Hd : Id;
    __half* D = (SEL == 0) ? g_Bg : (SEL == 1) ? g_Bu : g_Bo;
    int e = blockIdx.y;
    int r = blockIdx.x * 4 + (threadIdx.x / 80);
    int c4 = (threadIdx.x % 80) * 4;
    const float* w = W + ((size_t)e * ROWS + r) * Rr;
    const float* u = U + ((size_t)e * ROWS + r) * Rr;
    float v[4];
#pragma unroll
    for (int j = 0; j < 4; j++) {
        int k = c4 + j;
        v[j] = (k < Rr) ? w[k] : ((k < R2) ? u[k - Rr] : 0.f);
    }
    __half2 h0 = __floats2half2_rn(v[0], v[1]);
    __half2 h1 = __floats2half2_rn(v[2], v[3]);
    uint2 pk = make_uint2(*(uint32_t*)&h0, *(uint32_t*)&h1);
    *(uint2*)(D + ((size_t)e * ROWS + r) * 320 + c4) = pk;
}

__global__ __launch_bounds__(256) void k_conv_Bq(
    const float* __restrict__ w2v, const float* __restrict__ v2)
{
    int j = blockIdx.x, e = blockIdx.y;
    const float* src = nullptr;
    if      (j < Rr) src = w2v + ((size_t)e * Rr + j) * Id;
    else if (j < R2) src = v2  + ((size_t)e * Rr + j - Rr) * Id;
    __half2* dst = (__half2*)(g_Bq + ((size_t)e * 384 + j) * Id);
    for (int i = threadIdx.x; i < Id / 2; i += 256) {
        float2 v = src ? ((const float2*)src)[i] : make_float2(0.f, 0.f);
        dst[i] = __floats2half2_rn(v.x, v.y);
    }
}

__global__ __launch_bounds__(256) void k_qsum() {
    size_t i = (size_t)blockIdx.x * 256 + threadIdx.x;   // grid covers RT*320
    constexpr size_t S = (size_t)RT * 320;
    float s = g_Qf[i] + g_Qf[i + S] + g_Qf[i + 2 * S] + g_Qf[i + 3 * S];
    g_Qh[i] = __float2half_rn(s);
}

// ---------------- router / routing ----------------
__device__ __forceinline__ float warpsum(float v) {
#pragma unroll
    for (int o = 16; o; o >>= 1) v += __shfl_down_sync(0xffffffffu, v, o);
    return v;
}

__global__ __launch_bounds__(256) void router_kernel(
    const float* __restrict__ x, const float* __restrict__ gw, float* __restrict__ logits)
{
    int t = blockIdx.x;
    const float4* xr = (const float4*)(x + (size_t)t * Hd);
    float acc[Ee];
#pragma unroll
    for (int e = 0; e < Ee; e++) acc[e] = 0.f;
    for (int i = threadIdx.x; i < Hd / 4; i += 256) {
        float4 xv = xr[i];
#pragma unroll
        for (int e = 0; e < Ee; e++) {
            float4 wv = ((const float4*)(gw + (size_t)e * Hd))[i];
            acc[e] = fmaf(xv.x, wv.x, fmaf(xv.y, wv.y, fmaf(xv.z, wv.z, fmaf(xv.w, wv.w, acc[e]))));
        }
    }
    __shared__ float red[8][Ee];
    int lane = threadIdx.x & 31, w = threadIdx.x >> 5;
#pragma unroll
    for (int e = 0; e < Ee; e++) {
        float s = warpsum(acc[e]);
        if (lane == 0) red[w][e] = s;
    }
    __syncthreads();
    if (threadIdx.x < Ee) {
        float s = 0.f;
#pragma unroll
        for (int w2 = 0; w2 < 8; w2++) s += red[w2][threadIdx.x];
        logits[(size_t)t * Ee + threadIdx.x] = s;
    }
}

__global__ void prep_kernel() { if (threadIdx.x < Ee) g_cnt[threadIdx.x] = 0; }

__global__ void route_kernel(const float* __restrict__ logits)
{
    int t = blockIdx.x * blockDim.x + threadIdx.x;
    if (t >= Tt) return;
    float l[Ee];
#pragma unroll
    for (int e = 0; e < Ee; e++) l[e] = logits[(size_t)t * Ee + e];
    int i1 = 0; float m1 = l[0];
#pragma unroll
    for (int e = 1; e < Ee; e++) if (l[e] > m1) { m1 = l[e]; i1 = e; }
    int i2 = -1; float m2 = -1e30f;
#pragma unroll
    for (int e = 0; e < Ee; e++) if (e != i1 && l[e] > m2) { m2 = l[e]; i2 = e; }
    float w1 = 1.f / (1.f + expf(m2 - m1));
    float w2 = 1.f - w1;
    int p = atomicAdd(&g_cnt[i1], 1); g_tok[i1][p] = t; g_wt[i1][p] = w1;
    p     = atomicAdd(&g_cnt[i2], 1); g_tok[i2][p] = t; g_wt[i2][p] = w2;
}

__global__ void offsets_kernel()
{
    if (threadIdx.x == 0) {
        int s = 0;
        for (int e = 0; e < Ee; e++) { g_off[e] = s; s += g_cnt[e]; }
    }
}

// ---------------- fp16 HMMA GEMM (128-M tile family, single-A) ----------------
// KIND 0: P = gather(xh) @ Bp^T       K=4096 NC=64  N=640(5)    3-stage, 96KB
// KIND 1: h = silu(P@Bg^T)*(P@Bu^T)   K=320 NC=5x2  N=14336(112) 2-stage + half stash, 96KB
// KIND 3: out += wt * (Q @ Bo^T)      K=320 NC=5    N=4096(32)  3-stage, 96KB
// All forced to 2 CTAs/SM via __launch_bounds__(256, 2).
template <int KIND>
__global__ __launch_bounds__(256, 2) void moe_mma(float* __restrict__ outp)
{
    constexpr int NSTAGE = (KIND == 1) ? 2 : STAGES;
    constexpr int STAGE_B = 2 * TILE_B;
    constexpr int NCc   = (KIND == 0) ? 64 : 5;
    constexpr int NPASS = (KIND == 1) ? 2 : 1;
    constexpr int Kb    = (KIND == 0) ? Hd : 320;
    constexpr int Brows = (KIND == 0) ? 640 : (KIND == 1) ? Id : Hd;

    int e     = blockIdx.z;
    int n_e   = g_cnt[e];
    int mbase = blockIdx.x * 128;
    if (mbase >= n_e) return;
    int nbase = blockIdx.y * 128;
    int off   = g_off[e];

    extern __shared__ char smem[];
    uint32_t smem_u32 = smem_to_u32(smem);
    __half2* sg2 = (__half2*)(smem + NSTAGE * STAGE_B);   // KIND1 silu stash (32KB)

    int tid = threadIdx.x, lane = tid & 31, wid = tid >> 5;
    int wm = wid & 1, wn = wid >> 1;
    int row = tid >> 1, half = tid & 1;
    int ml = mbase + row;
    unsigned szA = (ml < n_e) ? 16u : 0u;

    // A row base
    const __half* Ah_row;
    if (KIND == 0) {
        int t = (ml < n_e) ? g_tok[e][ml] : 0;
        Ah_row = g_xh + (size_t)t * Hd;
    } else {
        size_t r = (size_t)off + ((ml < n_e) ? ml : 0);
        Ah_row = (KIND == 1) ? (g_Ph + r * 640) : (g_Qh + r * 320);
    }

    float acc[4][4][4];
#pragma unroll
    for (int i = 0; i < 4; i++)
#pragma unroll
        for (int j = 0; j < 4; j++)
#pragma unroll
            for (int q = 0; q < 4; q++) acc[i][j][q] = 0.f;

    for (int p = 0; p < NPASS; p++) {
        int acoff = (KIND == 1) ? p * 320 : 0;
        const __half* Bm = (KIND == 0) ? g_Bp : (KIND == 1) ? (p ? g_Bu : g_Bg) : g_Bo;
        const __half* Brow = Bm + ((size_t)e * Brows + nbase + row) * Kb;

        auto issue_load = [&](int st, int c) {
            uint32_t sb = smem_u32 + st * STAGE_B;
            int col = c * 64 + half * 32;
#pragma unroll
            for (int i = 0; i < 4; i++) {
                uint32_t so = tile_off(row, half * 4 + i);
                CP16(sb + so, Ah_row + acoff + col + i * 8, szA);
                CP16(sb + TILE_B + so, Brow + col + i * 8, 16u);
            }
        };

        auto compute = [&](int st) {
            uint32_t base = smem_u32 + st * STAGE_B;
#pragma unroll
            for (int ks = 0; ks < 4; ks++) {
                uint32_t Ahf[4][4], Bf[4][2];
#pragma unroll
                for (int mf = 0; mf < 4; mf++) {
                    int ar = wm * 64 + mf * 16 + (lane & 15);
                    LDSM4(Ahf[mf], base + tile_off(ar, ks * 2 + (lane >> 4)));
                }
#pragma unroll
                for (int g = 0; g < 2; g++) {
                    int br = wn * 32 + g * 16 + ((lane >> 4) << 3) + (lane & 7);
                    uint32_t o = tile_off(br, ks * 2 + ((lane >> 3) & 1));
                    uint32_t r[4];
                    LDSM4(r, base + TILE_B + o);
                    Bf[2 * g][0] = r[0]; Bf[2 * g][1] = r[1];
                    Bf[2 * g + 1][0] = r[2]; Bf[2 * g + 1][1] = r[3];
                }
#pragma unroll
                for (int mf = 0; mf < 4; mf++)
#pragma unroll
                    for (int nf = 0; nf < 4; nf++) MMA16816(acc[mf][nf], Ahf[mf], Bf[nf]);
            }
        };

        if (NSTAGE == 3) {
            issue_load(0, 0); CP_COMMIT();
            if (NCc > 1) issue_load(1, 1);
            CP_COMMIT();
            CP_WAIT(1);
            __syncthreads();
            for (int c = 0; c < NCc; c++) {
                if (c + 2 < NCc) issue_load((c + 2) % 3, c + 2);
                CP_COMMIT();
                compute(c % 3);
                CP_WAIT(1);
                __syncthreads();
            }
        } else {
            // 2-stage double buffer
            issue_load(0, 0); CP_COMMIT();
            CP_WAIT(0);
            __syncthreads();
            for (int c = 0; c < NCc; c++) {
                if (c + 1 < NCc) { issue_load((c + 1) & 1, c + 1); CP_COMMIT(); }
                compute(c & 1);
                if (c + 1 < NCc) { CP_WAIT(0); __syncthreads(); }
            }
        }

        if (KIND == 1 && p == 0) {
#pragma unroll
            for (int mf = 0; mf < 4; mf++)
#pragma unroll
                for (int nf = 0; nf < 4; nf++)
#pragma unroll
                    for (int qp = 0; qp < 2; qp++) {
                        float g0 = acc[mf][nf][qp * 2 + 0];
                        float g1 = acc[mf][nf][qp * 2 + 1];
                        g0 = g0 / (1.f + __expf(-g0));
                        g1 = g1 / (1.f + __expf(-g1));
                        sg2[((mf * 4 + nf) * 2 + qp) * 256 + tid] = __floats2half2_rn(g0, g1);
                        acc[mf][nf][qp * 2 + 0] = 0.f;
                        acc[mf][nf][qp * 2 + 1] = 0.f;
                    }
            __syncthreads();
        }
    }

    // ---------------- epilogue ----------------
#pragma unroll
    for (int mf = 0; mf < 4; mf++)
#pragma unroll
        for (int nf = 0; nf < 4; nf++)
#pragma unroll
            for (int qp = 0; qp < 2; qp++) {
                int r = wm * 64 + mf * 16 + (lane >> 2) + qp * 8;
                int m = mbase + r;
                if (m >= n_e) continue;
                int col = nbase + wn * 32 + nf * 8 + (lane & 3) * 2;
                float v0 = acc[mf][nf][qp * 2 + 0];
                float v1 = acc[mf][nf][qp * 2 + 1];
                if (KIND == 0) {
                    size_t b = (size_t)(off + m) * 640 + col;
                    *(__half2*)(g_Ph + b) = __floats2half2_rn(v0, v1);
                } else if (KIND == 1) {
                    float2 sf = __half22float2(sg2[((mf * 4 + nf) * 2 + qp) * 256 + tid]);
                    v0 *= sf.x;
                    v1 *= sf.y;
                    size_t b = (size_t)(off + m) * Id + col;
                    *(__half2*)(g_hh + b) = __floats2half2_rn(v0, v1);
                } else {
                    float wt  = g_wt[e][m];
                    int   tok = g_tok[e][m];
                    float* dst = outp + (size_t)tok * Hd + col;
                    atomicAdd(dst, wt * v0);
                    atomicAdd(dst + 1, wt * v1);
                }
            }
}

// ---------------- Q GEMM: M=64, N=384 single pass, 4 K-slices ----------------
#define QA_B 8192
#define QB_B 49152
#define QST_B (QA_B + QB_B)
#define QCHUNKS 3584   // (64 + 384) rows * 8 chunks
__global__ __launch_bounds__(256, 1) void moe_mma_q()
{
    int e     = blockIdx.z;
    int n_e   = g_cnt[e];
    int mbase = blockIdx.x * 64;
    if (mbase >= n_e) return;
    int kslice = blockIdx.y;
    int cbase  = kslice * QNC;
    int off    = g_off[e];

    extern __shared__ char smem[];
    uint32_t smem_u32 = smem_to_u32(smem);

    int tid = threadIdx.x, lane = tid & 31, wn = tid >> 5;

    float acc[4][6][4];
#pragma unroll
    for (int i = 0; i < 4; i++)
#pragma unroll
        for (int j = 0; j < 6; j++)
#pragma unroll
            for (int q = 0; q < 4; q++) acc[i][j][q] = 0.f;

    const __half* Bq_e = g_Bq + (size_t)e * 384 * Id;

    auto issue_load = [&](int st, int c) {
        uint32_t sb = smem_u32 + st * QST_B;
        int col = (cbase + c) * 64;
#pragma unroll
        for (int i = 0; i < 14; i++) {
            int ci = tid + i * 256;
            if (ci >= QCHUNKS) break;
            if (ci < 512) {
                int row = ci >> 3, ch = ci & 7;
                int m = mbase + row;
                unsigned sz = (m < n_e) ? 16u : 0u;
                const __half* src = g_hh + ((size_t)off + ((m < n_e) ? m : 0)) * Id + col + ch * 8;
                CP16(sb + tile_off(row, ch), src, sz);
            } else {
                int bi = ci - 512;
                int row = bi >> 3, ch = bi & 7;
                const __half* src = Bq_e + (size_t)row * Id + col + ch * 8;
                CP16(sb + QA_B + tile_off(row, ch), src, 16u);
            }
        }
    };

    auto compute = [&](int st) {
        uint32_t base = smem_u32 + st * QST_B;
#pragma unroll
        for (int ks = 0; ks < 4; ks++) {
            uint32_t Af[4][4], Bf[6][2];
#pragma unroll
            for (int mf = 0; mf < 4; mf++) {
                int ar = mf * 16 + (lane & 15);
                LDSM4(Af[mf], base + tile_off(ar, ks * 2 + (lane >> 4)));
            }
#pragma unroll
            for (int g = 0; g < 3; g++) {
                int br = wn * 48 + g * 16 + ((lane >> 4) << 3) + (lane & 7);
                uint32_t o = tile_off(br, ks * 2 + ((lane >> 3) & 1));
                uint32_t r[4];
                LDSM4(r, base + QA_B + o);
                Bf[2 * g][0] = r[0]; Bf[2 * g][1] = r[1];
                Bf[2 * g + 1][0] = r[2]; Bf[2 * g + 1][1] = r[3];
            }
#pragma unroll
            for (int mf = 0; mf < 4; mf++)
#pragma unroll
                for (int nf = 0; nf < 6; nf++) MMA16816(acc[mf][nf], Af[mf], Bf[nf]);
        }
    };

    issue_load(0, 0); CP_COMMIT();
    issue_load(1, 1); CP_COMMIT();
    CP_WAIT(1);
    __syncthreads();

    for (int c = 0; c < QNC; c++) {
        if (c + 2 < QNC) issue_load((c + 2) % STAGES, c + 2);
        CP_COMMIT();
        compute(c % STAGES);
        CP_WAIT(1);
        __syncthreads();
    }

    float* qf = g_Qf + (size_t)kslice * RT * 320;
#pragma unroll
    for (int mf = 0; mf < 4; mf++)
#pragma unroll
        for (int nf = 0; nf < 6; nf++)
#pragma unroll
            for (int qp = 0; qp < 2; qp++) {
                int m = mbase + mf * 16 + (lane >> 2) + qp * 8;
                if (m >= n_e) continue;
                int col = wn * 48 + nf * 8 + (lane & 3) * 2;
                if (col >= 320) continue;
                size_t b = (size_t)(off + m) * 320 + col;
                qf[b]     = acc[mf][nf][qp * 2 + 0];
                qf[b + 1] = acc[mf][nf][qp * 2 + 1];
            }
}

// ---------------- launch ----------------
extern "C" void kernel_launch(void* const* d_in, const int* in_sizes, int n_in,
                              void* d_out, int out_size)
{
    const float* x    = (const float*)d_in[0];
    const float* gw   = (const float*)d_in[1];
    const float* w1u  = (const float*)d_in[2];
    const float* w1v  = (const float*)d_in[3];
    const float* w2u  = (const float*)d_in[4];
    const float* w2v  = (const float*)d_in[5];
    const float* w3u  = (const float*)d_in[6];
    const float* w3v  = (const float*)d_in[7];
    const float* u1   = (const float*)d_in[8];
    const float* v1   = (const float*)d_in[9];
    const float* u2   = (const float*)d_in[10];
    const float* v2   = (const float*)d_in[11];
    const float* u3   = (const float*)d_in[12];
    const float* v3   = (const float*)d_in[13];

    float* outp   = (float*)d_out;
    float* logits = outp + (size_t)Tt * Hd;

    // one-time host resources (streams/events are host objects; no device alloc)
    static cudaStream_t s_pack = nullptr;
    static cudaEvent_t evStart, evBp, evBgu, evBq, evBo;
    if (!s_pack) {
        cudaStreamCreateWithFlags(&s_pack, cudaStreamNonBlocking);
        cudaEventCreateWithFlags(&evStart, cudaEventDisableTiming);
        cudaEventCreateWithFlags(&evBp,    cudaEventDisableTiming);
        cudaEventCreateWithFlags(&evBgu,   cudaEventDisableTiming);
        cudaEventCreateWithFlags(&evBq,    cudaEventDisableTiming);
        cudaEventCreateWithFlags(&evBo,    cudaEventDisableTiming);

        int smem_s2 = STAGES * 2 * TILE_B;        // 96KB (KIND0/3)
        int smem_gu = 2 * 2 * TILE_B + 32768;     // 96KB (KIND1: 2-stage + half stash)
        int smem_q  = STAGES * QST_B;             // 168KB
        cudaFuncSetAttribute(moe_mma<0>, cudaFuncAttributeMaxDynamicSharedMemorySize, smem_s2);
        cudaFuncSetAttribute(moe_mma<1>, cudaFuncAttributeMaxDynamicSharedMemorySize, smem_gu);
        cudaFuncSetAttribute(moe_mma<3>, cudaFuncAttributeMaxDynamicSharedMemorySize, smem_s2);
        cudaFuncSetAttribute(moe_mma_q,  cudaFuncAttributeMaxDynamicSharedMemorySize, smem_q);
    }
    int smem_s2 = STAGES * 2 * TILE_B;
    int smem_gu = 2 * 2 * TILE_B + 32768;
    int smem_q  = STAGES * QST_B;

    // fork: weight packing on side stream, overlapped with router/P/GU chain
    cudaEventRecord(evStart, 0);
    cudaStreamWaitEvent(s_pack, evStart, 0);

    k_conv_Bp<<<dim3(640, Ee), 256, 0, s_pack>>>(w1v, v1, w3v, v3);
    cudaEventRecord(evBp, s_pack);
    k_pack320<0><<<dim3(Id / 4, Ee), 320, 0, s_pack>>>(w1u, u1);
    k_pack320<1><<<dim3(Id / 4, Ee), 320, 0, s_pack>>>(w3u, u3);
    cudaEventRecord(evBgu, s_pack);
    k_conv_Bq<<<dim3(384, Ee), 256, 0, s_pack>>>(w2v, v2);
    cudaEventRecord(evBq, s_pack);
    k_pack320<2><<<dim3(Hd / 4, Ee), 320, 0, s_pack>>>(w2u, u2);
    cudaEventRecord(evBo, s_pack);

    // main stream: routing chain
    cudaMemsetAsync(outp, 0, (size_t)Tt * Hd * sizeof(float));
    k_split_x<<<Tt, 256>>>(x);
    prep_kernel<<<1, 32>>>();
    router_kernel<<<Tt, 256>>>(x, gw, logits);
    route_kernel<<<Tt / 256, 256>>>(logits);
    offsets_kernel<<<1, 32>>>();

    cudaStreamWaitEvent(0, evBp, 0);
    moe_mma<0><<<dim3(32, 5, Ee),   256, smem_s2>>>(nullptr);   // P
    cudaStreamWaitEvent(0, evBgu, 0);
    moe_mma<1><<<dim3(32, 112, Ee), 256, smem_gu>>>(nullptr);   // gate/up -> h
    cudaStreamWaitEvent(0, evBq, 0);
    moe_mma_q<<<dim3(64, QSPLIT, Ee), 256, smem_q>>>();         // Q (h read once)
    k_qsum<<<(RT * 320) / 256, 256>>>();
    cudaStreamWaitEvent(0, evBo, 0);
    moe_mma<3><<<dim3(32, 32, Ee),  256, smem_s2>>>(outp);      // scatter
}

// round 11
// speedup vs baseline: 7.5972x; 1.0062x over previous
#include <cuda_runtime.h>
#include <cuda_fp16.h>
#include <cstdint>
#include <math.h>

// ---------------- problem constants ----------------
#define Hd   4096
#define Id   14336
#define Rr   159
#define R2   318
#define Ee   8
#define Tt   4096
#define RT   8192          // total routed rows (Tt * topk)

#define STAGES  3
#define TILE_B  16384      // one 128x64 fp16 tile
#define QSPLIT  4
#define QNC     56         // 14336 / 64 / 4

// ---------------- scratch (device globals) ----------------
__device__ int   g_cnt[Ee];
__device__ int   g_off[Ee];
__device__ int   g_tok[Ee][Tt];
__device__ float g_wt[Ee][Tt];

__device__ __align__(16) __half g_xh[(size_t)Tt * Hd];
__device__ __align__(16) __half g_Bp[(size_t)Ee * 640 * Hd];      // rows: 0-317 gate(w1v,v1), 320-637 up(w3v,v3)
__device__ __align__(16) __half g_Bg[(size_t)Ee * Id * 320];      // [I,320] = w1u|u1|pad
__device__ __align__(16) __half g_Bu[(size_t)Ee * Id * 320];      // w3u|u3|pad
__device__ __align__(16) __half g_Bq[(size_t)Ee * 384 * Id];      // rows: w2v|v2 (only 320 used)
__device__ __align__(16) __half g_Bo[(size_t)Ee * Hd * 320];      // w2u|u2|pad
__device__ __align__(16) __half g_Ph[(size_t)RT * 640];           // hi only (A of gate/up)
__device__ __align__(16) __half g_hh[(size_t)RT * Id];            // hi only (A of Q)
__device__ float g_Qf[(size_t)QSPLIT * RT * 320];
__device__ __align__(16) __half g_Qh[(size_t)RT * 320];

// ---------------- PTX helpers ----------------
__device__ __forceinline__ uint32_t smem_to_u32(const void* p) {
    uint32_t a;
    asm("{ .reg .u64 t; cvta.to.shared.u64 t, %1; cvt.u32.u64 %0, t; }" : "=r"(a) : "l"(p));
    return a;
}
#define LDSM4(r, a)                                                               \
    asm volatile("ldmatrix.sync.aligned.m8n8.x4.shared.b16 {%0,%1,%2,%3}, [%4];"  \
        : "=r"((r)[0]), "=r"((r)[1]), "=r"((r)[2]), "=r"((r)[3]) : "r"(a))
#define LDSM2(r, a)                                                               \
    asm volatile("ldmatrix.sync.aligned.m8n8.x2.shared.b16 {%0,%1}, [%2];"        \
        : "=r"((r)[0]), "=r"((r)[1]) : "r"(a))
#define MMA16816(d, a, b)                                                         \
    asm volatile("mma.sync.aligned.m16n8k16.row.col.f32.f16.f16.f32 "             \
        "{%0,%1,%2,%3},{%4,%5,%6,%7},{%8,%9},{%0,%1,%2,%3};"                      \
        : "+f"((d)[0]), "+f"((d)[1]), "+f"((d)[2]), "+f"((d)[3])                  \
        : "r"((a)[0]), "r"((a)[1]), "r"((a)[2]), "r"((a)[3]),                     \
          "r"((b)[0]), "r"((b)[1]))
#define CP16(dst, src, sz)                                                        \
    asm volatile("cp.async.cg.shared.global [%0], [%1], 16, %2;"                  \
        :: "r"(dst), "l"(src), "r"(sz))
#define CP_COMMIT() asm volatile("cp.async.commit_group;" ::: "memory")
#define CP_WAIT(n)  asm volatile("cp.async.wait_group %0;" :: "n"(n) : "memory")

__device__ __forceinline__ uint32_t tile_off(int row, int chunk) {
    return (uint32_t)(row * 128 + ((chunk ^ (row & 7)) << 4));
}

// ---------------- conversion / packing kernels ----------------
__global__ __launch_bounds__(256) void k_conv_Bp(
    const float* __restrict__ w1v, const float* __restrict__ v1,
    const float* __restrict__ w3v, const float* __restrict__ v3)
{
    int j = blockIdx.x, e = blockIdx.y;
    const float* src = nullptr;
    if      (j < Rr)            src = w1v + ((size_t)e * Rr + j) * Hd;
    else if (j < R2)            src = v1  + ((size_t)e * Rr + j - Rr) * Hd;
    else if (j >= 320 && j < 320 + Rr) src = w3v + ((size_t)e * Rr + j - 320) * Hd;
    else if (j >= 320 + Rr && j < 320 + R2) src = v3 + ((size_t)e * Rr + j - 320 - Rr) * Hd;
    __half2* dst = (__half2*)(g_Bp + ((size_t)e * 640 + j) * Hd);
    for (int i = threadIdx.x; i < Hd / 2; i += 256) {
        float2 v = src ? ((const float2*)src)[i] : make_float2(0.f, 0.f);
        dst[i] = __floats2half2_rn(v.x, v.y);
    }
}

template <int SEL>  // 0: Bg(w1u,u1,I)  1: Bu(w3u,u3,I)  2: Bo(w2u,u2,H)
__global__ __launch_bounds__(320) void k_pack320(
    const float* __restrict__ W, const float* __restrict__ U)
{
    constexpr int ROWS = (SEL == 2) ? Hd : Id;
    __half* D = (SEL == 0) ? g_Bg : (SEL == 1) ? g_Bu : g_Bo;
    int e = blockIdx.y;
    int r = blockIdx.x * 4 + (threadIdx.x / 80);
    int c4 = (threadIdx.x % 80) * 4;
    const float* w = W + ((size_t)e * ROWS + r) * Rr;
    const float* u = U + ((size_t)e * ROWS + r) * Rr;
    float v[4];
#pragma unroll
    for (int j = 0; j < 4; j++) {
        int k = c4 + j;
        v[j] = (k < Rr) ? w[k] : ((k < R2) ? u[k - Rr] : 0.f);
    }
    __half2 h0 = __floats2half2_rn(v[0], v[1]);
    __half2 h1 = __floats2half2_rn(v[2], v[3]);
    uint2 pk = make_uint2(*(uint32_t*)&h0, *(uint32_t*)&h1);
    *(uint2*)(D + ((size_t)e * ROWS + r) * 320 + c4) = pk;
}

__global__ __launch_bounds__(256) void k_conv_Bq(
    const float* __restrict__ w2v, const float* __restrict__ v2)
{
    int j = blockIdx.x, e = blockIdx.y;   // j in [0,320)
    const float* src = nullptr;
    if      (j < Rr) src = w2v + ((size_t)e * Rr + j) * Id;
    else if (j < R2) src = v2  + ((size_t)e * Rr + j - Rr) * Id;
    __half2* dst = (__half2*)(g_Bq + ((size_t)e * 384 + j) * Id);
    for (int i = threadIdx.x; i < Id / 2; i += 256) {
        float2 v = src ? ((const float2*)src)[i] : make_float2(0.f, 0.f);
        dst[i] = __floats2half2_rn(v.x, v.y);
    }
}

__global__ __launch_bounds__(256) void k_qsum() {
    size_t i = (size_t)blockIdx.x * 256 + threadIdx.x;   // grid covers RT*320
    constexpr size_t S = (size_t)RT * 320;
    float s = g_Qf[i] + g_Qf[i + S] + g_Qf[i + 2 * S] + g_Qf[i + 3 * S];
    g_Qh[i] = __float2half_rn(s);
}

// ---------------- router (fused: logits fp32 + x -> fp16 split) ----------------
__device__ __forceinline__ float warpsum(float v) {
#pragma unroll
    for (int o = 16; o; o >>= 1) v += __shfl_down_sync(0xffffffffu, v, o);
    return v;
}

// 512 CTAs x 8 tokens; gw staged in 128KB smem once per CTA.
__global__ __launch_bounds__(256) void router_kernel(
    const float* __restrict__ x, const float* __restrict__ gw, float* __restrict__ logits)
{
    extern __shared__ float sgw[];   // [Ee * Hd] = 128KB
    int tid = threadIdx.x;
    for (int i = tid; i < Ee * Hd / 4; i += 256)
        ((float4*)sgw)[i] = ((const float4*)gw)[i];
    __syncthreads();

    int lane = tid & 31, grp = tid >> 5;
    int t = blockIdx.x * 8 + grp;
    const float4* xr = (const float4*)(x + (size_t)t * Hd);
    __half2* dh = (__half2*)(g_xh + (size_t)t * Hd);

    float acc[Ee];
#pragma unroll
    for (int e = 0; e < Ee; e++) acc[e] = 0.f;

    for (int it = 0; it < Hd / 4 / 32; it++) {
        int i = lane + it * 32;
        float4 xv = xr[i];
        dh[2 * i]     = __floats2half2_rn(xv.x, xv.y);
        dh[2 * i + 1] = __floats2half2_rn(xv.z, xv.w);
#pragma unroll
        for (int e = 0; e < Ee; e++) {
            float4 wv = ((const float4*)(sgw + (size_t)e * Hd))[i];
            acc[e] = fmaf(xv.x, wv.x, fmaf(xv.y, wv.y, fmaf(xv.z, wv.z, fmaf(xv.w, wv.w, acc[e]))));
        }
    }
#pragma unroll
    for (int e = 0; e < Ee; e++) {
        float s = warpsum(acc[e]);
        if (lane == 0) logits[(size_t)t * Ee + e] = s;
    }
}

__global__ void prep_kernel() { if (threadIdx.x < Ee) g_cnt[threadIdx.x] = 0; }

__global__ void route_kernel(const float* __restrict__ logits)
{
    int t = blockIdx.x * blockDim.x + threadIdx.x;
    if (t >= Tt) return;
    float l[Ee];
#pragma unroll
    for (int e = 0; e < Ee; e++) l[e] = logits[(size_t)t * Ee + e];
    int i1 = 0; float m1 = l[0];
#pragma unroll
    for (int e = 1; e < Ee; e++) if (l[e] > m1) { m1 = l[e]; i1 = e; }
    int i2 = -1; float m2 = -1e30f;
#pragma unroll
    for (int e = 0; e < Ee; e++) if (e != i1 && l[e] > m2) { m2 = l[e]; i2 = e; }
    float w1 = 1.f / (1.f + expf(m2 - m1));
    float w2 = 1.f - w1;
    int p = atomicAdd(&g_cnt[i1], 1); g_tok[i1][p] = t; g_wt[i1][p] = w1;
    p     = atomicAdd(&g_cnt[i2], 1); g_tok[i2][p] = t; g_wt[i2][p] = w2;
}

__global__ void offsets_kernel()
{
    if (threadIdx.x == 0) {
        int s = 0;
        for (int e = 0; e < Ee; e++) { g_off[e] = s; s += g_cnt[e]; }
    }
}

// ---------------- fp16 HMMA GEMM (128-M tile family, single-A) ----------------
// KIND 0: P = gather(xh) @ Bp^T       K=4096 NC=64  N=640(5)    3-stage, 96KB
// KIND 1: h = silu(P@Bg^T)*(P@Bu^T)   K=320 NC=5x2  N=14336(112) 2-stage + half stash, 96KB
// KIND 3: out += wt * (Q @ Bo^T)      K=320 NC=5    N=4096(32)  3-stage, 96KB
template <int KIND>
__global__ __launch_bounds__(256, 2) void moe_mma(float* __restrict__ outp)
{
    constexpr int NSTAGE = (KIND == 1) ? 2 : STAGES;
    constexpr int STAGE_B = 2 * TILE_B;
    constexpr int NCc   = (KIND == 0) ? 64 : 5;
    constexpr int NPASS = (KIND == 1) ? 2 : 1;
    constexpr int Kb    = (KIND == 0) ? Hd : 320;
    constexpr int Brows = (KIND == 0) ? 640 : (KIND == 1) ? Id : Hd;

    int e     = blockIdx.z;
    int n_e   = g_cnt[e];
    int mbase = blockIdx.x * 128;
    if (mbase >= n_e) return;
    int nbase = blockIdx.y * 128;
    int off   = g_off[e];

    extern __shared__ char smem[];
    uint32_t smem_u32 = smem_to_u32(smem);
    __half2* sg2 = (__half2*)(smem + NSTAGE * STAGE_B);   // KIND1 silu stash (32KB)

    int tid = threadIdx.x, lane = tid & 31, wid = tid >> 5;
    int wm = wid & 1, wn = wid >> 1;
    int row = tid >> 1, half = tid & 1;
    int ml = mbase + row;
    unsigned szA = (ml < n_e) ? 16u : 0u;

    const __half* Ah_row;
    if (KIND == 0) {
        int t = (ml < n_e) ? g_tok[e][ml] : 0;
        Ah_row = g_xh + (size_t)t * Hd;
    } else {
        size_t r = (size_t)off + ((ml < n_e) ? ml : 0);
        Ah_row = (KIND == 1) ? (g_Ph + r * 640) : (g_Qh + r * 320);
    }

    float acc[4][4][4];
#pragma unroll
    for (int i = 0; i < 4; i++)
#pragma unroll
        for (int j = 0; j < 4; j++)
#pragma unroll
            for (int q = 0; q < 4; q++) acc[i][j][q] = 0.f;

    for (int p = 0; p < NPASS; p++) {
        int acoff = (KIND == 1) ? p * 320 : 0;
        const __half* Bm = (KIND == 0) ? g_Bp : (KIND == 1) ? (p ? g_Bu : g_Bg) : g_Bo;
        const __half* Brow = Bm + ((size_t)e * Brows + nbase + row) * Kb;

        auto issue_load = [&](int st, int c) {
            uint32_t sb = smem_u32 + st * STAGE_B;
            int col = c * 64 + half * 32;
#pragma unroll
            for (int i = 0; i < 4; i++) {
                uint32_t so = tile_off(row, half * 4 + i);
                CP16(sb + so, Ah_row + acoff + col + i * 8, szA);
                CP16(sb + TILE_B + so, Brow + col + i * 8, 16u);
            }
        };

        auto compute = [&](int st) {
            uint32_t base = smem_u32 + st * STAGE_B;
#pragma unroll
            for (int ks = 0; ks < 4; ks++) {
                uint32_t Ahf[4][4], Bf[4][2];
#pragma unroll
                for (int mf = 0; mf < 4; mf++) {
                    int ar = wm * 64 + mf * 16 + (lane & 15);
                    LDSM4(Ahf[mf], base + tile_off(ar, ks * 2 + (lane >> 4)));
                }
#pragma unroll
                for (int g = 0; g < 2; g++) {
                    int br = wn * 32 + g * 16 + ((lane >> 4) << 3) + (lane & 7);
                    uint32_t o = tile_off(br, ks * 2 + ((lane >> 3) & 1));
                    uint32_t r[4];
                    LDSM4(r, base + TILE_B + o);
                    Bf[2 * g][0] = r[0]; Bf[2 * g][1] = r[1];
                    Bf[2 * g + 1][0] = r[2]; Bf[2 * g + 1][1] = r[3];
                }
#pragma unroll
                for (int mf = 0; mf < 4; mf++)
#pragma unroll
                    for (int nf = 0; nf < 4; nf++) MMA16816(acc[mf][nf], Ahf[mf], Bf[nf]);
            }
        };

        if (NSTAGE == 3) {
            issue_load(0, 0); CP_COMMIT();
            if (NCc > 1) issue_load(1, 1);
            CP_COMMIT();
            CP_WAIT(1);
            __syncthreads();
            for (int c = 0; c < NCc; c++) {
                if (c + 2 < NCc) issue_load((c + 2) % 3, c + 2);
                CP_COMMIT();
                compute(c % 3);
                CP_WAIT(1);
                __syncthreads();
            }
        } else {
            issue_load(0, 0); CP_COMMIT();
            CP_WAIT(0);
            __syncthreads();
            for (int c = 0; c < NCc; c++) {
                if (c + 1 < NCc) { issue_load((c + 1) & 1, c + 1); CP_COMMIT(); }
                compute(c & 1);
                if (c + 1 < NCc) { CP_WAIT(0); __syncthreads(); }
            }
        }

        if (KIND == 1 && p == 0) {
#pragma unroll
            for (int mf = 0; mf < 4; mf++)
#pragma unroll
                for (int nf = 0; nf < 4; nf++)
#pragma unroll
                    for (int qp = 0; qp < 2; qp++) {
                        float g0 = acc[mf][nf][qp * 2 + 0];
                        float g1 = acc[mf][nf][qp * 2 + 1];
                        g0 = g0 / (1.f + __expf(-g0));
                        g1 = g1 / (1.f + __expf(-g1));
                        sg2[((mf * 4 + nf) * 2 + qp) * 256 + tid] = __floats2half2_rn(g0, g1);
                        acc[mf][nf][qp * 2 + 0] = 0.f;
                        acc[mf][nf][qp * 2 + 1] = 0.f;
                    }
            __syncthreads();
        }
    }

    // epilogue
#pragma unroll
    for (int mf = 0; mf < 4; mf++)
#pragma unroll
        for (int nf = 0; nf < 4; nf++)
#pragma unroll
            for (int qp = 0; qp < 2; qp++) {
                int r = wm * 64 + mf * 16 + (lane >> 2) + qp * 8;
                int m = mbase + r;
                if (m >= n_e) continue;
                int col = nbase + wn * 32 + nf * 8 + (lane & 3) * 2;
                float v0 = acc[mf][nf][qp * 2 + 0];
                float v1 = acc[mf][nf][qp * 2 + 1];
                if (KIND == 0) {
                    size_t b = (size_t)(off + m) * 640 + col;
                    *(__half2*)(g_Ph + b) = __floats2half2_rn(v0, v1);
                } else if (KIND == 1) {
                    float2 sf = __half22float2(sg2[((mf * 4 + nf) * 2 + qp) * 256 + tid]);
                    v0 *= sf.x;
                    v1 *= sf.y;
                    size_t b = (size_t)(off + m) * Id + col;
                    *(__half2*)(g_hh + b) = __floats2half2_rn(v0, v1);
                } else {
                    float wt  = g_wt[e][m];
                    int   tok = g_tok[e][m];
                    float* dst = outp + (size_t)tok * Hd + col;
                    atomicAdd(dst, wt * v0);
                    atomicAdd(dst + 1, wt * v1);
                }
            }
}

// ---------------- Q GEMM: M=64, N=320 exact, 4 K-slices ----------------
#define QA_B 8192
#define QB_B 40960
#define QST_B (QA_B + QB_B)   // 49152
#define QCHUNKS 3072          // (64 + 320) rows * 8 chunks
__global__ __launch_bounds__(256, 1) void moe_mma_q()
{
    int e     = blockIdx.z;
    int n_e   = g_cnt[e];
    int mbase = blockIdx.x * 64;
    if (mbase >= n_e) return;
    int kslice = blockIdx.y;
    int cbase  = kslice * QNC;
    int off    = g_off[e];

    extern __shared__ char smem[];
    uint32_t smem_u32 = smem_to_u32(smem);

    int tid = threadIdx.x, lane = tid & 31, wn = tid >> 5;

    float acc[4][5][4];
#pragma unroll
    for (int i = 0; i < 4; i++)
#pragma unroll
        for (int j = 0; j < 5; j++)
#pragma unroll
            for (int q = 0; q < 4; q++) acc[i][j][q] = 0.f;

    const __half* Bq_e = g_Bq + (size_t)e * 384 * Id;

    auto issue_load = [&](int st, int c) {
        uint32_t sb = smem_u32 + st * QST_B;
        int col = (cbase + c) * 64;
#pragma unroll
        for (int i = 0; i < 12; i++) {
            int ci = tid + i * 256;
            if (ci >= QCHUNKS) break;
            if (ci < 512) {
                int row = ci >> 3, ch = ci & 7;
                int m = mbase + row;
                unsigned sz = (m < n_e) ? 16u : 0u;
                const __half* src = g_hh + ((size_t)off + ((m < n_e) ? m : 0)) * Id + col + ch * 8;
                CP16(sb + tile_off(row, ch), src, sz);
            } else {
                int bi = ci - 512;
                int row = bi >> 3, ch = bi & 7;
                const __half* src = Bq_e + (size_t)row * Id + col + ch * 8;
                CP16(sb + QA_B + tile_off(row, ch), src, 16u);
            }
        }
    };

    auto compute = [&](int st) {
        uint32_t base = smem_u32 + st * QST_B;
#pragma unroll
        for (int ks = 0; ks < 4; ks++) {
            uint32_t Af[4][4], Bf[5][2];
#pragma unroll
            for (int mf = 0; mf < 4; mf++) {
                int ar = mf * 16 + (lane & 15);
                LDSM4(Af[mf], base + tile_off(ar, ks * 2 + (lane >> 4)));
            }
#pragma unroll
            for (int g = 0; g < 2; g++) {
                int br = wn * 40 + g * 16 + ((lane >> 4) << 3) + (lane & 7);
                uint32_t o = tile_off(br, ks * 2 + ((lane >> 3) & 1));
                uint32_t r[4];
                LDSM4(r, base + QA_B + o);
                Bf[2 * g][0] = r[0]; Bf[2 * g][1] = r[1];
                Bf[2 * g + 1][0] = r[2]; Bf[2 * g + 1][1] = r[3];
            }
            {
                int br = wn * 40 + 32 + (lane & 7);
                uint32_t o = tile_off(br, ks * 2 + ((lane >> 3) & 1));
                uint32_t r2[2];
                LDSM2(r2, base + QA_B + o);
                Bf[4][0] = r2[0]; Bf[4][1] = r2[1];
            }
#pragma unroll
            for (int mf = 0; mf < 4; mf++)
#pragma unroll
                for (int nf = 0; nf < 5; nf++) MMA16816(acc[mf][nf], Af[mf], Bf[nf]);
        }
    };

    issue_load(0, 0); CP_COMMIT();
    issue_load(1, 1); CP_COMMIT();
    CP_WAIT(1);
    __syncthreads();

    for (int c = 0; c < QNC; c++) {
        if (c + 2 < QNC) issue_load((c + 2) % STAGES, c + 2);
        CP_COMMIT();
        compute(c % STAGES);
        CP_WAIT(1);
        __syncthreads();
    }

    float* qf = g_Qf + (size_t)kslice * RT * 320;
#pragma unroll
    for (int mf = 0; mf < 4; mf++)
#pragma unroll
        for (int nf = 0; nf < 5; nf++)
#pragma unroll
            for (int qp = 0; qp < 2; qp++) {
                int m = mbase + mf * 16 + (lane >> 2) + qp * 8;
                if (m >= n_e) continue;
                int col = wn * 40 + nf * 8 + (lane & 3) * 2;
                size_t b = (size_t)(off + m) * 320 + col;
                qf[b]     = acc[mf][nf][qp * 2 + 0];
                qf[b + 1] = acc[mf][nf][qp * 2 + 1];
            }
}

// ---------------- launch ----------------
extern "C" void kernel_launch(void* const* d_in, const int* in_sizes, int n_in,
                              void* d_out, int out_size)
{
    const float* x    = (const float*)d_in[0];
    const float* gw   = (const float*)d_in[1];
    const float* w1u  = (const float*)d_in[2];
    const float* w1v  = (const float*)d_in[3];
    const float* w2u  = (const float*)d_in[4];
    const float* w2v  = (const float*)d_in[5];
    const float* w3u  = (const float*)d_in[6];
    const float* w3v  = (const float*)d_in[7];
    const float* u1   = (const float*)d_in[8];
    const float* v1   = (const float*)d_in[9];
    const float* u2   = (const float*)d_in[10];
    const float* v2   = (const float*)d_in[11];
    const float* u3   = (const float*)d_in[12];
    const float* v3   = (const float*)d_in[13];

    float* outp   = (float*)d_out;
    float* logits = outp + (size_t)Tt * Hd;

    static cudaStream_t s_pack = nullptr;
    static cudaEvent_t evStart, evBp, evBgu, evBq, evBo;
    if (!s_pack) {
        cudaStreamCreateWithFlags(&s_pack, cudaStreamNonBlocking);
        cudaEventCreateWithFlags(&evStart, cudaEventDisableTiming);
        cudaEventCreateWithFlags(&evBp,    cudaEventDisableTiming);
        cudaEventCreateWithFlags(&evBgu,   cudaEventDisableTiming);
        cudaEventCreateWithFlags(&evBq,    cudaEventDisableTiming);
        cudaEventCreateWithFlags(&evBo,    cudaEventDisableTiming);

        int smem_s2 = STAGES * 2 * TILE_B;        // 96KB (KIND0/3)
        int smem_gu = 2 * 2 * TILE_B + 32768;     // 96KB (KIND1)
        int smem_q  = STAGES * QST_B;             // 144KB
        cudaFuncSetAttribute(moe_mma<0>, cudaFuncAttributeMaxDynamicSharedMemorySize, smem_s2);
        cudaFuncSetAttribute(moe_mma<1>, cudaFuncAttributeMaxDynamicSharedMemorySize, smem_gu);
        cudaFuncSetAttribute(moe_mma<3>, cudaFuncAttributeMaxDynamicSharedMemorySize, smem_s2);
        cudaFuncSetAttribute(moe_mma_q,  cudaFuncAttributeMaxDynamicSharedMemorySize, smem_q);
        cudaFuncSetAttribute(router_kernel, cudaFuncAttributeMaxDynamicSharedMemorySize,
                             Ee * Hd * (int)sizeof(float));   // 128KB
    }
    int smem_s2 = STAGES * 2 * TILE_B;
    int smem_gu = 2 * 2 * TILE_B + 32768;
    int smem_q  = STAGES * QST_B;

    // fork: weight packing on side stream
    cudaEventRecord(evStart, 0);
    cudaStreamWaitEvent(s_pack, evStart, 0);

    k_conv_Bp<<<dim3(640, Ee), 256, 0, s_pack>>>(w1v, v1, w3v, v3);
    cudaEventRecord(evBp, s_pack);
    k_pack320<0><<<dim3(Id / 4, Ee), 320, 0, s_pack>>>(w1u, u1);
    k_pack320<1><<<dim3(Id / 4, Ee), 320, 0, s_pack>>>(w3u, u3);
    cudaEventRecord(evBgu, s_pack);
    k_conv_Bq<<<dim3(320, Ee), 256, 0, s_pack>>>(w2v, v2);
    cudaEventRecord(evBq, s_pack);
    k_pack320<2><<<dim3(Hd / 4, Ee), 320, 0, s_pack>>>(w2u, u2);
    cudaEventRecord(evBo, s_pack);

    // main stream: routing chain (router also produces g_xh)
    cudaMemsetAsync(outp, 0, (size_t)Tt * Hd * sizeof(float));
    prep_kernel<<<1, 32>>>();
    router_kernel<<<Tt / 8, 256, Ee * Hd * sizeof(float)>>>(x, gw, logits);
    route_kernel<<<Tt / 256, 256>>>(logits);
    offsets_kernel<<<1, 32>>>();

    cudaStreamWaitEvent(0, evBp, 0);
    moe_mma<0><<<dim3(32, 5, Ee),   256, smem_s2>>>(nullptr);   // P
    cudaStreamWaitEvent(0, evBgu, 0);
    moe_mma<1><<<dim3(32, 112, Ee), 256, smem_gu>>>(nullptr);   // gate/up -> h
    cudaStreamWaitEvent(0, evBq, 0);
    moe_mma_q<<<dim3(64, QSPLIT, Ee), 256, smem_q>>>();         // Q (N=320 exact)
    k_qsum<<<(RT * 320) / 256, 256>>>();
    cudaStreamWaitEvent(0, evBo, 0);
    moe_mma<3><<<dim3(32, 32, Ee),  256, smem_s2>>>(outp);      // scatter
}

// round 12
// speedup vs baseline: 7.9209x; 1.0426x over previous
#include <cuda_runtime.h>
#include <cuda_fp16.h>
#include <cstdint>
#include <math.h>

// ---------------- problem constants ----------------
#define Hd   4096
#define Id   14336
#define Rr   159
#define R2   318
#define Ee   8
#define Tt   4096
#define RT   8192          // total routed rows (Tt * topk)

#define STAGES  3
#define TILE_B  16384      // one 128x64 fp16 tile
#define QSPLIT  4
#define QNC     56         // 14336 / 64 / 4

// ---------------- scratch (device globals) ----------------
__device__ int   g_cnt[Ee];
__device__ int   g_off[Ee];
__device__ int   g_tok[Ee][Tt];
__device__ float g_wt[Ee][Tt];

__device__ __align__(16) __half g_xh[(size_t)Tt * Hd];
__device__ __align__(16) __half g_Bp[(size_t)Ee * 640 * Hd];      // rows: 0-317 gate(w1v,v1), 320-637 up(w3v,v3)
__device__ __align__(16) __half g_Bg[(size_t)Ee * Id * 320];      // [I,320] = w1u|u1|pad
__device__ __align__(16) __half g_Bu[(size_t)Ee * Id * 320];      // w3u|u3|pad
__device__ __align__(16) __half g_Bq[(size_t)Ee * 384 * Id];      // rows: w2v|v2 (only 320 used)
__device__ __align__(16) __half g_Bo[(size_t)Ee * Hd * 320];      // w2u|u2|pad
__device__ __align__(16) __half g_Ph[(size_t)RT * 640];           // hi only (A of gate/up)
__device__ __align__(16) __half g_hh[(size_t)RT * Id];            // hi only (A of Q)
__device__ float g_Qf[(size_t)QSPLIT * RT * 320];
__device__ __align__(16) __half g_Qh[(size_t)RT * 320];

// ---------------- PTX helpers ----------------
__device__ __forceinline__ uint32_t smem_to_u32(const void* p) {
    uint32_t a;
    asm("{ .reg .u64 t; cvta.to.shared.u64 t, %1; cvt.u32.u64 %0, t; }" : "=r"(a) : "l"(p));
    return a;
}
#define LDSM4(r, a)                                                               \
    asm volatile("ldmatrix.sync.aligned.m8n8.x4.shared.b16 {%0,%1,%2,%3}, [%4];"  \
        : "=r"((r)[0]), "=r"((r)[1]), "=r"((r)[2]), "=r"((r)[3]) : "r"(a))
#define LDSM2(r, a)                                                               \
    asm volatile("ldmatrix.sync.aligned.m8n8.x2.shared.b16 {%0,%1}, [%2];"        \
        : "=r"((r)[0]), "=r"((r)[1]) : "r"(a))
#define MMA16816(d, a, b)                                                         \
    asm volatile("mma.sync.aligned.m16n8k16.row.col.f32.f16.f16.f32 "             \
        "{%0,%1,%2,%3},{%4,%5,%6,%7},{%8,%9},{%0,%1,%2,%3};"                      \
        : "+f"((d)[0]), "+f"((d)[1]), "+f"((d)[2]), "+f"((d)[3])                  \
        : "r"((a)[0]), "r"((a)[1]), "r"((a)[2]), "r"((a)[3]),                     \
          "r"((b)[0]), "r"((b)[1]))
#define CP16(dst, src, sz)                                                        \
    asm volatile("cp.async.cg.shared.global [%0], [%1], 16, %2;"                  \
        :: "r"(dst), "l"(src), "r"(sz))
#define CP_COMMIT() asm volatile("cp.async.commit_group;" ::: "memory")
#define CP_WAIT(n)  asm volatile("cp.async.wait_group %0;" :: "n"(n) : "memory")

__device__ __forceinline__ uint32_t tile_off(int row, int chunk) {
    return (uint32_t)(row * 128 + ((chunk ^ (row & 7)) << 4));
}

// ---------------- conversion / packing kernels ----------------
__global__ __launch_bounds__(256) void k_conv_Bp(
    const float* __restrict__ w1v, const float* __restrict__ v1,
    const float* __restrict__ w3v, const float* __restrict__ v3)
{
    int j = blockIdx.x, e = blockIdx.y;
    const float* src = nullptr;
    if      (j < Rr)            src = w1v + ((size_t)e * Rr + j) * Hd;
    else if (j < R2)            src = v1  + ((size_t)e * Rr + j - Rr) * Hd;
    else if (j >= 320 && j < 320 + Rr) src = w3v + ((size_t)e * Rr + j - 320) * Hd;
    else if (j >= 320 + Rr && j < 320 + R2) src = v3 + ((size_t)e * Rr + j - 320 - Rr) * Hd;
    __half2* dst = (__half2*)(g_Bp + ((size_t)e * 640 + j) * Hd);
    for (int i = threadIdx.x; i < Hd / 2; i += 256) {
        float2 v = src ? ((const float2*)src)[i] : make_float2(0.f, 0.f);
        dst[i] = __floats2half2_rn(v.x, v.y);
    }
}

template <int SEL>  // 0: Bg(w1u,u1,I)  1: Bu(w3u,u3,I)  2: Bo(w2u,u2,H)
__global__ __launch_bounds__(320) void k_pack320(
    const float* __restrict__ W, const float* __restrict__ U)
{
    constexpr int ROWS = (SEL == 2) ? Hd : Id;
    __half* D = (SEL == 0) ? g_Bg : (SEL == 1) ? g_Bu : g_Bo;
    int e = blockIdx.y;
    int r = blockIdx.x * 4 + (threadIdx.x / 80);
    int c4 = (threadIdx.x % 80) * 4;
    const float* w = W + ((size_t)e * ROWS + r) * Rr;
    const float* u = U + ((size_t)e * ROWS + r) * Rr;
    float v[4];
#pragma unroll
    for (int j = 0; j < 4; j++) {
        int k = c4 + j;
        v[j] = (k < Rr) ? w[k] : ((k < R2) ? u[k - Rr] : 0.f);
    }
    __half2 h0 = __floats2half2_rn(v[0], v[1]);
    __half2 h1 = __floats2half2_rn(v[2], v[3]);
    uint2 pk = make_uint2(*(uint32_t*)&h0, *(uint32_t*)&h1);
    *(uint2*)(D + ((size_t)e * ROWS + r) * 320 + c4) = pk;
}

__global__ __launch_bounds__(256) void k_conv_Bq(
    const float* __restrict__ w2v, const float* __restrict__ v2)
{
    int j = blockIdx.x, e = blockIdx.y;   // j in [0,320)
    const float* src = nullptr;
    if      (j < Rr) src = w2v + ((size_t)e * Rr + j) * Id;
    else if (j < R2) src = v2  + ((size_t)e * Rr + j - Rr) * Id;
    __half2* dst = (__half2*)(g_Bq + ((size_t)e * 384 + j) * Id);
    for (int i = threadIdx.x; i < Id / 2; i += 256) {
        float2 v = src ? ((const float2*)src)[i] : make_float2(0.f, 0.f);
        dst[i] = __floats2half2_rn(v.x, v.y);
    }
}

__global__ __launch_bounds__(256) void k_qsum() {
    size_t i = (size_t)blockIdx.x * 256 + threadIdx.x;   // grid covers RT*320
    constexpr size_t S = (size_t)RT * 320;
    float s = g_Qf[i] + g_Qf[i + S] + g_Qf[i + 2 * S] + g_Qf[i + 3 * S];
    g_Qh[i] = __float2half_rn(s);
}

// ---------------- router (fused: logits fp32 + x -> fp16) ----------------
__device__ __forceinline__ float warpsum(float v) {
#pragma unroll
    for (int o = 16; o; o >>= 1) v += __shfl_down_sync(0xffffffffu, v, o);
    return v;
}

__global__ __launch_bounds__(256) void router_kernel(
    const float* __restrict__ x, const float* __restrict__ gw, float* __restrict__ logits)
{
    extern __shared__ float sgw[];   // [Ee * Hd] = 128KB
    int tid = threadIdx.x;
    for (int i = tid; i < Ee * Hd / 4; i += 256)
        ((float4*)sgw)[i] = ((const float4*)gw)[i];
    __syncthreads();

    int lane = tid & 31, grp = tid >> 5;
    int t = blockIdx.x * 8 + grp;
    const float4* xr = (const float4*)(x + (size_t)t * Hd);
    __half2* dh = (__half2*)(g_xh + (size_t)t * Hd);

    float acc[Ee];
#pragma unroll
    for (int e = 0; e < Ee; e++) acc[e] = 0.f;

    for (int it = 0; it < Hd / 4 / 32; it++) {
        int i = lane + it * 32;
        float4 xv = xr[i];
        dh[2 * i]     = __floats2half2_rn(xv.x, xv.y);
        dh[2 * i + 1] = __floats2half2_rn(xv.z, xv.w);
#pragma unroll
        for (int e = 0; e < Ee; e++) {
            float4 wv = ((const float4*)(sgw + (size_t)e * Hd))[i];
            acc[e] = fmaf(xv.x, wv.x, fmaf(xv.y, wv.y, fmaf(xv.z, wv.z, fmaf(xv.w, wv.w, acc[e]))));
        }
    }
#pragma unroll
    for (int e = 0; e < Ee; e++) {
        float s = warpsum(acc[e]);
        if (lane == 0) logits[(size_t)t * Ee + e] = s;
    }
}

__global__ void prep_kernel() { if (threadIdx.x < Ee) g_cnt[threadIdx.x] = 0; }

__global__ void route_kernel(const float* __restrict__ logits)
{
    int t = blockIdx.x * blockDim.x + threadIdx.x;
    if (t >= Tt) return;
    float l[Ee];
#pragma unroll
    for (int e = 0; e < Ee; e++) l[e] = logits[(size_t)t * Ee + e];
    int i1 = 0; float m1 = l[0];
#pragma unroll
    for (int e = 1; e < Ee; e++) if (l[e] > m1) { m1 = l[e]; i1 = e; }
    int i2 = -1; float m2 = -1e30f;
#pragma unroll
    for (int e = 0; e < Ee; e++) if (e != i1 && l[e] > m2) { m2 = l[e]; i2 = e; }
    float w1 = 1.f / (1.f + expf(m2 - m1));
    float w2 = 1.f - w1;
    int p = atomicAdd(&g_cnt[i1], 1); g_tok[i1][p] = t; g_wt[i1][p] = w1;
    p     = atomicAdd(&g_cnt[i2], 1); g_tok[i2][p] = t; g_wt[i2][p] = w2;
}

__global__ void offsets_kernel()
{
    if (threadIdx.x == 0) {
        int s = 0;
        for (int e = 0; e < Ee; e++) { g_off[e] = s; s += g_cnt[e]; }
    }
}

// ---------------- fp16 HMMA GEMM (128-M tile family, single-A) ----------------
// KIND 0: P = gather(xh) @ Bp^T       K=4096 NC=64  N=640(5)    3-stage
// KIND 1: h = silu(P@Bg^T)*(P@Bu^T)   fused NC=10 (gate 0-4, up 5-9), 2-stage + stash
// KIND 3: out += wt * (Q @ Bo^T)      K=320 NC=5    N=4096(32)  3-stage
template <int KIND>
__global__ __launch_bounds__(256, 2) void moe_mma(float* __restrict__ outp)
{
    constexpr int NSTAGE = (KIND == 1) ? 2 : STAGES;
    constexpr int STAGE_B = 2 * TILE_B;
    constexpr int NCc   = (KIND == 0) ? 64 : (KIND == 1) ? 10 : 5;
    constexpr int Kb    = (KIND == 0) ? Hd : 320;
    constexpr int Brows = (KIND == 0) ? 640 : (KIND == 1) ? Id : Hd;

    int e     = blockIdx.z;
    int n_e   = g_cnt[e];
    int mbase = blockIdx.x * 128;
    if (mbase >= n_e) return;
    int nbase = blockIdx.y * 128;
    int off   = g_off[e];

    extern __shared__ char smem[];
    uint32_t smem_u32 = smem_to_u32(smem);
    __half2* sg2 = (__half2*)(smem + NSTAGE * STAGE_B);   // KIND1 silu stash (32KB, per-thread)

    int tid = threadIdx.x, lane = tid & 31, wid = tid >> 5;
    int wm = wid & 1, wn = wid >> 1;
    int row = tid >> 1, half = tid & 1;
    int ml = mbase + row;
    unsigned szA = (ml < n_e) ? 16u : 0u;

    const __half* Ah_row;
    if (KIND == 0) {
        int t = (ml < n_e) ? g_tok[e][ml] : 0;
        Ah_row = g_xh + (size_t)t * Hd;
    } else {
        size_t r = (size_t)off + ((ml < n_e) ? ml : 0);
        Ah_row = (KIND == 1) ? (g_Ph + r * 640) : (g_Qh + r * 320);
    }

    // B row bases
    const __half *BrowG = nullptr, *BrowU = nullptr, *Brow = nullptr;
    if (KIND == 1) {
        size_t ro = ((size_t)e * Brows + nbase + row) * 320;
        BrowG = g_Bg + ro;
        BrowU = g_Bu + ro;
    } else {
        const __half* Bm = (KIND == 0) ? g_Bp : g_Bo;
        Brow = Bm + ((size_t)e * Brows + nbase + row) * Kb;
    }

    float acc[4][4][4];
#pragma unroll
    for (int i = 0; i < 4; i++)
#pragma unroll
        for (int j = 0; j < 4; j++)
#pragma unroll
            for (int q = 0; q < 4; q++) acc[i][j][q] = 0.f;

    auto issue_load = [&](int st, int c) {
        uint32_t sb = smem_u32 + st * STAGE_B;
        int acol = c * 64 + half * 32;
        const __half* bsrc;
        int bcol;
        if (KIND == 1) {
            bsrc = (c < 5) ? BrowG : BrowU;
            bcol = (c % 5) * 64 + half * 32;
        } else {
            bsrc = Brow;
            bcol = acol;
        }
#pragma unroll
        for (int i = 0; i < 4; i++) {
            uint32_t so = tile_off(row, half * 4 + i);
            CP16(sb + so, Ah_row + acol + i * 8, szA);
            CP16(sb + TILE_B + so, bsrc + bcol + i * 8, 16u);
        }
    };

    auto compute = [&](int st) {
        uint32_t base = smem_u32 + st * STAGE_B;
#pragma unroll
        for (int ks = 0; ks < 4; ks++) {
            uint32_t Ahf[4][4], Bf[4][2];
#pragma unroll
            for (int mf = 0; mf < 4; mf++) {
                int ar = wm * 64 + mf * 16 + (lane & 15);
                LDSM4(Ahf[mf], base + tile_off(ar, ks * 2 + (lane >> 4)));
            }
#pragma unroll
            for (int g = 0; g < 2; g++) {
                int br = wn * 32 + g * 16 + ((lane >> 4) << 3) + (lane & 7);
                uint32_t o = tile_off(br, ks * 2 + ((lane >> 3) & 1));
                uint32_t r[4];
                LDSM4(r, base + TILE_B + o);
                Bf[2 * g][0] = r[0]; Bf[2 * g][1] = r[1];
                Bf[2 * g + 1][0] = r[2]; Bf[2 * g + 1][1] = r[3];
            }
#pragma unroll
            for (int mf = 0; mf < 4; mf++)
#pragma unroll
                for (int nf = 0; nf < 4; nf++) MMA16816(acc[mf][nf], Ahf[mf], Bf[nf]);
        }
    };

    auto stash_silu = [&]() {
#pragma unroll
        for (int mf = 0; mf < 4; mf++)
#pragma unroll
            for (int nf = 0; nf < 4; nf++)
#pragma unroll
                for (int qp = 0; qp < 2; qp++) {
                    float g0 = acc[mf][nf][qp * 2 + 0];
                    float g1 = acc[mf][nf][qp * 2 + 1];
                    g0 = g0 / (1.f + __expf(-g0));
                    g1 = g1 / (1.f + __expf(-g1));
                    sg2[((mf * 4 + nf) * 2 + qp) * 256 + tid] = __floats2half2_rn(g0, g1);
                    acc[mf][nf][qp * 2 + 0] = 0.f;
                    acc[mf][nf][qp * 2 + 1] = 0.f;
                }
    };

    if (NSTAGE == 3) {
        issue_load(0, 0); CP_COMMIT();
        if (NCc > 1) issue_load(1, 1);
        CP_COMMIT();
        CP_WAIT(1);
        __syncthreads();
        for (int c = 0; c < NCc; c++) {
            if (c + 2 < NCc) issue_load((c + 2) % 3, c + 2);
            CP_COMMIT();
            compute(c % 3);
            CP_WAIT(1);
            __syncthreads();
        }
    } else {
        // fused 2-stage (KIND1): gate chunks 0-4, up chunks 5-9
        issue_load(0, 0); CP_COMMIT();
        CP_WAIT(0);
        __syncthreads();
        for (int c = 0; c < NCc; c++) {
            if (c + 1 < NCc) { issue_load((c + 1) & 1, c + 1); CP_COMMIT(); }
            compute(c & 1);
            if (KIND == 1 && c == 4) stash_silu();   // per-thread smem, no sync needed
            if (c + 1 < NCc) { CP_WAIT(0); __syncthreads(); }
        }
    }

    // epilogue
#pragma unroll
    for (int mf = 0; mf < 4; mf++)
#pragma unroll
        for (int nf = 0; nf < 4; nf++)
#pragma unroll
            for (int qp = 0; qp < 2; qp++) {
                int r = wm * 64 + mf * 16 + (lane >> 2) + qp * 8;
                int m = mbase + r;
                if (m >= n_e) continue;
                int col = nbase + wn * 32 + nf * 8 + (lane & 3) * 2;
                float v0 = acc[mf][nf][qp * 2 + 0];
                float v1 = acc[mf][nf][qp * 2 + 1];
                if (KIND == 0) {
                    size_t b = (size_t)(off + m) * 640 + col;
                    *(__half2*)(g_Ph + b) = __floats2half2_rn(v0, v1);
                } else if (KIND == 1) {
                    float2 sf = __half22float2(sg2[((mf * 4 + nf) * 2 + qp) * 256 + tid]);
                    v0 *= sf.x;
                    v1 *= sf.y;
                    size_t b = (size_t)(off + m) * Id + col;
                    *(__half2*)(g_hh + b) = __floats2half2_rn(v0, v1);
                } else {
                    float wt  = g_wt[e][m];
                    int   tok = g_tok[e][m];
                    float* dst = outp + (size_t)tok * Hd + col;
                    atomicAdd(dst, wt * v0);
                    atomicAdd(dst + 1, wt * v1);
                }
            }
}

// ---------------- Q GEMM: M=64 x N=160, 4 K-slices, 3-stage, 2 CTAs/SM ----------------
#define QA_B 8192
#define QB_B 20480
#define QST_B (QA_B + QB_B)   // 28672
#define QCHUNKS 1792          // (64 + 160) rows * 8 chunks
__global__ __launch_bounds__(256, 2) void moe_mma_q()
{
    int e     = blockIdx.z;
    int n_e   = g_cnt[e];
    int mbase = blockIdx.x * 64;
    if (mbase >= n_e) return;
    int nhalf  = blockIdx.y & 1;
    int kslice = blockIdx.y >> 1;
    int cbase  = kslice * QNC;
    int off    = g_off[e];

    extern __shared__ char smem[];
    uint32_t smem_u32 = smem_to_u32(smem);

    int tid = threadIdx.x, lane = tid & 31, wid = tid >> 5;
    int wm = wid >> 2, wn = wid & 3;   // 2M x 4N warps

    float acc[2][5][4];
#pragma unroll
    for (int i = 0; i < 2; i++)
#pragma unroll
        for (int j = 0; j < 5; j++)
#pragma unroll
            for (int q = 0; q < 4; q++) acc[i][j][q] = 0.f;

    const __half* Bq_e = g_Bq + (size_t)e * 384 * Id + (size_t)(nhalf * 160) * Id;

    auto issue_load = [&](int st, int c) {
        uint32_t sb = smem_u32 + st * QST_B;
        int col = (cbase + c) * 64;
#pragma unroll
        for (int i = 0; i < 7; i++) {
            int ci = tid + i * 256;
            if (ci < 512) {
                int row = ci >> 3, ch = ci & 7;
                int m = mbase + row;
                unsigned sz = (m < n_e) ? 16u : 0u;
                const __half* src = g_hh + ((size_t)off + ((m < n_e) ? m : 0)) * Id + col + ch * 8;
                CP16(sb + tile_off(row, ch), src, sz);
            } else {
                int bi = ci - 512;   // < 1280
                int row = bi >> 3, ch = bi & 7;
                const __half* src = Bq_e + (size_t)row * Id + col + ch * 8;
                CP16(sb + QA_B + tile_off(row, ch), src, 16u);
            }
        }
    };

    auto compute = [&](int st) {
        uint32_t base = smem_u32 + st * QST_B;
#pragma unroll
        for (int ks = 0; ks < 4; ks++) {
            uint32_t Af[2][4], Bf[5][2];
#pragma unroll
            for (int mf = 0; mf < 2; mf++) {
                int ar = wm * 32 + mf * 16 + (lane & 15);
                LDSM4(Af[mf], base + tile_off(ar, ks * 2 + (lane >> 4)));
            }
#pragma unroll
            for (int g = 0; g < 2; g++) {
                int br = wn * 40 + g * 16 + ((lane >> 4) << 3) + (lane & 7);
                uint32_t o = tile_off(br, ks * 2 + ((lane >> 3) & 1));
                uint32_t r[4];
                LDSM4(r, base + QA_B + o);
                Bf[2 * g][0] = r[0]; Bf[2 * g][1] = r[1];
                Bf[2 * g + 1][0] = r[2]; Bf[2 * g + 1][1] = r[3];
            }
            {
                int br = wn * 40 + 32 + (lane & 7);
                uint32_t o = tile_off(br, ks * 2 + ((lane >> 3) & 1));
                uint32_t r2[2];
                LDSM2(r2, base + QA_B + o);
                Bf[4][0] = r2[0]; Bf[4][1] = r2[1];
            }
#pragma unroll
            for (int mf = 0; mf < 2; mf++)
#pragma unroll
                for (int nf = 0; nf < 5; nf++) MMA16816(acc[mf][nf], Af[mf], Bf[nf]);
        }
    };

    issue_load(0, 0); CP_COMMIT();
    issue_load(1, 1); CP_COMMIT();
    CP_WAIT(1);
    __syncthreads();

    for (int c = 0; c < QNC; c++) {
        if (c + 2 < QNC) issue_load((c + 2) % 3, c + 2);
        CP_COMMIT();
        compute(c % 3);
        CP_WAIT(1);
        __syncthreads();
    }

    float* qf = g_Qf + (size_t)kslice * RT * 320;
#pragma unroll
    for (int mf = 0; mf < 2; mf++)
#pragma unroll
        for (int nf = 0; nf < 5; nf++)
#pragma unroll
            for (int qp = 0; qp < 2; qp++) {
                int m = mbase + wm * 32 + mf * 16 + (lane >> 2) + qp * 8;
                if (m >= n_e) continue;
                int col = nhalf * 160 + wn * 40 + nf * 8 + (lane & 3) * 2;
                size_t b = (size_t)(off + m) * 320 + col;
                qf[b]     = acc[mf][nf][qp * 2 + 0];
                qf[b + 1] = acc[mf][nf][qp * 2 + 1];
            }
}

// ---------------- launch ----------------
extern "C" void kernel_launch(void* const* d_in, const int* in_sizes, int n_in,
                              void* d_out, int out_size)
{
    const float* x    = (const float*)d_in[0];
    const float* gw   = (const float*)d_in[1];
    const float* w1u  = (const float*)d_in[2];
    const float* w1v  = (const float*)d_in[3];
    const float* w2u  = (const float*)d_in[4];
    const float* w2v  = (const float*)d_in[5];
    const float* w3u  = (const float*)d_in[6];
    const float* w3v  = (const float*)d_in[7];
    const float* u1   = (const float*)d_in[8];
    const float* v1   = (const float*)d_in[9];
    const float* u2   = (const float*)d_in[10];
    const float* v2   = (const float*)d_in[11];
    const float* u3   = (const float*)d_in[12];
    const float* v3   = (const float*)d_in[13];

    float* outp   = (float*)d_out;
    float* logits = outp + (size_t)Tt * Hd;

    static cudaStream_t s_pack = nullptr;
    static cudaEvent_t evStart, evBp, evBgu, evBq, evBo;
    if (!s_pack) {
        cudaStreamCreateWithFlags(&s_pack, cudaStreamNonBlocking);
        cudaEventCreateWithFlags(&evStart, cudaEventDisableTiming);
        cudaEventCreateWithFlags(&evBp,    cudaEventDisableTiming);
        cudaEventCreateWithFlags(&evBgu,   cudaEventDisableTiming);
        cudaEventCreateWithFlags(&evBq,    cudaEventDisableTiming);
        cudaEventCreateWithFlags(&evBo,    cudaEventDisableTiming);

        int smem_s2 = STAGES * 2 * TILE_B;        // 96KB (KIND0/3)
        int smem_gu = 2 * 2 * TILE_B + 32768;     // 96KB (KIND1)
        int smem_q  = 3 * QST_B;                  // 84KB
        cudaFuncSetAttribute(moe_mma<0>, cudaFuncAttributeMaxDynamicSharedMemorySize, smem_s2);
        cudaFuncSetAttribute(moe_mma<1>, cudaFuncAttributeMaxDynamicSharedMemorySize, smem_gu);
        cudaFuncSetAttribute(moe_mma<3>, cudaFuncAttributeMaxDynamicSharedMemorySize, smem_s2);
        cudaFuncSetAttribute(moe_mma_q,  cudaFuncAttributeMaxDynamicSharedMemorySize, smem_q);
        cudaFuncSetAttribute(router_kernel, cudaFuncAttributeMaxDynamicSharedMemorySize,
                             Ee * Hd * (int)sizeof(float));   // 128KB
    }
    int smem_s2 = STAGES * 2 * TILE_B;
    int smem_gu = 2 * 2 * TILE_B + 32768;
    int smem_q  = 3 * QST_B;

    // fork: weight packing on side stream
    cudaEventRecord(evStart, 0);
    cudaStreamWaitEvent(s_pack, evStart, 0);

    k_conv_Bp<<<dim3(640, Ee), 256, 0, s_pack>>>(w1v, v1, w3v, v3);
    cudaEventRecord(evBp, s_pack);
    k_pack320<0><<<dim3(Id / 4, Ee), 320, 0, s_pack>>>(w1u, u1);
    k_pack320<1><<<dim3(Id / 4, Ee), 320, 0, s_pack>>>(w3u, u3);
    cudaEventRecord(evBgu, s_pack);
    k_conv_Bq<<<dim3(320, Ee), 256, 0, s_pack>>>(w2v, v2);
    cudaEventRecord(evBq, s_pack);
    k_pack320<2><<<dim3(Hd / 4, Ee), 320, 0, s_pack>>>(w2u, u2);
    cudaEventRecord(evBo, s_pack);

    // main stream: routing chain (router also produces g_xh)
    cudaMemsetAsync(outp, 0, (size_t)Tt * Hd * sizeof(float));
    prep_kernel<<<1, 32>>>();
    router_kernel<<<Tt / 8, 256, Ee * Hd * sizeof(float)>>>(x, gw, logits);
    route_kernel<<<Tt / 256, 256>>>(logits);
    offsets_kernel<<<1, 32>>>();

    cudaStreamWaitEvent(0, evBp, 0);
    moe_mma<0><<<dim3(32, 5, Ee),   256, smem_s2>>>(nullptr);   // P
    cudaStreamWaitEvent(0, evBgu, 0);
    moe_mma<1><<<dim3(32, 112, Ee), 256, smem_gu>>>(nullptr);   // fused gate/up -> h
    cudaStreamWaitEvent(0, evBq, 0);
    moe_mma_q<<<dim3(64, 2 * QSPLIT, Ee), 256, smem_q>>>();     // Q (occ 2)
    k_qsum<<<(RT * 320) / 256, 256>>>();
    cudaStreamWaitEvent(0, evBo, 0);
    moe_mma<3><<<dim3(32, 32, Ee),  256, smem_s2>>>(outp);      // scatter
}

// round 14
// speedup vs baseline: 8.2600x; 1.0428x over previous
#include <cuda_runtime.h>
#include <cuda_fp16.h>
#include <cstdint>
#include <math.h>

// ---------------- problem constants ----------------
#define Hd   4096
#define Id   14336
#define Rr   159
#define R2   318
#define Ee   8
#define Tt   4096
#define RT   8192          // total routed rows (Tt * topk)

#define STAGES  3
#define TILE_B  16384      // one 128x64 fp16 tile
#define QSPLIT  4
#define QNC     56         // 14336 / 64 / 4

// ---------------- scratch (device globals) ----------------
__device__ int   g_cnt[Ee];
__device__ int   g_off[Ee];
__device__ int   g_tok[Ee][Tt];
__device__ float g_wt[Ee][Tt];

__device__ __align__(16) __half g_xh[(size_t)Tt * Hd];
__device__ __align__(16) __half g_Bp[(size_t)Ee * 640 * Hd];      // rows: 0-317 gate(w1v,v1), 320-637 up(w3v,v3)
__device__ __align__(16) __half g_Bg[(size_t)Ee * Id * 320];      // [I,320] = w1u|u1|pad
__device__ __align__(16) __half g_Bu[(size_t)Ee * Id * 320];      // w3u|u3|pad
__device__ __align__(16) __half g_Bq[(size_t)Ee * 384 * Id];      // rows: w2v|v2 (only 320 used)
__device__ __align__(16) __half g_Bo[(size_t)Ee * Hd * 320];      // w2u|u2|pad
__device__ __align__(16) __half g_Ph[(size_t)RT * 640];           // hi only (A of gate/up)
__device__ __align__(16) __half g_hh[(size_t)RT * Id];            // hi only (A of Q)
__device__ float g_Qf[(size_t)QSPLIT * RT * 320];
__device__ __align__(16) __half g_Qh[(size_t)RT * 320];

// ---------------- PTX helpers ----------------
__device__ __forceinline__ uint32_t smem_to_u32(const void* p) {
    uint32_t a;
    asm("{ .reg .u64 t; cvta.to.shared.u64 t, %1; cvt.u32.u64 %0, t; }" : "=r"(a) : "l"(p));
    return a;
}
#define LDSM4(r, a)                                                               \
    asm volatile("ldmatrix.sync.aligned.m8n8.x4.shared.b16 {%0,%1,%2,%3}, [%4];"  \
        : "=r"((r)[0]), "=r"((r)[1]), "=r"((r)[2]), "=r"((r)[3]) : "r"(a))
#define LDSM2(r, a)                                                               \
    asm volatile("ldmatrix.sync.aligned.m8n8.x2.shared.b16 {%0,%1}, [%2];"        \
        : "=r"((r)[0]), "=r"((r)[1]) : "r"(a))
#define MMA16816(d, a, b)                                                         \
    asm volatile("mma.sync.aligned.m16n8k16.row.col.f32.f16.f16.f32 "             \
        "{%0,%1,%2,%3},{%4,%5,%6,%7},{%8,%9},{%0,%1,%2,%3};"                      \
        : "+f"((d)[0]), "+f"((d)[1]), "+f"((d)[2]), "+f"((d)[3])                  \
        : "r"((a)[0]), "r"((a)[1]), "r"((a)[2]), "r"((a)[3]),                     \
          "r"((b)[0]), "r"((b)[1]))
#define CP16(dst, src, sz)                                                        \
    asm volatile("cp.async.cg.shared.global [%0], [%1], 16, %2;"                  \
        :: "r"(dst), "l"(src), "r"(sz))
#define CP_COMMIT() asm volatile("cp.async.commit_group;" ::: "memory")
#define CP_WAIT(n)  asm volatile("cp.async.wait_group %0;" :: "n"(n) : "memory")

__device__ __forceinline__ uint32_t tile_off(int row, int chunk) {
    return (uint32_t)(row * 128 + ((chunk ^ (row & 7)) << 4));
}

// ---------------- conversion / packing kernels ----------------
__global__ __launch_bounds__(256) void k_conv_Bp(
    const float* __restrict__ w1v, const float* __restrict__ v1,
    const float* __restrict__ w3v, const float* __restrict__ v3)
{
    int j = blockIdx.x, e = blockIdx.y;
    const float* src = nullptr;
    if      (j < Rr)            src = w1v + ((size_t)e * Rr + j) * Hd;
    else if (j < R2)            src = v1  + ((size_t)e * Rr + j - Rr) * Hd;
    else if (j >= 320 && j < 320 + Rr) src = w3v + ((size_t)e * Rr + j - 320) * Hd;
    else if (j >= 320 + Rr && j < 320 + R2) src = v3 + ((size_t)e * Rr + j - 320 - Rr) * Hd;
    __half2* dst = (__half2*)(g_Bp + ((size_t)e * 640 + j) * Hd);
    for (int i = threadIdx.x; i < Hd / 2; i += 256) {
        float2 v = src ? ((const float2*)src)[i] : make_float2(0.f, 0.f);
        dst[i] = __floats2half2_rn(v.x, v.y);
    }
}

template <int SEL>  // 0: Bg(w1u,u1,I)  1: Bu(w3u,u3,I)  2: Bo(w2u,u2,H)
__global__ __launch_bounds__(320) void k_pack320(
    const float* __restrict__ W, const float* __restrict__ U)
{
    constexpr int ROWS = (SEL == 2) ? Hd : Id;
    __half* D = (SEL == 0) ? g_Bg : (SEL == 1) ? g_Bu : g_Bo;
    int e = blockIdx.y;
    int r = blockIdx.x * 4 + (threadIdx.x / 80);
    int c4 = (threadIdx.x % 80) * 4;
    const float* w = W + ((size_t)e * ROWS + r) * Rr;
    const float* u = U + ((size_t)e * ROWS + r) * Rr;
    float v[4];
#pragma unroll
    for (int j = 0; j < 4; j++) {
        int k = c4 + j;
        v[j] = (k < Rr) ? w[k] : ((k < R2) ? u[k - Rr] : 0.f);
    }
    __half2 h0 = __floats2half2_rn(v[0], v[1]);
    __half2 h1 = __floats2half2_rn(v[2], v[3]);
    uint2 pk = make_uint2(*(uint32_t*)&h0, *(uint32_t*)&h1);
    *(uint2*)(D + ((size_t)e * ROWS + r) * 320 + c4) = pk;
}

__global__ __launch_bounds__(256) void k_conv_Bq(
    const float* __restrict__ w2v, const float* __restrict__ v2)
{
    int j = blockIdx.x, e = blockIdx.y;   // j in [0,320)
    const float* src = nullptr;
    if      (j < Rr) src = w2v + ((size_t)e * Rr + j) * Id;
    else if (j < R2) src = v2  + ((size_t)e * Rr + j - Rr) * Id;
    __half2* dst = (__half2*)(g_Bq + ((size_t)e * 384 + j) * Id);
    for (int i = threadIdx.x; i < Id / 2; i += 256) {
        float2 v = src ? ((const float2*)src)[i] : make_float2(0.f, 0.f);
        dst[i] = __floats2half2_rn(v.x, v.y);
    }
}

// per-group qsum: rows [off[e0], end)
__global__ __launch_bounds__(256) void k_qsum_g(int e0) {
    int start = g_off[e0];
    int end   = (e0 + 4 < Ee) ? g_off[e0 + 4] : RT;
    int idx = blockIdx.x * 256 + threadIdx.x;
    int row = idx / 320;
    if (row >= end - start) return;
    size_t i = (size_t)(start + row) * 320 + (idx % 320);
    constexpr size_t S = (size_t)RT * 320;
    float s = g_Qf[i] + g_Qf[i + S] + g_Qf[i + 2 * S] + g_Qf[i + 3 * S];
    g_Qh[i] = __float2half_rn(s);
}

// ---------------- router (fused: logits fp32 + x -> fp16) ----------------
__device__ __forceinline__ float warpsum(float v) {
#pragma unroll
    for (int o = 16; o; o >>= 1) v += __shfl_down_sync(0xffffffffu, v, o);
    return v;
}

__global__ __launch_bounds__(256) void router_kernel(
    const float* __restrict__ x, const float* __restrict__ gw, float* __restrict__ logits)
{
    extern __shared__ float sgw[];   // [Ee * Hd] = 128KB
    int tid = threadIdx.x;
    for (int i = tid; i < Ee * Hd / 4; i += 256)
        ((float4*)sgw)[i] = ((const float4*)gw)[i];
    __syncthreads();

    int lane = tid & 31, grp = tid >> 5;
    int t = blockIdx.x * 8 + grp;
    const float4* xr = (const float4*)(x + (size_t)t * Hd);
    __half2* dh = (__half2*)(g_xh + (size_t)t * Hd);

    float acc[Ee];
#pragma unroll
    for (int e = 0; e < Ee; e++) acc[e] = 0.f;

    for (int it = 0; it < Hd / 4 / 32; it++) {
        int i = lane + it * 32;
        float4 xv = xr[i];
        dh[2 * i]     = __floats2half2_rn(xv.x, xv.y);
        dh[2 * i + 1] = __floats2half2_rn(xv.z, xv.w);
#pragma unroll
        for (int e = 0; e < Ee; e++) {
            float4 wv = ((const float4*)(sgw + (size_t)e * Hd))[i];
            acc[e] = fmaf(xv.x, wv.x, fmaf(xv.y, wv.y, fmaf(xv.z, wv.z, fmaf(xv.w, wv.w, acc[e]))));
        }
    }
#pragma unroll
    for (int e = 0; e < Ee; e++) {
        float s = warpsum(acc[e]);
        if (lane == 0) logits[(size_t)t * Ee + e] = s;
    }
}

__global__ void prep_kernel() { if (threadIdx.x < Ee) g_cnt[threadIdx.x] = 0; }

__global__ void route_kernel(const float* __restrict__ logits)
{
    int t = blockIdx.x * blockDim.x + threadIdx.x;
    if (t >= Tt) return;
    float l[Ee];
#pragma unroll
    for (int e = 0; e < Ee; e++) l[e] = logits[(size_t)t * Ee + e];
    int i1 = 0; float m1 = l[0];
#pragma unroll
    for (int e = 1; e < Ee; e++) if (l[e] > m1) { m1 = l[e]; i1 = e; }
    int i2 = -1; float m2 = -1e30f;
#pragma unroll
    for (int e = 0; e < Ee; e++) if (e != i1 && l[e] > m2) { m2 = l[e]; i2 = e; }
    float w1 = 1.f / (1.f + expf(m2 - m1));
    float w2 = 1.f - w1;
    int p = atomicAdd(&g_cnt[i1], 1); g_tok[i1][p] = t; g_wt[i1][p] = w1;
    p     = atomicAdd(&g_cnt[i2], 1); g_tok[i2][p] = t; g_wt[i2][p] = w2;
}

__global__ void offsets_kernel()
{
    if (threadIdx.x == 0) {
        int s = 0;
        for (int e = 0; e < Ee; e++) { g_off[e] = s; s += g_cnt[e]; }
    }
}

// ---------------- fp16 HMMA GEMM (128-M tile family, single-A), expert-group ----------------
// KIND 0: P = gather(xh) @ Bp^T       K=4096 NC=64  N=640(5)    3-stage
// KIND 1: h = silu(P@Bg^T)*(P@Bu^T)   fused NC=10 (gate 0-4, up 5-9), 2-stage + stash
// KIND 3: out += wt * (Q @ Bo^T)      K=320 NC=5    N=4096(32)  3-stage
template <int KIND>
__global__ __launch_bounds__(256, 2) void moe_mma(float* __restrict__ outp, int ebase)
{
    constexpr int NSTAGE = (KIND == 1) ? 2 : STAGES;
    constexpr int STAGE_B = 2 * TILE_B;
    constexpr int NCc   = (KIND == 0) ? 64 : (KIND == 1) ? 10 : 5;
    constexpr int Kb    = (KIND == 0) ? Hd : 320;
    constexpr int Brows = (KIND == 0) ? 640 : (KIND == 1) ? Id : Hd;

    int e     = ebase + blockIdx.z;
    int n_e   = g_cnt[e];
    int mbase = blockIdx.x * 128;
    if (mbase >= n_e) return;
    int nbase = blockIdx.y * 128;
    int off   = g_off[e];

    extern __shared__ char smem[];
    uint32_t smem_u32 = smem_to_u32(smem);
    __half2* sg2 = (__half2*)(smem + NSTAGE * STAGE_B);   // KIND1 silu stash (32KB, per-thread)

    int tid = threadIdx.x, lane = tid & 31, wid = tid >> 5;
    int wm = wid & 1, wn = wid >> 1;
    int row = tid >> 1, half = tid & 1;
    int ml = mbase + row;
    unsigned szA = (ml < n_e) ? 16u : 0u;

    const __half* Ah_row;
    if (KIND == 0) {
        int t = (ml < n_e) ? g_tok[e][ml] : 0;
        Ah_row = g_xh + (size_t)t * Hd;
    } else {
        size_t r = (size_t)off + ((ml < n_e) ? ml : 0);
        Ah_row = (KIND == 1) ? (g_Ph + r * 640) : (g_Qh + r * 320);
    }

    const __half *BrowG = nullptr, *BrowU = nullptr, *Brow = nullptr;
    if (KIND == 1) {
        size_t ro = ((size_t)e * Brows + nbase + row) * 320;
        BrowG = g_Bg + ro;
        BrowU = g_Bu + ro;
    } else {
        const __half* Bm = (KIND == 0) ? g_Bp : g_Bo;
        Brow = Bm + ((size_t)e * Brows + nbase + row) * Kb;
    }

    float acc[4][4][4];
#pragma unroll
    for (int i = 0; i < 4; i++)
#pragma unroll
        for (int j = 0; j < 4; j++)
#pragma unroll
            for (int q = 0; q < 4; q++) acc[i][j][q] = 0.f;

    auto issue_load = [&](int st, int c) {
        uint32_t sb = smem_u32 + st * STAGE_B;
        int acol = c * 64 + half * 32;
        const __half* bsrc;
        int bcol;
        if (KIND == 1) {
            bsrc = (c < 5) ? BrowG : BrowU;
            bcol = (c % 5) * 64 + half * 32;
        } else {
            bsrc = Brow;
            bcol = acol;
        }
#pragma unroll
        for (int i = 0; i < 4; i++) {
            uint32_t so = tile_off(row, half * 4 + i);
            CP16(sb + so, Ah_row + acol + i * 8, szA);
            CP16(sb + TILE_B + so, bsrc + bcol + i * 8, 16u);
        }
    };

    auto compute = [&](int st) {
        uint32_t base = smem_u32 + st * STAGE_B;
#pragma unroll
        for (int ks = 0; ks < 4; ks++) {
            uint32_t Ahf[4][4], Bf[4][2];
#pragma unroll
            for (int mf = 0; mf < 4; mf++) {
                int ar = wm * 64 + mf * 16 + (lane & 15);
                LDSM4(Ahf[mf], base + tile_off(ar, ks * 2 + (lane >> 4)));
            }
#pragma unroll
            for (int g = 0; g < 2; g++) {
                int br = wn * 32 + g * 16 + ((lane >> 4) << 3) + (lane & 7);
                uint32_t o = tile_off(br, ks * 2 + ((lane >> 3) & 1));
                uint32_t r[4];
                LDSM4(r, base + TILE_B + o);
                Bf[2 * g][0] = r[0]; Bf[2 * g][1] = r[1];
                Bf[2 * g + 1][0] = r[2]; Bf[2 * g + 1][1] = r[3];
            }
#pragma unroll
            for (int mf = 0; mf < 4; mf++)
#pragma unroll
                for (int nf = 0; nf < 4; nf++) MMA16816(acc[mf][nf], Ahf[mf], Bf[nf]);
        }
    };

    auto stash_silu = [&]() {
#pragma unroll
        for (int mf = 0; mf < 4; mf++)
#pragma unroll
            for (int nf = 0; nf < 4; nf++)
#pragma unroll
                for (int qp = 0; qp < 2; qp++) {
                    float g0 = acc[mf][nf][qp * 2 + 0];
                    float g1 = acc[mf][nf][qp * 2 + 1];
                    g0 = g0 / (1.f + __expf(-g0));
                    g1 = g1 / (1.f + __expf(-g1));
                    sg2[((mf * 4 + nf) * 2 + qp) * 256 + tid] = __floats2half2_rn(g0, g1);
                    acc[mf][nf][qp * 2 + 0] = 0.f;
                    acc[mf][nf][qp * 2 + 1] = 0.f;
                }
    };

    if (NSTAGE == 3) {
        issue_load(0, 0); CP_COMMIT();
        if (NCc > 1) issue_load(1, 1);
        CP_COMMIT();
        CP_WAIT(1);
        __syncthreads();
        for (int c = 0; c < NCc; c++) {
            if (c + 2 < NCc) issue_load((c + 2) % 3, c + 2);
            CP_COMMIT();
            compute(c % 3);
            CP_WAIT(1);
            __syncthreads();
        }
    } else {
        issue_load(0, 0); CP_COMMIT();
        CP_WAIT(0);
        __syncthreads();
        for (int c = 0; c < NCc; c++) {
            if (c + 1 < NCc) { issue_load((c + 1) & 1, c + 1); CP_COMMIT(); }
            compute(c & 1);
            if (KIND == 1 && c == 4) stash_silu();   // per-thread smem, no sync needed
            if (c + 1 < NCc) { CP_WAIT(0); __syncthreads(); }
        }
    }

    // epilogue
#pragma unroll
    for (int mf = 0; mf < 4; mf++)
#pragma unroll
        for (int nf = 0; nf < 4; nf++)
#pragma unroll
            for (int qp = 0; qp < 2; qp++) {
                int r = wm * 64 + mf * 16 + (lane >> 2) + qp * 8;
                int m = mbase + r;
                if (m >= n_e) continue;
                int col = nbase + wn * 32 + nf * 8 + (lane & 3) * 2;
                float v0 = acc[mf][nf][qp * 2 + 0];
                float v1 = acc[mf][nf][qp * 2 + 1];
                if (KIND == 0) {
                    size_t b = (size_t)(off + m) * 640 + col;
                    *(__half2*)(g_Ph + b) = __floats2half2_rn(v0, v1);
                } else if (KIND == 1) {
                    float2 sf = __half22float2(sg2[((mf * 4 + nf) * 2 + qp) * 256 + tid]);
                    v0 *= sf.x;
                    v1 *= sf.y;
                    size_t b = (size_t)(off + m) * Id + col;
                    *(__half2*)(g_hh + b) = __floats2half2_rn(v0, v1);
                } else {
                    float wt  = g_wt[e][m];
                    int   tok = g_tok[e][m];
                    float* dst = outp + (size_t)tok * Hd + col;
                    atomicAdd(dst, wt * v0);
                    atomicAdd(dst + 1, wt * v1);
                }
            }
}

// ---------------- Q GEMM: M=64 x N=160, 4 K-slices, 3-stage, 2 CTAs/SM ----------------
#define QA_B 8192
#define QB_B 20480
#define QST_B (QA_B + QB_B)   // 28672
__global__ __launch_bounds__(256, 2) void moe_mma_q(int ebase)
{
    int e     = ebase + blockIdx.z;
    int n_e   = g_cnt[e];
    int mbase = blockIdx.x * 64;
    if (mbase >= n_e) return;
    int nhalf  = blockIdx.y & 1;
    int kslice = blockIdx.y >> 1;
    int cbase  = kslice * QNC;
    int off    = g_off[e];

    extern __shared__ char smem[];
    uint32_t smem_u32 = smem_to_u32(smem);

    int tid = threadIdx.x, lane = tid & 31, wid = tid >> 5;
    int wm = wid >> 2, wn = wid & 3;   // 2M x 4N warps

    float acc[2][5][4];
#pragma unroll
    for (int i = 0; i < 2; i++)
#pragma unroll
        for (int j = 0; j < 5; j++)
#pragma unroll
            for (int q = 0; q < 4; q++) acc[i][j][q] = 0.f;

    const __half* Bq_e = g_Bq + (size_t)e * 384 * Id + (size_t)(nhalf * 160) * Id;

    auto issue_load = [&](int st, int c) {
        uint32_t sb = smem_u32 + st * QST_B;
        int col = (cbase + c) * 64;
#pragma unroll
        for (int i = 0; i < 7; i++) {
            int ci = tid + i * 256;
            if (ci < 512) {
                int row = ci >> 3, ch = ci & 7;
                int m = mbase + row;
                unsigned sz = (m < n_e) ? 16u : 0u;
                const __half* src = g_hh + ((size_t)off + ((m < n_e) ? m : 0)) * Id + col + ch * 8;
                CP16(sb + tile_off(row, ch), src, sz);
            } else {
                int bi = ci - 512;   // < 1280
                int row = bi >> 3, ch = bi & 7;
                const __half* src = Bq_e + (size_t)row * Id + col + ch * 8;
                CP16(sb + QA_B + tile_off(row, ch), src, 16u);
            }
        }
    };

    auto compute = [&](int st) {
        uint32_t base = smem_u32 + st * QST_B;
#pragma unroll
        for (int ks = 0; ks < 4; ks++) {
            uint32_t Af[2][4], Bf[5][2];
#pragma unroll
            for (int mf = 0; mf < 2; mf++) {
                int ar = wm * 32 + mf * 16 + (lane & 15);
                LDSM4(Af[mf], base + tile_off(ar, ks * 2 + (lane >> 4)));
            }
#pragma unroll
            for (int g = 0; g < 2; g++) {
                int br = wn * 40 + g * 16 + ((lane >> 4) << 3) + (lane & 7);
                uint32_t o = tile_off(br, ks * 2 + ((lane >> 3) & 1));
                uint32_t r[4];
                LDSM4(r, base + QA_B + o);
                Bf[2 * g][0] = r[0]; Bf[2 * g][1] = r[1];
                Bf[2 * g + 1][0] = r[2]; Bf[2 * g + 1][1] = r[3];
            }
            {
                int br = wn * 40 + 32 + (lane & 7);
                uint32_t o = tile_off(br, ks * 2 + ((lane >> 3) & 1));
                uint32_t r2[2];
                LDSM2(r2, base + QA_B + o);
                Bf[4][0] = r2[0]; Bf[4][1] = r2[1];
            }
#pragma unroll
            for (int mf = 0; mf < 2; mf++)
#pragma unroll
                for (int nf = 0; nf < 5; nf++) MMA16816(acc[mf][nf], Af[mf], Bf[nf]);
        }
    };

    issue_load(0, 0); CP_COMMIT();
    issue_load(1, 1); CP_COMMIT();
    CP_WAIT(1);
    __syncthreads();

    for (int c = 0; c < QNC; c++) {
        if (c + 2 < QNC) issue_load((c + 2) % 3, c + 2);
        CP_COMMIT();
        compute(c % 3);
        CP_WAIT(1);
        __syncthreads();
    }

    float* qf = g_Qf + (size_t)kslice * RT * 320;
#pragma unroll
    for (int mf = 0; mf < 2; mf++)
#pragma unroll
        for (int nf = 0; nf < 5; nf++)
#pragma unroll
            for (int qp = 0; qp < 2; qp++) {
                int m = mbase + wm * 32 + mf * 16 + (lane >> 2) + qp * 8;
                if (m >= n_e) continue;
                int col = nhalf * 160 + wn * 40 + nf * 8 + (lane & 3) * 2;
                size_t b = (size_t)(off + m) * 320 + col;
                qf[b]     = acc[mf][nf][qp * 2 + 0];
                qf[b + 1] = acc[mf][nf][qp * 2 + 1];
            }
}

// ---------------- launch ----------------
extern "C" void kernel_launch(void* const* d_in, const int* in_sizes, int n_in,
                              void* d_out, int out_size)
{
    const float* x    = (const float*)d_in[0];
    const float* gw   = (const float*)d_in[1];
    const float* w1u  = (const float*)d_in[2];
    const float* w1v  = (const float*)d_in[3];
    const float* w2u  = (const float*)d_in[4];
    const float* w2v  = (const float*)d_in[5];
    const float* w3u  = (const float*)d_in[6];
    const float* w3v  = (const float*)d_in[7];
    const float* u1   = (const float*)d_in[8];
    const float* v1   = (const float*)d_in[9];
    const float* u2   = (const float*)d_in[10];
    const float* v2   = (const float*)d_in[11];
    const float* u3   = (const float*)d_in[12];
    const float* v3   = (const float*)d_in[13];

    float* outp   = (float*)d_out;
    float* logits = outp + (size_t)Tt * Hd;

    static cudaStream_t s_pack = nullptr;
    static cudaEvent_t evStart, evBp, evBgu, evBq, evBo, evRoute, evZero, evDoneB;
    if (!s_pack) {
        cudaStreamCreateWithFlags(&s_pack, cudaStreamNonBlocking);
        cudaEventCreateWithFlags(&evStart, cudaEventDisableTiming);
        cudaEventCreateWithFlags(&evBp,    cudaEventDisableTiming);
        cudaEventCreateWithFlags(&evBgu,   cudaEventDisableTiming);
        cudaEventCreateWithFlags(&evBq,    cudaEventDisableTiming);
        cudaEventCreateWithFlags(&evBo,    cudaEventDisableTiming);
        cudaEventCreateWithFlags(&evRoute, cudaEventDisableTiming);
        cudaEventCreateWithFlags(&evZero,  cudaEventDisableTiming);
        cudaEventCreateWithFlags(&evDoneB, cudaEventDisableTiming);

        int smem_s2 = STAGES * 2 * TILE_B;        // 96KB (KIND0/3)
        int smem_gu = 2 * 2 * TILE_B + 32768;     // 96KB (KIND1)
        int smem_q  = 3 * QST_B;                  // 84KB
        cudaFuncSetAttribute(moe_mma<0>, cudaFuncAttributeMaxDynamicSharedMemorySize, smem_s2);
        cudaFuncSetAttribute(moe_mma<1>, cudaFuncAttributeMaxDynamicSharedMemorySize, smem_gu);
        cudaFuncSetAttribute(moe_mma<3>, cudaFuncAttributeMaxDynamicSharedMemorySize, smem_s2);
        cudaFuncSetAttribute(moe_mma_q,  cudaFuncAttributeMaxDynamicSharedMemorySize, smem_q);
        cudaFuncSetAttribute(router_kernel, cudaFuncAttributeMaxDynamicSharedMemorySize,
                             Ee * Hd * (int)sizeof(float));   // 128KB
    }
    int smem_s2 = STAGES * 2 * TILE_B;
    int smem_gu = 2 * 2 * TILE_B + 32768;
    int smem_q  = 3 * QST_B;

    // fork: weight packing on side stream
    cudaEventRecord(evStart, 0);
    cudaStreamWaitEvent(s_pack, evStart, 0);

    k_conv_Bp<<<dim3(640, Ee), 256, 0, s_pack>>>(w1v, v1, w3v, v3);
    cudaEventRecord(evBp, s_pack);
    k_pack320<0><<<dim3(Id / 4, Ee), 320, 0, s_pack>>>(w1u, u1);
    k_pack320<1><<<dim3(Id / 4, Ee), 320, 0, s_pack>>>(w3u, u3);
    cudaEventRecord(evBgu, s_pack);
    k_conv_Bq<<<dim3(320, Ee), 256, 0, s_pack>>>(w2v, v2);
    cudaEventRecord(evBq, s_pack);
    k_pack320<2><<<dim3(Hd / 4, Ee), 320, 0, s_pack>>>(w2u, u2);
    cudaEventRecord(evBo, s_pack);

    // main stream: routing chain (router also produces g_xh)
    cudaMemsetAsync(outp, 0, (size_t)Tt * Hd * sizeof(float));
    cudaEventRecord(evZero, 0);
    prep_kernel<<<1, 32>>>();
    router_kernel<<<Tt / 8, 256, Ee * Hd * sizeof(float)>>>(x, gw, logits);
    route_kernel<<<Tt / 256, 256>>>(logits);
    offsets_kernel<<<1, 32>>>();
    cudaEventRecord(evRoute, 0);

    // group A (experts 0-3) on main stream
    cudaStreamWaitEvent(0, evBp, 0);
    moe_mma<0><<<dim3(32, 5, 4), 256, smem_s2>>>(nullptr, 0);
    cudaStreamWaitEvent(0, evBgu, 0);
    moe_mma<1><<<dim3(32, 112, 4), 256, smem_gu>>>(nullptr, 0);
    cudaStreamWaitEvent(0, evBq, 0);
    moe_mma_q<<<dim3(64, 2 * QSPLIT, 4), 256, smem_q>>>(0);
    k_qsum_g<<<(RT * 320) / 256, 256>>>(0);
    cudaStreamWaitEvent(0, evBo, 0);
    moe_mma<3><<<dim3(32, 32, 4), 256, smem_s2>>>(outp, 0);

    // group B (experts 4-7) on s_pack (packing already ordered there)
    cudaStreamWaitEvent(s_pack, evRoute, 0);
    cudaStreamWaitEvent(s_pack, evZero, 0);
    moe_mma<0><<<dim3(32, 5, 4), 256, smem_s2, s_pack>>>(nullptr, 4);
    moe_mma<1><<<dim3(32, 112, 4), 256, smem_gu, s_pack>>>(nullptr, 4);
    moe_mma_q<<<dim3(64, 2 * QSPLIT, 4), 256, smem_q, s_pack>>>(4);
    k_qsum_g<<<(RT * 320) / 256, 256, 0, s_pack>>>(4);
    moe_mma<3><<<dim3(32, 32, 4), 256, smem_s2, s_pack>>>(outp, 4);
    cudaEventRecord(evDoneB, s_pack);

    // join
    cudaStreamWaitEvent(0, evDoneB, 0);
}